// round 5
// baseline (speedup 1.0000x reference)
#include <cuda_runtime.h>
#include <math.h>

#define T_LEN 256
#define HID   2048
#define NHEAD 16
#define DHEAD 128
#define KD    2048
#define CHUNK 16
#define NSLOT (T_LEN / CHUNK)

// ---------------- scratch ----------------
__device__ float g_Q0[T_LEN * KD];
__device__ float g_K0[T_LEN * KD];
__device__ float g_V0[T_LEN * KD];
__device__ float g_qn[T_LEN * KD];
__device__ float g_kn[T_LEN * KD];
__device__ float g_beta[T_LEN * NHEAD];
__device__ float g_decay[T_LEN * NHEAD];
__device__ float g_on[T_LEN * KD];
__device__ float g_hkk_ck[(size_t)NSLOT * NHEAD * DHEAD * DHEAD];  // 16 MB
__device__ float g_hkv_ck[(size_t)NSLOT * NHEAD * DHEAD * DHEAD];  // 16 MB

// ---------------- f32x2 helpers ----------------
typedef unsigned long long u64;
__device__ __forceinline__ u64 splat2(float a) {
    u64 d; unsigned u = __float_as_uint(a);
    asm("mov.b64 %0, {%1, %1};" : "=l"(d) : "r"(u));
    return d;
}
__device__ __forceinline__ void ffma2(u64& d, u64 a, u64 b) {
    asm("fma.rn.f32x2 %0, %1, %2, %0;" : "+l"(d) : "l"(a), "l"(b));
}
__device__ __forceinline__ void mul2(u64& d, u64 a) {
    asm("mul.rn.f32x2 %0, %0, %1;" : "+l"(d) : "l"(a));
}
__device__ __forceinline__ float2 unpk(u64 v) {
    unsigned lo, hi;
    asm("mov.b64 {%0, %1}, %2;" : "=r"(lo), "=r"(hi) : "l"(v));
    return make_float2(__uint_as_float(lo), __uint_as_float(hi));
}

// ---------------- GEMM tile: TM=32, TN=128, BK=32, 128 threads, micro 4x8 ----------------
__device__ __forceinline__ void gemm_tile32x128(const float* __restrict__ X,
                                                const float* __restrict__ W,
                                                float* __restrict__ C, int N,
                                                int m0, int n0) {
    __shared__ __align__(16) float As[32][36];    // 144B stride (16B multiple)
    __shared__ __align__(16) float Bs[32][132];   // 528B stride (16B multiple)
    const int tid = threadIdx.x;
    const int tmr = tid >> 4;           // 0..7  -> m rows tmr*4..+3
    const int tnc = tid & 15;           // 0..15 -> n cols tnc*8..+7
    const int arow = tid >> 2;          // 0..31
    const int acol = (tid & 3) * 8;
    const int brow = tid >> 2;          // 0..31
    const int bcol = (tid & 3) * 32;

    u64 acc[4][4];
#pragma unroll
    for (int i = 0; i < 4; i++)
#pragma unroll
        for (int j = 0; j < 4; j++) acc[i][j] = 0ull;

    for (int k0 = 0; k0 < HID; k0 += 32) {
        const float* xp = &X[(m0 + arow) * HID + k0 + acol];
        *(float4*)&As[arow][acol]     = *(const float4*)&xp[0];
        *(float4*)&As[arow][acol + 4] = *(const float4*)&xp[4];
        const float* wp = &W[(k0 + brow) * N + n0 + bcol];
#pragma unroll
        for (int q = 0; q < 8; q++)
            *(float4*)&Bs[brow][bcol + q * 4] = *(const float4*)&wp[q * 4];
        __syncthreads();
#pragma unroll
        for (int kk = 0; kk < 32; kk++) {
            ulonglong2 b0 = *(const ulonglong2*)&Bs[kk][tnc * 8];
            ulonglong2 b1 = *(const ulonglong2*)&Bs[kk][tnc * 8 + 4];
            float a0 = As[tmr * 4 + 0][kk];
            float a1 = As[tmr * 4 + 1][kk];
            float a2 = As[tmr * 4 + 2][kk];
            float a3 = As[tmr * 4 + 3][kk];
            u64 s0 = splat2(a0), s1 = splat2(a1), s2 = splat2(a2), s3 = splat2(a3);
            ffma2(acc[0][0], s0, b0.x); ffma2(acc[0][1], s0, b0.y);
            ffma2(acc[0][2], s0, b1.x); ffma2(acc[0][3], s0, b1.y);
            ffma2(acc[1][0], s1, b0.x); ffma2(acc[1][1], s1, b0.y);
            ffma2(acc[1][2], s1, b1.x); ffma2(acc[1][3], s1, b1.y);
            ffma2(acc[2][0], s2, b0.x); ffma2(acc[2][1], s2, b0.y);
            ffma2(acc[2][2], s2, b1.x); ffma2(acc[2][3], s2, b1.y);
            ffma2(acc[3][0], s3, b0.x); ffma2(acc[3][1], s3, b0.y);
            ffma2(acc[3][2], s3, b1.x); ffma2(acc[3][3], s3, b1.y);
        }
        __syncthreads();
    }
#pragma unroll
    for (int i = 0; i < 4; i++) {
        float2 p0 = unpk(acc[i][0]), p1 = unpk(acc[i][1]);
        float2 p2 = unpk(acc[i][2]), p3 = unpk(acc[i][3]);
        float* cp = &C[(m0 + tmr * 4 + i) * N + n0 + tnc * 8];
        *(float4*)&cp[0] = make_float4(p0.x, p0.y, p1.x, p1.y);
        *(float4*)&cp[4] = make_float4(p2.x, p2.y, p3.x, p3.y);
    }
}

// qkv: 384 blocks = 3 mats x 16 n-tiles x 8 m-tiles
__global__ void __launch_bounds__(128) qkv_kernel(const float* __restrict__ x,
                                                  const float* __restrict__ Wq,
                                                  const float* __restrict__ Wk,
                                                  const float* __restrict__ Wv) {
    const int bx = blockIdx.x;
    const int mat = bx % 3;
    const int nt = (bx / 3) & 15;
    const int mt = (bx / 3) >> 4;
    const float* W = (mat == 0) ? Wq : (mat == 1) ? Wk : Wv;
    float* C = (mat == 0) ? g_Q0 : (mat == 1) ? g_K0 : g_V0;
    gemm_tile32x128(x, W, C, KD, mt * 32, nt * 128);
}

// out: 128 blocks = 16 n-tiles x 8 m-tiles
__global__ void __launch_bounds__(128) out_kernel(const float* __restrict__ Wo,
                                                  float* __restrict__ out) {
    const int nt = blockIdx.x & 15;
    const int mt = blockIdx.x >> 4;
    gemm_tile32x128(g_on, Wo, out, HID, mt * 32, nt * 128);
}

// ---------------- prep (conv+silu+l2norm) fused with beta/decay ----------------
__device__ __forceinline__ void conv_silu_l2(const float* __restrict__ src,
                                             const float* __restrict__ cw,
                                             float* __restrict__ dst,
                                             int t, int tid) {
    const int c0 = tid * 8;
    float wv[8][4];
#pragma unroll
    for (int e = 0; e < 8; e++) {
        float4 f = *(const float4*)&cw[(c0 + e) * 4];
        wv[e][0] = f.x; wv[e][1] = f.y; wv[e][2] = f.z; wv[e][3] = f.w;
    }
    float y[8];
#pragma unroll
    for (int e = 0; e < 8; e++) y[e] = 0.f;
#pragma unroll
    for (int i = 0; i < 4; i++) {
        int ts = t + i - 3;
        if (ts >= 0) {
            float4 xa = *(const float4*)&src[ts * HID + c0];
            float4 xb = *(const float4*)&src[ts * HID + c0 + 4];
            float xv[8] = {xa.x, xa.y, xa.z, xa.w, xb.x, xb.y, xb.z, xb.w};
#pragma unroll
            for (int e = 0; e < 8; e++) y[e] += xv[e] * wv[e][i];
        }
    }
#pragma unroll
    for (int e = 0; e < 8; e++) {
        float s = 1.f / (1.f + expf(-y[e]));
        y[e] *= s;
    }
    float ss = 0.f;
#pragma unroll
    for (int e = 0; e < 8; e++) ss += y[e] * y[e];
#pragma unroll
    for (int off = 1; off <= 8; off <<= 1) ss += __shfl_xor_sync(0xffffffffu, ss, off);
    float sc = rsqrtf(ss + 1e-6f);
    float4 o0 = make_float4(y[0] * sc, y[1] * sc, y[2] * sc, y[3] * sc);
    float4 o1 = make_float4(y[4] * sc, y[5] * sc, y[6] * sc, y[7] * sc);
    *(float4*)&dst[t * HID + c0] = o0;
    *(float4*)&dst[t * HID + c0 + 4] = o1;
}

__global__ void __launch_bounds__(256) prep_kernel(const float* __restrict__ cwq,
                                                   const float* __restrict__ cwk,
                                                   const float* __restrict__ x,
                                                   const float* __restrict__ Wa,
                                                   const float* __restrict__ ba,
                                                   const float* __restrict__ Wb,
                                                   const float* __restrict__ bb) {
    const int tid = threadIdx.x;
    if (blockIdx.x < 256) {
        const int t = blockIdx.x;
        conv_silu_l2(g_Q0, cwq, g_qn, t, tid);
        conv_silu_l2(g_K0, cwk, g_kn, t, tid);
        return;
    }
    // ---- beta/decay mini-GEMM path: blocks 256..271 ----
    __shared__ float Xs[32][17];
    __shared__ float Ws[32][32];
    const int m0 = (blockIdx.x - 256) * 16;
    const int n = tid & 31;
    const int mg = tid >> 5;
    const int lxm = tid >> 4;
    const int lxk = (tid & 15) * 2;

    float acc0 = 0.f, acc1 = 0.f;
    for (int k0 = 0; k0 < HID; k0 += 32) {
        float2 xv = *(const float2*)&x[(m0 + lxm) * HID + k0 + lxk];
        Xs[lxk][lxm] = xv.x;
        Xs[lxk + 1][lxm] = xv.y;
        const int i4 = tid * 4;
        const int wk = i4 >> 5, wn = i4 & 31;
#pragma unroll
        for (int j = 0; j < 4; j++) {
            int nn = wn + j;
            Ws[wk][nn] = (nn < 16) ? Wa[(k0 + wk) * NHEAD + nn]
                                   : Wb[(k0 + wk) * NHEAD + nn - 16];
        }
        __syncthreads();
#pragma unroll
        for (int kk = 0; kk < 32; kk++) {
            float w = Ws[kk][n];
            acc0 += Xs[kk][mg * 2] * w;
            acc1 += Xs[kk][mg * 2 + 1] * w;
        }
        __syncthreads();
    }
    const int row0 = m0 + mg * 2;
    if (n < 16) {
        float z0 = acc0 + ba[n], z1 = acc1 + ba[n];
        g_decay[row0 * NHEAD + n] = 1.f / (1.f + expf(-z0));
        g_decay[(row0 + 1) * NHEAD + n] = 1.f / (1.f + expf(-z1));
    } else {
        int c = n - 16;
        float z0 = acc0 + bb[c], z1 = acc1 + bb[c];
        g_beta[row0 * NHEAD + c] = 1.f / (1.f + expf(-z0));
        g_beta[(row0 + 1) * NHEAD + c] = 1.f / (1.f + expf(-z1));
    }
}

// ---------------- state scan: chunk-boundary checkpoints ----------------
__global__ void scan_kernel() {
    const int h = blockIdx.y;
    const int i0 = blockIdx.x * 8;
    const int tid = threadIdx.x;
    __shared__ float ds[T_LEN], bs[T_LEN];
    __shared__ __align__(16) float ks[2][DHEAD], vs[2][DHEAD];
    ds[tid] = g_decay[tid * NHEAD + h];
    bs[tid] = g_beta[tid * NHEAD + h];
    if (tid < 32)
        *(float4*)&ks[0][tid * 4] = *(const float4*)&g_kn[h * DHEAD + tid * 4];
    else if (tid < 64) {
        int l = tid - 32;
        *(float4*)&vs[0][l * 4] = *(const float4*)&g_V0[h * DHEAD + l * 4];
    }
    const int row = i0 + (tid >> 5);
    const int j0 = (tid & 31) * 4;
    float kk0 = 0, kk1 = 0, kk2 = 0, kk3 = 0;
    float kv0 = 0, kv1 = 0, kv2 = 0, kv3 = 0;
    for (int t = 0; t < T_LEN; t++) {
        __syncthreads();
        const int cb = t & 1, nb = (t + 1) & 1;
        if (t + 1 < T_LEN) {
            if (tid < 32)
                *(float4*)&ks[nb][tid * 4] =
                    *(const float4*)&g_kn[(t + 1) * HID + h * DHEAD + tid * 4];
            else if (tid < 64) {
                int l = tid - 32;
                *(float4*)&vs[nb][l * 4] =
                    *(const float4*)&g_V0[(t + 1) * HID + h * DHEAD + l * 4];
            }
        }
        const float d = ds[t], b = bs[t];
        const float kr = ks[cb][row];
        float4 kj = *(const float4*)&ks[cb][j0];
        float4 vj = *(const float4*)&vs[cb][j0];
        const float bk = b * kr;
        kk0 = kk0 * d + bk * kj.x; kk1 = kk1 * d + bk * kj.y;
        kk2 = kk2 * d + bk * kj.z; kk3 = kk3 * d + bk * kj.w;
        kv0 = kv0 * d + bk * vj.x; kv1 = kv1 * d + bk * vj.y;
        kv2 = kv2 * d + bk * vj.z; kv3 = kv3 * d + bk * vj.w;
        if (((t + 1) & (CHUNK - 1)) == 0) {
            const int slot = t >> 4;
            size_t base = (((size_t)slot * NHEAD + h) << 14) + (size_t)row * DHEAD + j0;
            *(float4*)&g_hkk_ck[base] = make_float4(kk0, kk1, kk2, kk3);
            *(float4*)&g_hkv_ck[base] = make_float4(kv0, kv1, kv2, kv3);
        }
    }
}

// ---------------- block reduce (parity-buffered) ----------------
__device__ __forceinline__ float blockReduce128(float v, int pb) {
    __shared__ float red[2][4];
#pragma unroll
    for (int off = 16; off > 0; off >>= 1) v += __shfl_xor_sync(0xffffffffu, v, off);
    const int w = threadIdx.x >> 5;
    if ((threadIdx.x & 31) == 0) red[pb][w] = v;
    __syncthreads();
    return red[pb][0] + red[pb][1] + red[pb][2] + red[pb][3];
}

// ---------------- CG solve (recon + early exit) + output + rmsnorm ----------------
__global__ void __launch_bounds__(128, 4) solve_kernel(const float* __restrict__ onw,
                                                       const float* __restrict__ lp) {
    const int h = blockIdx.x;
    const int t = blockIdx.y;
    const int r = threadIdx.x;
    const int cs = t & ~(CHUNK - 1);
    const int jend = t - cs;
    const int slot = (t >> 4) - 1;

    __shared__ __align__(16) float ks[CHUNK][DHEAD];
    __shared__ __align__(16) float vs[CHUNK][DHEAD];
    __shared__ __align__(16) float ps[DHEAD];
    __shared__ float dsh[CHUNK], bsh[CHUNK], Pp[CHUNK], cf[CHUNK], gsh[CHUNK];

    {
        const int row = r >> 3;
        const int c0 = (r & 7) * 16;
        const float* kp = &g_kn[(cs + row) * HID + h * DHEAD + c0];
        const float* vp = &g_V0[(cs + row) * HID + h * DHEAD + c0];
#pragma unroll
        for (int q = 0; q < 4; q++) {
            *(float4*)&ks[row][c0 + q * 4] = *(const float4*)&kp[q * 4];
            *(float4*)&vs[row][c0 + q * 4] = *(const float4*)&vp[q * 4];
        }
        if (r < CHUNK) {
            dsh[r] = g_decay[(cs + r) * NHEAD + h];
            bsh[r] = g_beta[(cs + r) * NHEAD + h];
        }
    }
    __syncthreads();
    if (r == 0) {
        float run = 1.f;
#pragma unroll
        for (int s = 0; s < CHUNK; s++) {
            run *= dsh[s];
            Pp[s] = run;
            cf[s] = bsh[s] / run;
        }
    }
    __syncthreads();
    const float Pt = Pp[jend];

    // build A row r in registers
    ulonglong2 A2[32];
    if (slot >= 0) {
        const float* base = g_hkk_ck + (((size_t)slot * NHEAD + h) << 14) + (size_t)r * DHEAD;
#pragma unroll
        for (int i = 0; i < 32; i++) A2[i] = *(const ulonglong2*)&base[i * 4];
    } else {
#pragma unroll
        for (int i = 0; i < 32; i++) { A2[i].x = 0ull; A2[i].y = 0ull; }
    }
    for (int s = 0; s <= jend; s++) {
        u64 w = splat2(cf[s] * ks[s][r]);
        const u64* kkp = (const u64*)&ks[s][0];
#pragma unroll
        for (int i = 0; i < 32; i++) {
            ffma2(A2[i].x, w, kkp[2 * i]);
            ffma2(A2[i].y, w, kkp[2 * i + 1]);
        }
    }
    {
        u64 pt2 = splat2(Pt);
#pragma unroll
        for (int i = 0; i < 32; i++) { mul2(A2[i].x, pt2); mul2(A2[i].y, pt2); }
    }

    // lambda = softplus(lp) + 0.25, inline
    float lam;
    {
        float v = lp[h * DHEAD + r];
        lam = ((v > 20.f) ? v : log1pf(expf(v))) + 0.25f;
    }
    const float b = g_qn[t * HID + h * DHEAD + r];

    float xx = 0.f, rr = b, p = b;
    ps[r] = b;
    int par = 0;
    float rs = blockReduce128(b * b, par); par ^= 1;
    const float rs_stop = 1e-12f * rs;

    for (int it = 0; it < 30; it++) {
        u64 aA = 0ull, aB = 0ull, aC = 0ull, aD = 0ull;
#pragma unroll
        for (int i = 0; i < 32; i += 2) {
            ulonglong2 p0 = *(const ulonglong2*)&ps[i * 4];
            ulonglong2 p1 = *(const ulonglong2*)&ps[i * 4 + 4];
            ffma2(aA, A2[i].x, p0.x);     ffma2(aB, A2[i].y, p0.y);
            ffma2(aC, A2[i + 1].x, p1.x); ffma2(aD, A2[i + 1].y, p1.y);
        }
        float2 fa = unpk(aA), fb = unpk(aB), fc = unpk(aC), fd = unpk(aD);
        float ap = ((fa.x + fa.y) + (fb.x + fb.y)) + ((fc.x + fc.y) + (fd.x + fd.y)) + lam * p;
        float pap = blockReduce128(p * ap, par); par ^= 1;
        float alpha = rs / (pap + 1e-12f);
        xx += alpha * p;
        rr -= alpha * ap;
        float rsn = blockReduce128(rr * rr, par); par ^= 1;
        if (rsn < rs_stop) break;   // converged: further reference iters are no-ops
        float bet = rsn / (rs + 1e-12f);
        p = rr + bet * p;
        rs = rsn;
        ps[r] = p;
        __syncthreads();
    }

    // ---- output ----
    ps[r] = xx;
    __syncthreads();
    {
        const int sIdx = r >> 3;
        const int part = r & 7;
        float pg = 0.f;
        const int e0 = part * 16;
#pragma unroll
        for (int e = 0; e < 16; e++) pg += ks[sIdx][e0 + e] * ps[e0 + e];
#pragma unroll
        for (int off = 1; off <= 4; off <<= 1) pg += __shfl_xor_sync(0xffffffffu, pg, off);
        if (part == 0)
            gsh[sIdx] = (sIdx <= jend) ? pg * cf[sIdx] * Pt : 0.f;
    }
    __syncthreads();

    float o = 0.f;
    if (slot >= 0) {
        const float* kvb = g_hkv_ck + (((size_t)slot * NHEAD + h) << 14) + r;
        float o0 = 0, o1 = 0, o2 = 0, o3 = 0;
#pragma unroll
        for (int k2 = 0; k2 < DHEAD; k2 += 4) {
            o0 += ps[k2]     * kvb[(size_t)k2 * DHEAD];
            o1 += ps[k2 + 1] * kvb[(size_t)(k2 + 1) * DHEAD];
            o2 += ps[k2 + 2] * kvb[(size_t)(k2 + 2) * DHEAD];
            o3 += ps[k2 + 3] * kvb[(size_t)(k2 + 3) * DHEAD];
        }
        o = Pt * ((o0 + o1) + (o2 + o3));
    }
#pragma unroll
    for (int s = 0; s < CHUNK; s++) o += gsh[s] * vs[s][r];

    float ms = blockReduce128(o * o, par) * (1.0f / 128.0f);
    float sc = rsqrtf(ms + 1e-5f);
    g_on[t * HID + h * DHEAD + r] = o * sc * onw[r];
}

// ---------------- launch ----------------
extern "C" void kernel_launch(void* const* d_in, const int* in_sizes, int n_in,
                              void* d_out, int out_size) {
    const float* x    = (const float*)d_in[0];
    const float* Wq   = (const float*)d_in[1];
    const float* Wk   = (const float*)d_in[2];
    const float* Wv   = (const float*)d_in[3];
    const float* Wa   = (const float*)d_in[4];
    const float* ba   = (const float*)d_in[5];
    const float* Wb   = (const float*)d_in[6];
    const float* bb   = (const float*)d_in[7];
    const float* cwq  = (const float*)d_in[8];
    const float* cwk  = (const float*)d_in[9];
    const float* lp   = (const float*)d_in[10];
    const float* onw  = (const float*)d_in[11];
    const float* Wo   = (const float*)d_in[12];
    float* out = (float*)d_out;

    qkv_kernel<<<384, 128>>>(x, Wq, Wk, Wv);
    prep_kernel<<<272, 256>>>(cwq, cwk, x, Wa, ba, Wb, bb);
    scan_kernel<<<dim3(16, NHEAD), 256>>>();
    solve_kernel<<<dim3(NHEAD, T_LEN), 128>>>(onw, lp);
    out_kernel<<<128, 128>>>(Wo, out);
}

// round 6
// speedup vs baseline: 1.4217x; 1.4217x over previous
#include <cuda_runtime.h>
#include <math.h>

#define T_LEN 256
#define HID   2048
#define NHEAD 16
#define DHEAD 128
#define KD    2048
#define CHUNK 8
#define NSLOT (T_LEN / CHUNK)

// ---------------- scratch ----------------
__device__ float g_Q0[T_LEN * KD];
__device__ float g_K0[T_LEN * KD];
__device__ float g_V0[T_LEN * KD];
__device__ float g_qn[T_LEN * KD];
__device__ float g_kn[T_LEN * KD];
__device__ float g_beta[T_LEN * NHEAD];
__device__ float g_decay[T_LEN * NHEAD];
__device__ float g_on[T_LEN * KD];
__device__ float g_hkk_ck[(size_t)NSLOT * NHEAD * DHEAD * DHEAD];  // 32 MB
__device__ float g_hkv_ck[(size_t)NSLOT * NHEAD * DHEAD * DHEAD];  // 32 MB

// ---------------- f32x2 helpers ----------------
typedef unsigned long long u64;
__device__ __forceinline__ u64 splat2(float a) {
    u64 d; unsigned u = __float_as_uint(a);
    asm("mov.b64 %0, {%1, %1};" : "=l"(d) : "r"(u));
    return d;
}
__device__ __forceinline__ void ffma2(u64& d, u64 a, u64 b) {
    asm("fma.rn.f32x2 %0, %1, %2, %0;" : "+l"(d) : "l"(a), "l"(b));
}
__device__ __forceinline__ void mul2(u64& d, u64 a) {
    asm("mul.rn.f32x2 %0, %0, %1;" : "+l"(d) : "l"(a));
}
__device__ __forceinline__ float2 unpk(u64 v) {
    unsigned lo, hi;
    asm("mov.b64 {%0, %1}, %2;" : "=r"(lo), "=r"(hi) : "l"(v));
    return make_float2(__uint_as_float(lo), __uint_as_float(hi));
}

// ---------------- GEMM 128x64 tile (qkv), 256 threads ----------------
__device__ __forceinline__ void gemm_tile128(const float* __restrict__ X,
                                             const float* __restrict__ W,
                                             float* __restrict__ C, int N,
                                             int m0, int n0) {
    __shared__ __align__(16) float As[128][36];   // 144B stride (16B multiple)
    __shared__ __align__(16) float Bs[32][64];
    const int tid = threadIdx.x;
    const int tn4 = (tid & 15) * 4;
    const int tm8 = (tid >> 4) * 8;
    const int arow = tid >> 1;
    const int akoff = (tid & 1) * 16;
    const int brow = tid >> 3;
    const int bcol = (tid & 7) * 8;

    u64 acc[8][2];
#pragma unroll
    for (int i = 0; i < 8; i++) { acc[i][0] = 0ull; acc[i][1] = 0ull; }

    for (int k0 = 0; k0 < HID; k0 += 32) {
        const float* xp = &X[(m0 + arow) * HID + k0 + akoff];
#pragma unroll
        for (int q = 0; q < 4; q++)
            *(float4*)&As[arow][akoff + q * 4] = *(const float4*)&xp[q * 4];
        const float* wp = &W[(k0 + brow) * N + n0 + bcol];
        *(float4*)&Bs[brow][bcol]     = *(const float4*)&wp[0];
        *(float4*)&Bs[brow][bcol + 4] = *(const float4*)&wp[4];
        __syncthreads();
#pragma unroll
        for (int kk = 0; kk < 32; kk++) {
            ulonglong2 bv = *(const ulonglong2*)&Bs[kk][tn4];
#pragma unroll
            for (int i = 0; i < 8; i++) {
                u64 s = splat2(As[tm8 + i][kk]);
                ffma2(acc[i][0], s, bv.x);
                ffma2(acc[i][1], s, bv.y);
            }
        }
        __syncthreads();
    }
#pragma unroll
    for (int i = 0; i < 8; i++) {
        float2 lo = unpk(acc[i][0]);
        float2 hi = unpk(acc[i][1]);
        *(float4*)&C[(m0 + tm8 + i) * N + n0 + tn4] = make_float4(lo.x, lo.y, hi.x, hi.y);
    }
}

// ---------------- GEMM 64x64 tile (out), 256 threads ----------------
__device__ __forceinline__ void gemm_tile64(const float* __restrict__ X,
                                            const float* __restrict__ W,
                                            float* __restrict__ C, int N,
                                            int m0, int n0) {
    __shared__ __align__(16) float As[64][36];
    __shared__ __align__(16) float Bs[32][64];
    const int tid = threadIdx.x;
    const int tn4 = (tid & 15) * 4;
    const int tm4 = (tid >> 4) * 4;
    const int lrow = tid >> 2;
    const int lk   = (tid & 3) * 8;
    const int bkk  = tid >> 3;
    const int bn8  = (tid & 7) * 8;

    u64 acc[4][2];
#pragma unroll
    for (int i = 0; i < 4; i++) { acc[i][0] = 0ull; acc[i][1] = 0ull; }

    for (int k0 = 0; k0 < HID; k0 += 32) {
        float4 xa = *(const float4*)&X[(m0 + lrow) * HID + k0 + lk];
        float4 xb = *(const float4*)&X[(m0 + lrow) * HID + k0 + lk + 4];
        *(float4*)&As[lrow][lk]     = xa;
        *(float4*)&As[lrow][lk + 4] = xb;
        float4 wa = *(const float4*)&W[(k0 + bkk) * N + n0 + bn8];
        float4 wb = *(const float4*)&W[(k0 + bkk) * N + n0 + bn8 + 4];
        *(float4*)&Bs[bkk][bn8]     = wa;
        *(float4*)&Bs[bkk][bn8 + 4] = wb;
        __syncthreads();
#pragma unroll
        for (int kk = 0; kk < 32; kk++) {
            ulonglong2 bv = *(const ulonglong2*)&Bs[kk][tn4];
            u64 s0 = splat2(As[tm4 + 0][kk]);
            u64 s1 = splat2(As[tm4 + 1][kk]);
            u64 s2 = splat2(As[tm4 + 2][kk]);
            u64 s3 = splat2(As[tm4 + 3][kk]);
            ffma2(acc[0][0], s0, bv.x); ffma2(acc[0][1], s0, bv.y);
            ffma2(acc[1][0], s1, bv.x); ffma2(acc[1][1], s1, bv.y);
            ffma2(acc[2][0], s2, bv.x); ffma2(acc[2][1], s2, bv.y);
            ffma2(acc[3][0], s3, bv.x); ffma2(acc[3][1], s3, bv.y);
        }
        __syncthreads();
    }
#pragma unroll
    for (int i = 0; i < 4; i++) {
        float2 lo = unpk(acc[i][0]);
        float2 hi = unpk(acc[i][1]);
        *(float4*)&C[(m0 + tm4 + i) * N + n0 + tn4] = make_float4(lo.x, lo.y, hi.x, hi.y);
    }
}

__global__ void __launch_bounds__(256) qkv_kernel(const float* __restrict__ x,
                                                  const float* __restrict__ Wq,
                                                  const float* __restrict__ Wk,
                                                  const float* __restrict__ Wv) {
    const int gx = blockIdx.x;
    const int mat = gx % 3;
    const int n0 = (gx / 3) * 64;
    const int m0 = blockIdx.y * 128;
    const float* W = (mat == 0) ? Wq : (mat == 1) ? Wk : Wv;
    float* C = (mat == 0) ? g_Q0 : (mat == 1) ? g_K0 : g_V0;
    gemm_tile128(x, W, C, KD, m0, n0);
}

__global__ void __launch_bounds__(256) out_kernel(const float* __restrict__ Wo,
                                                  float* __restrict__ out) {
    gemm_tile64(g_on, Wo, out, HID, blockIdx.y * 64, blockIdx.x * 64);
}

// ---------------- prep (conv+silu+l2norm) fused with beta/decay ----------------
__device__ __forceinline__ void conv_silu_l2(const float* __restrict__ src,
                                             const float* __restrict__ cw,
                                             float* __restrict__ dst,
                                             int t, int tid) {
    const int c0 = tid * 8;
    float wv[8][4];
#pragma unroll
    for (int e = 0; e < 8; e++) {
        float4 f = *(const float4*)&cw[(c0 + e) * 4];
        wv[e][0] = f.x; wv[e][1] = f.y; wv[e][2] = f.z; wv[e][3] = f.w;
    }
    float y[8];
#pragma unroll
    for (int e = 0; e < 8; e++) y[e] = 0.f;
#pragma unroll
    for (int i = 0; i < 4; i++) {
        int ts = t + i - 3;
        if (ts >= 0) {
            float4 xa = *(const float4*)&src[ts * HID + c0];
            float4 xb = *(const float4*)&src[ts * HID + c0 + 4];
            float xv[8] = {xa.x, xa.y, xa.z, xa.w, xb.x, xb.y, xb.z, xb.w};
#pragma unroll
            for (int e = 0; e < 8; e++) y[e] += xv[e] * wv[e][i];
        }
    }
#pragma unroll
    for (int e = 0; e < 8; e++) {
        float s = 1.f / (1.f + expf(-y[e]));
        y[e] *= s;
    }
    float ss = 0.f;
#pragma unroll
    for (int e = 0; e < 8; e++) ss += y[e] * y[e];
#pragma unroll
    for (int off = 1; off <= 8; off <<= 1) ss += __shfl_xor_sync(0xffffffffu, ss, off);
    float sc = rsqrtf(ss + 1e-6f);
    float4 o0 = make_float4(y[0] * sc, y[1] * sc, y[2] * sc, y[3] * sc);
    float4 o1 = make_float4(y[4] * sc, y[5] * sc, y[6] * sc, y[7] * sc);
    *(float4*)&dst[t * HID + c0] = o0;
    *(float4*)&dst[t * HID + c0 + 4] = o1;
}

__global__ void __launch_bounds__(256) prep_kernel(const float* __restrict__ cwq,
                                                   const float* __restrict__ cwk,
                                                   const float* __restrict__ x,
                                                   const float* __restrict__ Wa,
                                                   const float* __restrict__ ba,
                                                   const float* __restrict__ Wb,
                                                   const float* __restrict__ bb) {
    const int tid = threadIdx.x;
    if (blockIdx.x < 256) {
        const int t = blockIdx.x;
        conv_silu_l2(g_Q0, cwq, g_qn, t, tid);
        conv_silu_l2(g_K0, cwk, g_kn, t, tid);
        return;
    }
    // ---- beta/decay mini-GEMM path: blocks 256..271 ----
    __shared__ float Xs[32][17];
    __shared__ float Ws[32][32];
    const int m0 = (blockIdx.x - 256) * 16;
    const int n = tid & 31;
    const int mg = tid >> 5;
    const int lxm = tid >> 4;
    const int lxk = (tid & 15) * 2;

    float acc0 = 0.f, acc1 = 0.f;
    for (int k0 = 0; k0 < HID; k0 += 32) {
        float2 xv = *(const float2*)&x[(m0 + lxm) * HID + k0 + lxk];
        Xs[lxk][lxm] = xv.x;
        Xs[lxk + 1][lxm] = xv.y;
        const int i4 = tid * 4;
        const int wk = i4 >> 5, wn = i4 & 31;
#pragma unroll
        for (int j = 0; j < 4; j++) {
            int nn = wn + j;
            Ws[wk][nn] = (nn < 16) ? Wa[(k0 + wk) * NHEAD + nn]
                                   : Wb[(k0 + wk) * NHEAD + nn - 16];
        }
        __syncthreads();
#pragma unroll
        for (int kk = 0; kk < 32; kk++) {
            float w = Ws[kk][n];
            acc0 += Xs[kk][mg * 2] * w;
            acc1 += Xs[kk][mg * 2 + 1] * w;
        }
        __syncthreads();
    }
    const int row0 = m0 + mg * 2;
    if (n < 16) {
        float z0 = acc0 + ba[n], z1 = acc1 + ba[n];
        g_decay[row0 * NHEAD + n] = 1.f / (1.f + expf(-z0));
        g_decay[(row0 + 1) * NHEAD + n] = 1.f / (1.f + expf(-z1));
    } else {
        int c = n - 16;
        float z0 = acc0 + bb[c], z1 = acc1 + bb[c];
        g_beta[row0 * NHEAD + c] = 1.f / (1.f + expf(-z0));
        g_beta[(row0 + 1) * NHEAD + c] = 1.f / (1.f + expf(-z1));
    }
}

// ---------------- state scan: checkpoints every CHUNK steps ----------------
__global__ void scan_kernel() {
    const int h = blockIdx.y;
    const int i0 = blockIdx.x * 8;
    const int tid = threadIdx.x;
    __shared__ float ds[T_LEN], bs[T_LEN];
    __shared__ __align__(16) float ks[2][DHEAD], vs[2][DHEAD];
    ds[tid] = g_decay[tid * NHEAD + h];
    bs[tid] = g_beta[tid * NHEAD + h];
    if (tid < 32)
        *(float4*)&ks[0][tid * 4] = *(const float4*)&g_kn[h * DHEAD + tid * 4];
    else if (tid < 64) {
        int l = tid - 32;
        *(float4*)&vs[0][l * 4] = *(const float4*)&g_V0[h * DHEAD + l * 4];
    }
    const int row = i0 + (tid >> 5);
    const int j0 = (tid & 31) * 4;
    float kk0 = 0, kk1 = 0, kk2 = 0, kk3 = 0;
    float kv0 = 0, kv1 = 0, kv2 = 0, kv3 = 0;
    for (int t = 0; t < T_LEN; t++) {
        __syncthreads();
        const int cb = t & 1, nb = (t + 1) & 1;
        if (t + 1 < T_LEN) {
            if (tid < 32)
                *(float4*)&ks[nb][tid * 4] =
                    *(const float4*)&g_kn[(t + 1) * HID + h * DHEAD + tid * 4];
            else if (tid < 64) {
                int l = tid - 32;
                *(float4*)&vs[nb][l * 4] =
                    *(const float4*)&g_V0[(t + 1) * HID + h * DHEAD + l * 4];
            }
        }
        const float d = ds[t], b = bs[t];
        const float kr = ks[cb][row];
        float4 kj = *(const float4*)&ks[cb][j0];
        float4 vj = *(const float4*)&vs[cb][j0];
        const float bk = b * kr;
        kk0 = kk0 * d + bk * kj.x; kk1 = kk1 * d + bk * kj.y;
        kk2 = kk2 * d + bk * kj.z; kk3 = kk3 * d + bk * kj.w;
        kv0 = kv0 * d + bk * vj.x; kv1 = kv1 * d + bk * vj.y;
        kv2 = kv2 * d + bk * vj.z; kv3 = kv3 * d + bk * vj.w;
        if (((t + 1) & (CHUNK - 1)) == 0) {
            const int slot = t / CHUNK;
            size_t base = (((size_t)slot * NHEAD + h) << 14) + (size_t)row * DHEAD + j0;
            *(float4*)&g_hkk_ck[base] = make_float4(kk0, kk1, kk2, kk3);
            *(float4*)&g_hkv_ck[base] = make_float4(kv0, kv1, kv2, kv3);
        }
    }
}

// ---------------- block reduce (parity-buffered) ----------------
__device__ __forceinline__ float blockReduce128(float v, int pb) {
    __shared__ float red[2][4];
#pragma unroll
    for (int off = 16; off > 0; off >>= 1) v += __shfl_xor_sync(0xffffffffu, v, off);
    const int w = threadIdx.x >> 5;
    if ((threadIdx.x & 31) == 0) red[pb][w] = v;
    __syncthreads();
    return red[pb][0] + red[pb][1] + red[pb][2] + red[pb][3];
}

// ---------------- CG solve (recon + early exit) + output + rmsnorm ----------------
__global__ void __launch_bounds__(128, 4) solve_kernel(const float* __restrict__ onw,
                                                       const float* __restrict__ lp) {
    const int h = blockIdx.x;
    const int t = blockIdx.y;
    const int r = threadIdx.x;
    const int cs = t & ~(CHUNK - 1);
    const int jend = t - cs;            // 0..7
    const int slot = (t / CHUNK) - 1;

    __shared__ __align__(16) float ks[CHUNK][DHEAD];
    __shared__ __align__(16) float vs[CHUNK][DHEAD];
    __shared__ __align__(16) float ps[DHEAD];
    __shared__ float dsh[CHUNK], bsh[CHUNK], Pp[CHUNK], cf[CHUNK], gsh[CHUNK];

    {
        const int row = r >> 4;             // 0..7
        const int c0 = (r & 15) * 8;
        const float* kp = &g_kn[(cs + row) * HID + h * DHEAD + c0];
        const float* vp = &g_V0[(cs + row) * HID + h * DHEAD + c0];
#pragma unroll
        for (int q = 0; q < 2; q++) {
            *(float4*)&ks[row][c0 + q * 4] = *(const float4*)&kp[q * 4];
            *(float4*)&vs[row][c0 + q * 4] = *(const float4*)&vp[q * 4];
        }
        if (r < CHUNK) {
            dsh[r] = g_decay[(cs + r) * NHEAD + h];
            bsh[r] = g_beta[(cs + r) * NHEAD + h];
        }
    }
    __syncthreads();
    if (r == 0) {
        float run = 1.f;
#pragma unroll
        for (int s = 0; s < CHUNK; s++) {
            run *= dsh[s];
            Pp[s] = run;
            cf[s] = bsh[s] / run;
        }
    }
    __syncthreads();
    const float Pt = Pp[jend];

    // build A row r in registers
    ulonglong2 A2[32];
    if (slot >= 0) {
        const float* base = g_hkk_ck + (((size_t)slot * NHEAD + h) << 14) + (size_t)r * DHEAD;
#pragma unroll
        for (int i = 0; i < 32; i++) A2[i] = *(const ulonglong2*)&base[i * 4];
    } else {
#pragma unroll
        for (int i = 0; i < 32; i++) { A2[i].x = 0ull; A2[i].y = 0ull; }
    }
    for (int s = 0; s <= jend; s++) {
        u64 w = splat2(cf[s] * ks[s][r]);
        const u64* kkp = (const u64*)&ks[s][0];
#pragma unroll
        for (int i = 0; i < 32; i++) {
            ffma2(A2[i].x, w, kkp[2 * i]);
            ffma2(A2[i].y, w, kkp[2 * i + 1]);
        }
    }
    {
        u64 pt2 = splat2(Pt);
#pragma unroll
        for (int i = 0; i < 32; i++) { mul2(A2[i].x, pt2); mul2(A2[i].y, pt2); }
    }

    // lambda = softplus(lp) + 0.25, inline
    float lam;
    {
        float v = lp[h * DHEAD + r];
        lam = ((v > 20.f) ? v : log1pf(expf(v))) + 0.25f;
    }
    const float b = g_qn[t * HID + h * DHEAD + r];

    float xx = 0.f, rr = b, p = b;
    ps[r] = b;
    int par = 0;
    float rs = blockReduce128(b * b, par); par ^= 1;
    const float rs_stop = 1e-10f * rs;

    for (int it = 0; it < 30; it++) {
        u64 aA = 0ull, aB = 0ull, aC = 0ull, aD = 0ull;
#pragma unroll
        for (int i = 0; i < 32; i += 2) {
            ulonglong2 p0 = *(const ulonglong2*)&ps[i * 4];
            ulonglong2 p1 = *(const ulonglong2*)&ps[i * 4 + 4];
            ffma2(aA, A2[i].x, p0.x);     ffma2(aB, A2[i].y, p0.y);
            ffma2(aC, A2[i + 1].x, p1.x); ffma2(aD, A2[i + 1].y, p1.y);
        }
        float2 fa = unpk(aA), fb = unpk(aB), fc = unpk(aC), fd = unpk(aD);
        float ap = ((fa.x + fa.y) + (fb.x + fb.y)) + ((fc.x + fc.y) + (fd.x + fd.y)) + lam * p;
        float pap = blockReduce128(p * ap, par); par ^= 1;
        float alpha = rs / (pap + 1e-12f);
        xx += alpha * p;
        rr -= alpha * ap;
        float rsn = blockReduce128(rr * rr, par); par ^= 1;
        if (rsn < rs_stop) break;   // converged: remaining reference iters are no-ops
        float bet = rsn / (rs + 1e-12f);
        p = rr + bet * p;
        rs = rsn;
        ps[r] = p;
        __syncthreads();
    }

    // ---- output: o = Pt*(x^T hkv_base) + sum_s cf[s]*Pt*(k_s.x)*v_s ----
    ps[r] = xx;
    __syncthreads();
    {
        const int sIdx = r >> 4;            // 0..7, 16 threads per s
        const int part = r & 15;
        float pg = 0.f;
        const int e0 = part * 8;
#pragma unroll
        for (int e = 0; e < 8; e++) pg += ks[sIdx][e0 + e] * ps[e0 + e];
#pragma unroll
        for (int off = 1; off <= 8; off <<= 1) pg += __shfl_xor_sync(0xffffffffu, pg, off);
        if (part == 0)
            gsh[sIdx] = (sIdx <= jend) ? pg * cf[sIdx] * Pt : 0.f;
    }
    __syncthreads();

    float o = 0.f;
    if (slot >= 0) {
        const float* kvb = g_hkv_ck + (((size_t)slot * NHEAD + h) << 14) + r;
        float o0 = 0, o1 = 0, o2 = 0, o3 = 0;
#pragma unroll
        for (int k2 = 0; k2 < DHEAD; k2 += 4) {
            o0 += ps[k2]     * kvb[(size_t)k2 * DHEAD];
            o1 += ps[k2 + 1] * kvb[(size_t)(k2 + 1) * DHEAD];
            o2 += ps[k2 + 2] * kvb[(size_t)(k2 + 2) * DHEAD];
            o3 += ps[k2 + 3] * kvb[(size_t)(k2 + 3) * DHEAD];
        }
        o = Pt * ((o0 + o1) + (o2 + o3));
    }
#pragma unroll
    for (int s = 0; s < CHUNK; s++) o += gsh[s] * vs[s][r];

    float ms = blockReduce128(o * o, par) * (1.0f / 128.0f);
    float sc = rsqrtf(ms + 1e-5f);
    g_on[t * HID + h * DHEAD + r] = o * sc * onw[r];
}

// ---------------- launch ----------------
extern "C" void kernel_launch(void* const* d_in, const int* in_sizes, int n_in,
                              void* d_out, int out_size) {
    const float* x    = (const float*)d_in[0];
    const float* Wq   = (const float*)d_in[1];
    const float* Wk   = (const float*)d_in[2];
    const float* Wv   = (const float*)d_in[3];
    const float* Wa   = (const float*)d_in[4];
    const float* ba   = (const float*)d_in[5];
    const float* Wb   = (const float*)d_in[6];
    const float* bb   = (const float*)d_in[7];
    const float* cwq  = (const float*)d_in[8];
    const float* cwk  = (const float*)d_in[9];
    const float* lp   = (const float*)d_in[10];
    const float* onw  = (const float*)d_in[11];
    const float* Wo   = (const float*)d_in[12];
    float* out = (float*)d_out;

    qkv_kernel<<<dim3(96, 2), 256>>>(x, Wq, Wk, Wv);
    prep_kernel<<<272, 256>>>(cwq, cwk, x, Wa, ba, Wb, bb);
    scan_kernel<<<dim3(16, NHEAD), 256>>>();
    solve_kernel<<<dim3(NHEAD, T_LEN), 128>>>(onw, lp);
    out_kernel<<<dim3(HID / 64, T_LEN / 64), 256>>>(Wo, out);
}

// round 7
// speedup vs baseline: 1.5612x; 1.0981x over previous
#include <cuda_runtime.h>
#include <math.h>

#define T_LEN 256
#define HID   2048
#define NHEAD 16
#define DHEAD 128
#define KD    2048
#define CHUNK 8
#define NSLOT (T_LEN / CHUNK)

// ---------------- scratch ----------------
__device__ float g_Q0[T_LEN * KD];
__device__ float g_K0[T_LEN * KD];
__device__ float g_V0[T_LEN * KD];
__device__ float g_qn[T_LEN * KD];
__device__ float g_kn[T_LEN * KD];
__device__ float g_beta[T_LEN * NHEAD];
__device__ float g_decay[T_LEN * NHEAD];
__device__ float g_on[T_LEN * KD];
__device__ float g_hkk_ck[(size_t)NSLOT * NHEAD * DHEAD * DHEAD];  // 32 MB
__device__ float g_hkv_ck[(size_t)NSLOT * NHEAD * DHEAD * DHEAD];  // 32 MB

// ---------------- f32x2 helpers ----------------
typedef unsigned long long u64;
__device__ __forceinline__ u64 splat2(float a) {
    u64 d; unsigned u = __float_as_uint(a);
    asm("mov.b64 %0, {%1, %1};" : "=l"(d) : "r"(u));
    return d;
}
__device__ __forceinline__ void ffma2(u64& d, u64 a, u64 b) {
    asm("fma.rn.f32x2 %0, %1, %2, %0;" : "+l"(d) : "l"(a), "l"(b));
}
__device__ __forceinline__ float2 unpk(u64 v) {
    unsigned lo, hi;
    asm("mov.b64 {%0, %1}, %2;" : "=r"(lo), "=r"(hi) : "l"(v));
    return make_float2(__uint_as_float(lo), __uint_as_float(hi));
}

// ---------------- GEMM 128x64 tile (qkv), 256 threads ----------------
__device__ __forceinline__ void gemm_tile128(const float* __restrict__ X,
                                             const float* __restrict__ W,
                                             float* __restrict__ C, int N,
                                             int m0, int n0) {
    __shared__ __align__(16) float As[128][36];
    __shared__ __align__(16) float Bs[32][64];
    const int tid = threadIdx.x;
    const int tn4 = (tid & 15) * 4;
    const int tm8 = (tid >> 4) * 8;
    const int arow = tid >> 1;
    const int akoff = (tid & 1) * 16;
    const int brow = tid >> 3;
    const int bcol = (tid & 7) * 8;

    u64 acc[8][2];
#pragma unroll
    for (int i = 0; i < 8; i++) { acc[i][0] = 0ull; acc[i][1] = 0ull; }

    for (int k0 = 0; k0 < HID; k0 += 32) {
        const float* xp = &X[(m0 + arow) * HID + k0 + akoff];
#pragma unroll
        for (int q = 0; q < 4; q++)
            *(float4*)&As[arow][akoff + q * 4] = *(const float4*)&xp[q * 4];
        const float* wp = &W[(k0 + brow) * N + n0 + bcol];
        *(float4*)&Bs[brow][bcol]     = *(const float4*)&wp[0];
        *(float4*)&Bs[brow][bcol + 4] = *(const float4*)&wp[4];
        __syncthreads();
#pragma unroll
        for (int kk = 0; kk < 32; kk++) {
            ulonglong2 bv = *(const ulonglong2*)&Bs[kk][tn4];
#pragma unroll
            for (int i = 0; i < 8; i++) {
                u64 s = splat2(As[tm8 + i][kk]);
                ffma2(acc[i][0], s, bv.x);
                ffma2(acc[i][1], s, bv.y);
            }
        }
        __syncthreads();
    }
#pragma unroll
    for (int i = 0; i < 8; i++) {
        float2 lo = unpk(acc[i][0]);
        float2 hi = unpk(acc[i][1]);
        *(float4*)&C[(m0 + tm8 + i) * N + n0 + tn4] = make_float4(lo.x, lo.y, hi.x, hi.y);
    }
}

// ---------------- GEMM 64x64 tile (out), 256 threads ----------------
__device__ __forceinline__ void gemm_tile64(const float* __restrict__ X,
                                            const float* __restrict__ W,
                                            float* __restrict__ C, int N,
                                            int m0, int n0) {
    __shared__ __align__(16) float As[64][36];
    __shared__ __align__(16) float Bs[32][64];
    const int tid = threadIdx.x;
    const int tn4 = (tid & 15) * 4;
    const int tm4 = (tid >> 4) * 4;
    const int lrow = tid >> 2;
    const int lk   = (tid & 3) * 8;
    const int bkk  = tid >> 3;
    const int bn8  = (tid & 7) * 8;

    u64 acc[4][2];
#pragma unroll
    for (int i = 0; i < 4; i++) { acc[i][0] = 0ull; acc[i][1] = 0ull; }

    for (int k0 = 0; k0 < HID; k0 += 32) {
        float4 xa = *(const float4*)&X[(m0 + lrow) * HID + k0 + lk];
        float4 xb = *(const float4*)&X[(m0 + lrow) * HID + k0 + lk + 4];
        *(float4*)&As[lrow][lk]     = xa;
        *(float4*)&As[lrow][lk + 4] = xb;
        float4 wa = *(const float4*)&W[(k0 + bkk) * N + n0 + bn8];
        float4 wb = *(const float4*)&W[(k0 + bkk) * N + n0 + bn8 + 4];
        *(float4*)&Bs[bkk][bn8]     = wa;
        *(float4*)&Bs[bkk][bn8 + 4] = wb;
        __syncthreads();
#pragma unroll
        for (int kk = 0; kk < 32; kk++) {
            ulonglong2 bv = *(const ulonglong2*)&Bs[kk][tn4];
            u64 s0 = splat2(As[tm4 + 0][kk]);
            u64 s1 = splat2(As[tm4 + 1][kk]);
            u64 s2 = splat2(As[tm4 + 2][kk]);
            u64 s3 = splat2(As[tm4 + 3][kk]);
            ffma2(acc[0][0], s0, bv.x); ffma2(acc[0][1], s0, bv.y);
            ffma2(acc[1][0], s1, bv.x); ffma2(acc[1][1], s1, bv.y);
            ffma2(acc[2][0], s2, bv.x); ffma2(acc[2][1], s2, bv.y);
            ffma2(acc[3][0], s3, bv.x); ffma2(acc[3][1], s3, bv.y);
        }
        __syncthreads();
    }
#pragma unroll
    for (int i = 0; i < 4; i++) {
        float2 lo = unpk(acc[i][0]);
        float2 hi = unpk(acc[i][1]);
        *(float4*)&C[(m0 + tm4 + i) * N + n0 + tn4] = make_float4(lo.x, lo.y, hi.x, hi.y);
    }
}

__global__ void __launch_bounds__(256) qkv_kernel(const float* __restrict__ x,
                                                  const float* __restrict__ Wq,
                                                  const float* __restrict__ Wk,
                                                  const float* __restrict__ Wv) {
    const int gx = blockIdx.x;
    const int mat = gx % 3;
    const int n0 = (gx / 3) * 64;
    const int m0 = blockIdx.y * 128;
    const float* W = (mat == 0) ? Wq : (mat == 1) ? Wk : Wv;
    float* C = (mat == 0) ? g_Q0 : (mat == 1) ? g_K0 : g_V0;
    gemm_tile128(x, W, C, KD, m0, n0);
}

__global__ void __launch_bounds__(256) out_kernel(const float* __restrict__ Wo,
                                                  float* __restrict__ out) {
    gemm_tile64(g_on, Wo, out, HID, blockIdx.y * 64, blockIdx.x * 64);
}

// ---------------- prep (conv+silu+l2norm) fused with beta/decay ----------------
__device__ __forceinline__ void conv_silu_l2(const float* __restrict__ src,
                                             const float* __restrict__ cw,
                                             float* __restrict__ dst,
                                             int t, int tid) {
    const int c0 = tid * 8;
    float wv[8][4];
#pragma unroll
    for (int e = 0; e < 8; e++) {
        float4 f = *(const float4*)&cw[(c0 + e) * 4];
        wv[e][0] = f.x; wv[e][1] = f.y; wv[e][2] = f.z; wv[e][3] = f.w;
    }
    float y[8];
#pragma unroll
    for (int e = 0; e < 8; e++) y[e] = 0.f;
#pragma unroll
    for (int i = 0; i < 4; i++) {
        int ts = t + i - 3;
        if (ts >= 0) {
            float4 xa = *(const float4*)&src[ts * HID + c0];
            float4 xb = *(const float4*)&src[ts * HID + c0 + 4];
            float xv[8] = {xa.x, xa.y, xa.z, xa.w, xb.x, xb.y, xb.z, xb.w};
#pragma unroll
            for (int e = 0; e < 8; e++) y[e] += xv[e] * wv[e][i];
        }
    }
#pragma unroll
    for (int e = 0; e < 8; e++) {
        float s = 1.f / (1.f + expf(-y[e]));
        y[e] *= s;
    }
    float ss = 0.f;
#pragma unroll
    for (int e = 0; e < 8; e++) ss += y[e] * y[e];
#pragma unroll
    for (int off = 1; off <= 8; off <<= 1) ss += __shfl_xor_sync(0xffffffffu, ss, off);
    float sc = rsqrtf(ss + 1e-6f);
    float4 o0 = make_float4(y[0] * sc, y[1] * sc, y[2] * sc, y[3] * sc);
    float4 o1 = make_float4(y[4] * sc, y[5] * sc, y[6] * sc, y[7] * sc);
    *(float4*)&dst[t * HID + c0] = o0;
    *(float4*)&dst[t * HID + c0 + 4] = o1;
}

__global__ void __launch_bounds__(256) prep_kernel(const float* __restrict__ cwq,
                                                   const float* __restrict__ cwk,
                                                   const float* __restrict__ x,
                                                   const float* __restrict__ Wa,
                                                   const float* __restrict__ ba,
                                                   const float* __restrict__ Wb,
                                                   const float* __restrict__ bb) {
    const int tid = threadIdx.x;
    if (blockIdx.x < 256) {
        const int t = blockIdx.x;
        conv_silu_l2(g_Q0, cwq, g_qn, t, tid);
        conv_silu_l2(g_K0, cwk, g_kn, t, tid);
        return;
    }
    __shared__ float Xs[32][17];
    __shared__ float Ws[32][32];
    const int m0 = (blockIdx.x - 256) * 16;
    const int n = tid & 31;
    const int mg = tid >> 5;
    const int lxm = tid >> 4;
    const int lxk = (tid & 15) * 2;

    float acc0 = 0.f, acc1 = 0.f;
    for (int k0 = 0; k0 < HID; k0 += 32) {
        float2 xv = *(const float2*)&x[(m0 + lxm) * HID + k0 + lxk];
        Xs[lxk][lxm] = xv.x;
        Xs[lxk + 1][lxm] = xv.y;
        const int i4 = tid * 4;
        const int wk = i4 >> 5, wn = i4 & 31;
#pragma unroll
        for (int j = 0; j < 4; j++) {
            int nn = wn + j;
            Ws[wk][nn] = (nn < 16) ? Wa[(k0 + wk) * NHEAD + nn]
                                   : Wb[(k0 + wk) * NHEAD + nn - 16];
        }
        __syncthreads();
#pragma unroll
        for (int kk = 0; kk < 32; kk++) {
            float w = Ws[kk][n];
            acc0 += Xs[kk][mg * 2] * w;
            acc1 += Xs[kk][mg * 2 + 1] * w;
        }
        __syncthreads();
    }
    const int row0 = m0 + mg * 2;
    if (n < 16) {
        float z0 = acc0 + ba[n], z1 = acc1 + ba[n];
        g_decay[row0 * NHEAD + n] = 1.f / (1.f + expf(-z0));
        g_decay[(row0 + 1) * NHEAD + n] = 1.f / (1.f + expf(-z1));
    } else {
        int c = n - 16;
        float z0 = acc0 + bb[c], z1 = acc1 + bb[c];
        g_beta[row0 * NHEAD + c] = 1.f / (1.f + expf(-z0));
        g_beta[(row0 + 1) * NHEAD + c] = 1.f / (1.f + expf(-z1));
    }
}

// ---------------- state scan: checkpoints every CHUNK steps ----------------
__global__ void scan_kernel() {
    const int h = blockIdx.y;
    const int i0 = blockIdx.x * 8;
    const int tid = threadIdx.x;
    __shared__ float ds[T_LEN], bs[T_LEN];
    __shared__ __align__(16) float ks[2][DHEAD], vs[2][DHEAD];
    ds[tid] = g_decay[tid * NHEAD + h];
    bs[tid] = g_beta[tid * NHEAD + h];
    if (tid < 32)
        *(float4*)&ks[0][tid * 4] = *(const float4*)&g_kn[h * DHEAD + tid * 4];
    else if (tid < 64) {
        int l = tid - 32;
        *(float4*)&vs[0][l * 4] = *(const float4*)&g_V0[h * DHEAD + l * 4];
    }
    const int row = i0 + (tid >> 5);
    const int j0 = (tid & 31) * 4;
    float kk0 = 0, kk1 = 0, kk2 = 0, kk3 = 0;
    float kv0 = 0, kv1 = 0, kv2 = 0, kv3 = 0;
    for (int t = 0; t < T_LEN; t++) {
        __syncthreads();
        const int cb = t & 1, nb = (t + 1) & 1;
        if (t + 1 < T_LEN) {
            if (tid < 32)
                *(float4*)&ks[nb][tid * 4] =
                    *(const float4*)&g_kn[(t + 1) * HID + h * DHEAD + tid * 4];
            else if (tid < 64) {
                int l = tid - 32;
                *(float4*)&vs[nb][l * 4] =
                    *(const float4*)&g_V0[(t + 1) * HID + h * DHEAD + l * 4];
            }
        }
        const float d = ds[t], b = bs[t];
        const float kr = ks[cb][row];
        float4 kj = *(const float4*)&ks[cb][j0];
        float4 vj = *(const float4*)&vs[cb][j0];
        const float bk = b * kr;
        kk0 = kk0 * d + bk * kj.x; kk1 = kk1 * d + bk * kj.y;
        kk2 = kk2 * d + bk * kj.z; kk3 = kk3 * d + bk * kj.w;
        kv0 = kv0 * d + bk * vj.x; kv1 = kv1 * d + bk * vj.y;
        kv2 = kv2 * d + bk * vj.z; kv3 = kv3 * d + bk * vj.w;
        if (((t + 1) & (CHUNK - 1)) == 0) {
            const int slot = t / CHUNK;
            size_t base = (((size_t)slot * NHEAD + h) << 14) + (size_t)row * DHEAD + j0;
            *(float4*)&g_hkk_ck[base] = make_float4(kk0, kk1, kk2, kk3);
            *(float4*)&g_hkv_ck[base] = make_float4(kv0, kv1, kv2, kv3);
        }
    }
}

// ---------------- block reduce (parity-buffered) ----------------
__device__ __forceinline__ float blockReduce128(float v, int pb) {
    __shared__ float red[2][4];
#pragma unroll
    for (int off = 16; off > 0; off >>= 1) v += __shfl_xor_sync(0xffffffffu, v, off);
    const int w = threadIdx.x >> 5;
    if ((threadIdx.x & 31) == 0) red[pb][w] = v;
    __syncthreads();
    return red[pb][0] + red[pb][1] + red[pb][2] + red[pb][3];
}

// ---------------- merged CG solve: one block per (head, chunk), 8 t's each ----------------
__global__ void __launch_bounds__(128, 4) solve_kernel(const float* __restrict__ onw,
                                                       const float* __restrict__ lp) {
    const int h = blockIdx.x;
    const int chunk = blockIdx.y;        // 0..31
    const int cs = chunk * CHUNK;
    const int slot = chunk - 1;          // checkpoint before this chunk
    const int r = threadIdx.x;

    __shared__ __align__(16) float ks[CHUNK][DHEAD];
    __shared__ __align__(16) float vs[CHUNK][DHEAD];
    __shared__ __align__(16) float ps[DHEAD];
    __shared__ float dsh[CHUNK], bsh[CHUNK], Pp[CHUNK], cf[CHUNK], gsh[CHUNK];

    {
        const int row = r >> 4;             // 0..7
        const int c0 = (r & 15) * 8;
        const float* kp = &g_kn[(cs + row) * HID + h * DHEAD + c0];
        const float* vp = &g_V0[(cs + row) * HID + h * DHEAD + c0];
        *(float4*)&ks[row][c0]     = *(const float4*)&kp[0];
        *(float4*)&ks[row][c0 + 4] = *(const float4*)&kp[4];
        *(float4*)&vs[row][c0]     = *(const float4*)&vp[0];
        *(float4*)&vs[row][c0 + 4] = *(const float4*)&vp[4];
        if (r < CHUNK) {
            dsh[r] = g_decay[(cs + r) * NHEAD + h];
            bsh[r] = g_beta[(cs + r) * NHEAD + h];
        }
    }
    __syncthreads();
    if (r == 0) {
        float run = 1.f;
#pragma unroll
        for (int s = 0; s < CHUNK; s++) {
            run *= dsh[s];
            Pp[s] = run;
            cf[s] = bsh[s] / run;
        }
    }

    // lambda = softplus(lp) + 0.25
    float lam;
    {
        float v = lp[h * DHEAD + r];
        lam = ((v > 20.f) ? v : log1pf(expf(v))) + 0.25f;
    }

    // un-scaled state row B (A_t = Pt*B_t + Lambda); checkpoint loaded ONCE per block
    ulonglong2 B2[32];
    if (slot >= 0) {
        const float* base = g_hkk_ck + (((size_t)slot * NHEAD + h) << 14) + (size_t)r * DHEAD;
#pragma unroll
        for (int i = 0; i < 32; i++) B2[i] = *(const ulonglong2*)&base[i * 4];
    } else {
#pragma unroll
        for (int i = 0; i < 32; i++) { B2[i].x = 0ull; B2[i].y = 0ull; }
    }
    const float* kvb = (slot >= 0)
        ? g_hkv_ck + (((size_t)slot * NHEAD + h) << 14) + r : (const float*)0;
    __syncthreads();   // Pp/cf visible

    int par = 0;
    for (int jt = 0; jt < CHUNK; jt++) {
        const int t = cs + jt;
        // grow B by rank-1 update for s = jt
        {
            u64 w = splat2(cf[jt] * ks[jt][r]);
            const u64* kkp = (const u64*)&ks[jt][0];
#pragma unroll
            for (int i = 0; i < 32; i++) {
                ffma2(B2[i].x, w, kkp[2 * i]);
                ffma2(B2[i].y, w, kkp[2 * i + 1]);
            }
        }
        const float Pt = Pp[jt];
        const float b = g_qn[t * HID + h * DHEAD + r];

        float xx = 0.f, rr = b, p = b;
        ps[r] = b;
        float rs = blockReduce128(b * b, par); par ^= 1;  // sync publishes ps
        const float rs_stop = 1e-10f * rs;

        for (int it = 0; it < 30; it++) {
            u64 aA = 0ull, aB = 0ull, aC = 0ull, aD = 0ull;
#pragma unroll
            for (int i = 0; i < 32; i += 2) {
                ulonglong2 p0 = *(const ulonglong2*)&ps[i * 4];
                ulonglong2 p1 = *(const ulonglong2*)&ps[i * 4 + 4];
                ffma2(aA, B2[i].x, p0.x);     ffma2(aB, B2[i].y, p0.y);
                ffma2(aC, B2[i + 1].x, p1.x); ffma2(aD, B2[i + 1].y, p1.y);
            }
            float2 fa = unpk(aA), fb = unpk(aB), fc = unpk(aC), fd = unpk(aD);
            float bp = ((fa.x + fa.y) + (fb.x + fb.y)) + ((fc.x + fc.y) + (fd.x + fd.y));
            float ap = Pt * bp + lam * p;
            float pap = blockReduce128(p * ap, par); par ^= 1;
            float alpha = rs / (pap + 1e-12f);
            xx += alpha * p;
            rr -= alpha * ap;
            float rsn = blockReduce128(rr * rr, par); par ^= 1;
            if (rsn < rs_stop) break;
            float bet = rsn / (rs + 1e-12f);
            p = rr + bet * p;
            rs = rsn;
            ps[r] = p;
            __syncthreads();
        }

        // ---- output: o = Pt*(x^T hkv_base) + sum_{s<=jt} cf[s]*Pt*(k_s.x)*v_s ----
        ps[r] = xx;
        __syncthreads();
        {
            const int sIdx = r >> 4;            // 16 threads per s
            const int part = r & 15;
            float pg = 0.f;
            const int e0 = part * 8;
#pragma unroll
            for (int e = 0; e < 8; e++) pg += ks[sIdx][e0 + e] * ps[e0 + e];
#pragma unroll
            for (int off = 1; off <= 8; off <<= 1) pg += __shfl_xor_sync(0xffffffffu, pg, off);
            if (part == 0)
                gsh[sIdx] = (sIdx <= jt) ? pg * cf[sIdx] * Pt : 0.f;
        }
        __syncthreads();

        float o = 0.f;
        if (slot >= 0) {
            float o0 = 0, o1 = 0, o2 = 0, o3 = 0;
#pragma unroll
            for (int k2 = 0; k2 < DHEAD; k2 += 4) {
                o0 += ps[k2]     * kvb[(size_t)k2 * DHEAD];
                o1 += ps[k2 + 1] * kvb[(size_t)(k2 + 1) * DHEAD];
                o2 += ps[k2 + 2] * kvb[(size_t)(k2 + 2) * DHEAD];
                o3 += ps[k2 + 3] * kvb[(size_t)(k2 + 3) * DHEAD];
            }
            o = Pt * ((o0 + o1) + (o2 + o3));
        }
#pragma unroll
        for (int s = 0; s < CHUNK; s++) o += gsh[s] * vs[s][r];

        float ms = blockReduce128(o * o, par) * (1.0f / 128.0f); par ^= 1;
        float sc = rsqrtf(ms + 1e-5f);
        g_on[t * HID + h * DHEAD + r] = o * sc * onw[r];
        __syncthreads();   // protect ps/gsh before next t
    }
}

// ---------------- launch ----------------
extern "C" void kernel_launch(void* const* d_in, const int* in_sizes, int n_in,
                              void* d_out, int out_size) {
    const float* x    = (const float*)d_in[0];
    const float* Wq   = (const float*)d_in[1];
    const float* Wk   = (const float*)d_in[2];
    const float* Wv   = (const float*)d_in[3];
    const float* Wa   = (const float*)d_in[4];
    const float* ba   = (const float*)d_in[5];
    const float* Wb   = (const float*)d_in[6];
    const float* bb   = (const float*)d_in[7];
    const float* cwq  = (const float*)d_in[8];
    const float* cwk  = (const float*)d_in[9];
    const float* lp   = (const float*)d_in[10];
    const float* onw  = (const float*)d_in[11];
    const float* Wo   = (const float*)d_in[12];
    float* out = (float*)d_out;

    qkv_kernel<<<dim3(96, 2), 256>>>(x, Wq, Wk, Wv);
    prep_kernel<<<272, 256>>>(cwq, cwk, x, Wa, ba, Wb, bb);
    scan_kernel<<<dim3(16, NHEAD), 256>>>();
    solve_kernel<<<dim3(NHEAD, NSLOT), 128>>>(onw, lp);
    out_kernel<<<dim3(HID / 64, T_LEN / 64), 256>>>(Wo, out);
}

// round 8
// speedup vs baseline: 1.8125x; 1.1610x over previous
#include <cuda_runtime.h>
#include <cuda_bf16.h>
#include <math.h>

#define T_LEN 256
#define HID   2048
#define NHEAD 16
#define DHEAD 128
#define KD    2048
#define CHUNK 8
#define NSLOT (T_LEN / CHUNK)
#define WELEM (KD * HID)        // 4194304 elems per weight matrix

// ---------------- scratch ----------------
__device__ float g_Q0[T_LEN * KD];
__device__ float g_K0[T_LEN * KD];
__device__ float g_V0[T_LEN * KD];
__device__ float g_qn[T_LEN * KD];
__device__ float g_kn[T_LEN * KD];
__device__ float g_beta[T_LEN * NHEAD];
__device__ float g_decay[T_LEN * NHEAD];
__device__ float g_on[T_LEN * KD];
__device__ float g_hkk_ck[(size_t)NSLOT * NHEAD * DHEAD * DHEAD];
__device__ float g_hkv_ck[(size_t)NSLOT * NHEAD * DHEAD * DHEAD];
// bf16 split-precision operands
__device__ __nv_bfloat16 g_xhi[T_LEN * HID];
__device__ __nv_bfloat16 g_xlo[T_LEN * HID];
__device__ __nv_bfloat16 g_onhi[T_LEN * KD];
__device__ __nv_bfloat16 g_onlo[T_LEN * KD];
__device__ __nv_bfloat16 g_wthi[(size_t)4 * WELEM];   // transposed [n][k], mats q,k,v,o
__device__ __nv_bfloat16 g_wtlo[(size_t)4 * WELEM];

// ---------------- f32x2 helpers (solve path) ----------------
typedef unsigned long long u64;
__device__ __forceinline__ u64 splat2(float a) {
    u64 d; unsigned u = __float_as_uint(a);
    asm("mov.b64 %0, {%1, %1};" : "=l"(d) : "r"(u));
    return d;
}
__device__ __forceinline__ void ffma2(u64& d, u64 a, u64 b) {
    asm("fma.rn.f32x2 %0, %1, %2, %0;" : "+l"(d) : "l"(a), "l"(b));
}
__device__ __forceinline__ float2 unpk(u64 v) {
    unsigned lo, hi;
    asm("mov.b64 {%0, %1}, %2;" : "=r"(lo), "=r"(hi) : "l"(v));
    return make_float2(__uint_as_float(lo), __uint_as_float(hi));
}

// ---------------- tensor-core helpers ----------------
__device__ __forceinline__ unsigned smem_u32(const void* p) {
    unsigned a;
    asm("{ .reg .u64 t; cvta.to.shared.u64 t, %1; cvt.u32.u64 %0, t; }" : "=r"(a) : "l"(p));
    return a;
}
__device__ __forceinline__ void ldm4(unsigned (&r)[4], unsigned addr) {
    asm volatile("ldmatrix.sync.aligned.m8n8.x4.shared.b16 {%0,%1,%2,%3}, [%4];"
        : "=r"(r[0]), "=r"(r[1]), "=r"(r[2]), "=r"(r[3]) : "r"(addr));
}
__device__ __forceinline__ void mma16816(float (&c)[4], const unsigned (&a)[4],
                                         unsigned b0, unsigned b1) {
    asm volatile("mma.sync.aligned.m16n8k16.row.col.f32.bf16.bf16.f32 "
        "{%0,%1,%2,%3}, {%4,%5,%6,%7}, {%8,%9}, {%0,%1,%2,%3};"
        : "+f"(c[0]), "+f"(c[1]), "+f"(c[2]), "+f"(c[3])
        : "r"(a[0]), "r"(a[1]), "r"(a[2]), "r"(a[3]), "r"(b0), "r"(b1));
}
__device__ __forceinline__ void splitbf(float x, __nv_bfloat16& h, __nv_bfloat16& l) {
    h = __float2bfloat16_rn(x);
    l = __float2bfloat16_rn(x - __bfloat162float(h));
}
__device__ __forceinline__ unsigned pk2(__nv_bfloat16 a, __nv_bfloat16 b) {
    __nv_bfloat162 t = __halves2bfloat162(a, b);
    return *reinterpret_cast<unsigned*>(&t);
}

// ---------------- convert kernels ----------------
__global__ void __launch_bounds__(256) convert_x_kernel(const float* __restrict__ src,
                                                        __nv_bfloat16* __restrict__ hi,
                                                        __nv_bfloat16* __restrict__ lo) {
    const int i = (blockIdx.x * 256 + threadIdx.x) * 8;
    float4 a = *(const float4*)(src + i);
    float4 b = *(const float4*)(src + i + 4);
    float v[8] = {a.x, a.y, a.z, a.w, b.x, b.y, b.z, b.w};
    __nv_bfloat16 h[8], l[8];
#pragma unroll
    for (int e = 0; e < 8; e++) splitbf(v[e], h[e], l[e]);
    uint4 ph = make_uint4(pk2(h[0], h[1]), pk2(h[2], h[3]), pk2(h[4], h[5]), pk2(h[6], h[7]));
    uint4 pl = make_uint4(pk2(l[0], l[1]), pk2(l[2], l[3]), pk2(l[4], l[5]), pk2(l[6], l[7]));
    *(uint4*)(hi + i) = ph;
    *(uint4*)(lo + i) = pl;
}

// W [k][n] fp32 -> Wt hi/lo [n][k] bf16, 32x32 tiles. grid (4096, 4mats)
__global__ void __launch_bounds__(256) convert_wt_kernel(const float* __restrict__ W0,
                                                         const float* __restrict__ W1,
                                                         const float* __restrict__ W2,
                                                         const float* __restrict__ W3) {
    __shared__ float T[32][33];
    const int mat = blockIdx.y;
    const float* W = (mat == 0) ? W0 : (mat == 1) ? W1 : (mat == 2) ? W2 : W3;
    __nv_bfloat16* oh = g_wthi + (size_t)mat * WELEM;
    __nv_bfloat16* ol = g_wtlo + (size_t)mat * WELEM;
    const int k0 = (blockIdx.x & 63) * 32;
    const int n0 = (blockIdx.x >> 6) * 32;
    const int tid = threadIdx.x;
    const int r = tid >> 5, c = tid & 31;
#pragma unroll
    for (int p = 0; p < 4; p++) {
        int k = k0 + p * 8 + r;
        T[c][p * 8 + r] = W[(size_t)k * 2048 + n0 + c];
    }
    __syncthreads();
    const int nl = tid >> 3, kc = (tid & 7) * 4;
    float v0 = T[nl][kc], v1 = T[nl][kc + 1], v2 = T[nl][kc + 2], v3 = T[nl][kc + 3];
    __nv_bfloat16 h0, h1, h2, h3, l0, l1, l2, l3;
    splitbf(v0, h0, l0); splitbf(v1, h1, l1);
    splitbf(v2, h2, l2); splitbf(v3, h3, l3);
    uint2 ph = make_uint2(pk2(h0, h1), pk2(h2, h3));
    uint2 pl = make_uint2(pk2(l0, l1), pk2(l2, l3));
    size_t off = (size_t)(n0 + nl) * 2048 + k0 + kc;
    *(uint2*)(oh + off) = ph;
    *(uint2*)(ol + off) = pl;
}

// ---------------- tensor GEMM: C[64mx128n tile] = A[256,2048] @ Wt^T ----------------
// A: [m][k] bf16 hi/lo; B: Wt [n][k] bf16 hi/lo. 128 threads, 4 warps (2m x 2n of 32x64).
__device__ __forceinline__ void tensor_gemm_tile(const __nv_bfloat16* __restrict__ Ahi,
                                                 const __nv_bfloat16* __restrict__ Alo,
                                                 const __nv_bfloat16* __restrict__ Bth,
                                                 const __nv_bfloat16* __restrict__ Btl,
                                                 float* __restrict__ C,
                                                 int m0, int n0) {
    __shared__ __align__(16) __nv_bfloat16 sAh[64 * 40];
    __shared__ __align__(16) __nv_bfloat16 sAl[64 * 40];
    __shared__ __align__(16) __nv_bfloat16 sBh[128 * 40];
    __shared__ __align__(16) __nv_bfloat16 sBl[128 * 40];

    const int tid = threadIdx.x;
    const int lane = tid & 31;
    const int warp = tid >> 5;
    const int wm0 = (warp & 1) * 32;
    const int wn0 = (warp >> 1) * 64;

    float acc[2][8][4];
#pragma unroll
    for (int i = 0; i < 2; i++)
#pragma unroll
        for (int j = 0; j < 8; j++)
#pragma unroll
            for (int q = 0; q < 4; q++) acc[i][j][q] = 0.f;

    const unsigned baseAh = smem_u32(sAh), baseAl = smem_u32(sAl);
    const unsigned baseBh = smem_u32(sBh), baseBl = smem_u32(sBl);

    const int a_k = (lane >> 4) * 8;               // ldmatrix A k offset
    const int b_k = ((lane >> 3) & 1) * 8;         // ldmatrix B k offset
    const int a_r = lane & 15;
    const int b_r = ((lane >> 4) & 1) * 8 + (lane & 7);

    const int am = tid >> 1, aseg = (tid & 1) * 16;
    const size_t a_src = (size_t)(m0 + am) * 2048 + aseg;
    const size_t b_src = (size_t)(n0 + tid) * 2048;

    for (int k0 = 0; k0 < 2048; k0 += 32) {
        uint4 rah0 = *(const uint4*)(Ahi + a_src + k0);
        uint4 rah1 = *(const uint4*)(Ahi + a_src + k0 + 8);
        uint4 ral0 = *(const uint4*)(Alo + a_src + k0);
        uint4 ral1 = *(const uint4*)(Alo + a_src + k0 + 8);
        uint4 rbh0 = *(const uint4*)(Bth + b_src + k0);
        uint4 rbh1 = *(const uint4*)(Bth + b_src + k0 + 8);
        uint4 rbh2 = *(const uint4*)(Bth + b_src + k0 + 16);
        uint4 rbh3 = *(const uint4*)(Bth + b_src + k0 + 24);
        uint4 rbl0 = *(const uint4*)(Btl + b_src + k0);
        uint4 rbl1 = *(const uint4*)(Btl + b_src + k0 + 8);
        uint4 rbl2 = *(const uint4*)(Btl + b_src + k0 + 16);
        uint4 rbl3 = *(const uint4*)(Btl + b_src + k0 + 24);
        __syncthreads();
        *(uint4*)&sAh[am * 40 + aseg]     = rah0;
        *(uint4*)&sAh[am * 40 + aseg + 8] = rah1;
        *(uint4*)&sAl[am * 40 + aseg]     = ral0;
        *(uint4*)&sAl[am * 40 + aseg + 8] = ral1;
        *(uint4*)&sBh[tid * 40]      = rbh0;
        *(uint4*)&sBh[tid * 40 + 8]  = rbh1;
        *(uint4*)&sBh[tid * 40 + 16] = rbh2;
        *(uint4*)&sBh[tid * 40 + 24] = rbh3;
        *(uint4*)&sBl[tid * 40]      = rbl0;
        *(uint4*)&sBl[tid * 40 + 8]  = rbl1;
        *(uint4*)&sBl[tid * 40 + 16] = rbl2;
        *(uint4*)&sBl[tid * 40 + 24] = rbl3;
        __syncthreads();

#pragma unroll
        for (int ks = 0; ks < 2; ks++) {
            unsigned bh[4][4], bl[4][4];
#pragma unroll
            for (int p = 0; p < 4; p++) {
                unsigned addr = ((unsigned)((wn0 + p * 16 + b_r) * 40 + ks * 16 + b_k)) * 2;
                ldm4(bh[p], baseBh + addr);
                ldm4(bl[p], baseBl + addr);
            }
#pragma unroll
            for (int mi = 0; mi < 2; mi++) {
                unsigned ah[4], al[4];
                unsigned addr = ((unsigned)((wm0 + mi * 16 + a_r) * 40 + ks * 16 + a_k)) * 2;
                ldm4(ah, baseAh + addr);
                ldm4(al, baseAl + addr);
#pragma unroll
                for (int nj = 0; nj < 8; nj++) {
                    unsigned b0h = bh[nj >> 1][(nj & 1) * 2];
                    unsigned b1h = bh[nj >> 1][(nj & 1) * 2 + 1];
                    unsigned b0l = bl[nj >> 1][(nj & 1) * 2];
                    unsigned b1l = bl[nj >> 1][(nj & 1) * 2 + 1];
                    mma16816(acc[mi][nj], ah, b0h, b1h);
                    mma16816(acc[mi][nj], ah, b0l, b1l);
                    mma16816(acc[mi][nj], al, b0h, b1h);
                }
            }
        }
    }

    const int g = lane >> 2, tc = (lane & 3) * 2;
#pragma unroll
    for (int mi = 0; mi < 2; mi++)
#pragma unroll
        for (int nj = 0; nj < 8; nj++) {
            int row = m0 + wm0 + 16 * mi + g;
            int col = n0 + wn0 + 8 * nj + tc;
            *(float2*)&C[(size_t)row * 2048 + col] =
                make_float2(acc[mi][nj][0], acc[mi][nj][1]);
            *(float2*)&C[(size_t)(row + 8) * 2048 + col] =
                make_float2(acc[mi][nj][2], acc[mi][nj][3]);
        }
}

__global__ void __launch_bounds__(128) qkv_tensor_kernel() {
    const int mat = blockIdx.z;
    const __nv_bfloat16* bh = g_wthi + (size_t)mat * WELEM;
    const __nv_bfloat16* bl = g_wtlo + (size_t)mat * WELEM;
    float* C = (mat == 0) ? g_Q0 : (mat == 1) ? g_K0 : g_V0;
    tensor_gemm_tile(g_xhi, g_xlo, bh, bl, C, blockIdx.y * 64, blockIdx.x * 128);
}

__global__ void __launch_bounds__(128) out_tensor_kernel(float* __restrict__ out) {
    tensor_gemm_tile(g_onhi, g_onlo, g_wthi + (size_t)3 * WELEM, g_wtlo + (size_t)3 * WELEM,
                     out, blockIdx.y * 64, blockIdx.x * 128);
}

// ---------------- prep (conv+silu+l2norm) fused with beta/decay ----------------
__device__ __forceinline__ void conv_silu_l2(const float* __restrict__ src,
                                             const float* __restrict__ cw,
                                             float* __restrict__ dst,
                                             int t, int tid) {
    const int c0 = tid * 8;
    float wv[8][4];
#pragma unroll
    for (int e = 0; e < 8; e++) {
        float4 f = *(const float4*)&cw[(c0 + e) * 4];
        wv[e][0] = f.x; wv[e][1] = f.y; wv[e][2] = f.z; wv[e][3] = f.w;
    }
    float y[8];
#pragma unroll
    for (int e = 0; e < 8; e++) y[e] = 0.f;
#pragma unroll
    for (int i = 0; i < 4; i++) {
        int ts = t + i - 3;
        if (ts >= 0) {
            float4 xa = *(const float4*)&src[ts * HID + c0];
            float4 xb = *(const float4*)&src[ts * HID + c0 + 4];
            float xv[8] = {xa.x, xa.y, xa.z, xa.w, xb.x, xb.y, xb.z, xb.w};
#pragma unroll
            for (int e = 0; e < 8; e++) y[e] += xv[e] * wv[e][i];
        }
    }
#pragma unroll
    for (int e = 0; e < 8; e++) {
        float s = 1.f / (1.f + expf(-y[e]));
        y[e] *= s;
    }
    float ss = 0.f;
#pragma unroll
    for (int e = 0; e < 8; e++) ss += y[e] * y[e];
#pragma unroll
    for (int off = 1; off <= 8; off <<= 1) ss += __shfl_xor_sync(0xffffffffu, ss, off);
    float sc = rsqrtf(ss + 1e-6f);
    *(float4*)&dst[t * HID + c0] = make_float4(y[0] * sc, y[1] * sc, y[2] * sc, y[3] * sc);
    *(float4*)&dst[t * HID + c0 + 4] = make_float4(y[4] * sc, y[5] * sc, y[6] * sc, y[7] * sc);
}

__global__ void __launch_bounds__(256) prep_kernel(const float* __restrict__ cwq,
                                                   const float* __restrict__ cwk,
                                                   const float* __restrict__ x,
                                                   const float* __restrict__ Wa,
                                                   const float* __restrict__ ba,
                                                   const float* __restrict__ Wb,
                                                   const float* __restrict__ bb) {
    const int tid = threadIdx.x;
    if (blockIdx.x < 256) {
        const int t = blockIdx.x;
        conv_silu_l2(g_Q0, cwq, g_qn, t, tid);
        conv_silu_l2(g_K0, cwk, g_kn, t, tid);
        return;
    }
    __shared__ float Xs[32][17];
    __shared__ float Ws[32][32];
    const int m0 = (blockIdx.x - 256) * 16;
    const int n = tid & 31;
    const int mg = tid >> 5;
    const int lxm = tid >> 4;
    const int lxk = (tid & 15) * 2;

    float acc0 = 0.f, acc1 = 0.f;
    for (int k0 = 0; k0 < HID; k0 += 32) {
        float2 xv = *(const float2*)&x[(m0 + lxm) * HID + k0 + lxk];
        Xs[lxk][lxm] = xv.x;
        Xs[lxk + 1][lxm] = xv.y;
        const int i4 = tid * 4;
        const int wk = i4 >> 5, wn = i4 & 31;
#pragma unroll
        for (int j = 0; j < 4; j++) {
            int nn = wn + j;
            Ws[wk][nn] = (nn < 16) ? Wa[(k0 + wk) * NHEAD + nn]
                                   : Wb[(k0 + wk) * NHEAD + nn - 16];
        }
        __syncthreads();
#pragma unroll
        for (int kk = 0; kk < 32; kk++) {
            float w = Ws[kk][n];
            acc0 += Xs[kk][mg * 2] * w;
            acc1 += Xs[kk][mg * 2 + 1] * w;
        }
        __syncthreads();
    }
    const int row0 = m0 + mg * 2;
    if (n < 16) {
        float z0 = acc0 + ba[n], z1 = acc1 + ba[n];
        g_decay[row0 * NHEAD + n] = 1.f / (1.f + expf(-z0));
        g_decay[(row0 + 1) * NHEAD + n] = 1.f / (1.f + expf(-z1));
    } else {
        int c = n - 16;
        float z0 = acc0 + bb[c], z1 = acc1 + bb[c];
        g_beta[row0 * NHEAD + c] = 1.f / (1.f + expf(-z0));
        g_beta[(row0 + 1) * NHEAD + c] = 1.f / (1.f + expf(-z1));
    }
}

// ---------------- state scan: checkpoints every CHUNK steps ----------------
__global__ void scan_kernel() {
    const int h = blockIdx.y;
    const int i0 = blockIdx.x * 8;
    const int tid = threadIdx.x;
    __shared__ float ds[T_LEN], bs[T_LEN];
    __shared__ __align__(16) float ks[2][DHEAD], vs[2][DHEAD];
    ds[tid] = g_decay[tid * NHEAD + h];
    bs[tid] = g_beta[tid * NHEAD + h];
    if (tid < 32)
        *(float4*)&ks[0][tid * 4] = *(const float4*)&g_kn[h * DHEAD + tid * 4];
    else if (tid < 64) {
        int l = tid - 32;
        *(float4*)&vs[0][l * 4] = *(const float4*)&g_V0[h * DHEAD + l * 4];
    }
    const int row = i0 + (tid >> 5);
    const int j0 = (tid & 31) * 4;
    float kk0 = 0, kk1 = 0, kk2 = 0, kk3 = 0;
    float kv0 = 0, kv1 = 0, kv2 = 0, kv3 = 0;
    for (int t = 0; t < T_LEN; t++) {
        __syncthreads();
        const int cb = t & 1, nb = (t + 1) & 1;
        if (t + 1 < T_LEN) {
            if (tid < 32)
                *(float4*)&ks[nb][tid * 4] =
                    *(const float4*)&g_kn[(t + 1) * HID + h * DHEAD + tid * 4];
            else if (tid < 64) {
                int l = tid - 32;
                *(float4*)&vs[nb][l * 4] =
                    *(const float4*)&g_V0[(t + 1) * HID + h * DHEAD + l * 4];
            }
        }
        const float d = ds[t], b = bs[t];
        const float kr = ks[cb][row];
        float4 kj = *(const float4*)&ks[cb][j0];
        float4 vj = *(const float4*)&vs[cb][j0];
        const float bk = b * kr;
        kk0 = kk0 * d + bk * kj.x; kk1 = kk1 * d + bk * kj.y;
        kk2 = kk2 * d + bk * kj.z; kk3 = kk3 * d + bk * kj.w;
        kv0 = kv0 * d + bk * vj.x; kv1 = kv1 * d + bk * vj.y;
        kv2 = kv2 * d + bk * vj.z; kv3 = kv3 * d + bk * vj.w;
        if (((t + 1) & (CHUNK - 1)) == 0) {
            const int slot = t / CHUNK;
            size_t base = (((size_t)slot * NHEAD + h) << 14) + (size_t)row * DHEAD + j0;
            *(float4*)&g_hkk_ck[base] = make_float4(kk0, kk1, kk2, kk3);
            *(float4*)&g_hkv_ck[base] = make_float4(kv0, kv1, kv2, kv3);
        }
    }
}

// ---------------- block reduce (parity-buffered) ----------------
__device__ __forceinline__ float blockReduce128(float v, int pb) {
    __shared__ float red[2][4];
#pragma unroll
    for (int off = 16; off > 0; off >>= 1) v += __shfl_xor_sync(0xffffffffu, v, off);
    const int w = threadIdx.x >> 5;
    if ((threadIdx.x & 31) == 0) red[pb][w] = v;
    __syncthreads();
    return red[pb][0] + red[pb][1] + red[pb][2] + red[pb][3];
}

// ---------------- merged CG solve: one block per (head, chunk) ----------------
__global__ void __launch_bounds__(128, 4) solve_kernel(const float* __restrict__ onw,
                                                       const float* __restrict__ lp) {
    const int h = blockIdx.x;
    const int chunk = blockIdx.y;
    const int cs = chunk * CHUNK;
    const int slot = chunk - 1;
    const int r = threadIdx.x;

    __shared__ __align__(16) float ks[CHUNK][DHEAD];
    __shared__ __align__(16) float vs[CHUNK][DHEAD];
    __shared__ __align__(16) float ps[DHEAD];
    __shared__ float dsh[CHUNK], bsh[CHUNK], Pp[CHUNK], cf[CHUNK], gsh[CHUNK];

    {
        const int row = r >> 4;
        const int c0 = (r & 15) * 8;
        const float* kp = &g_kn[(cs + row) * HID + h * DHEAD + c0];
        const float* vp = &g_V0[(cs + row) * HID + h * DHEAD + c0];
        *(float4*)&ks[row][c0]     = *(const float4*)&kp[0];
        *(float4*)&ks[row][c0 + 4] = *(const float4*)&kp[4];
        *(float4*)&vs[row][c0]     = *(const float4*)&vp[0];
        *(float4*)&vs[row][c0 + 4] = *(const float4*)&vp[4];
        if (r < CHUNK) {
            dsh[r] = g_decay[(cs + r) * NHEAD + h];
            bsh[r] = g_beta[(cs + r) * NHEAD + h];
        }
    }
    __syncthreads();
    if (r == 0) {
        float run = 1.f;
#pragma unroll
        for (int s = 0; s < CHUNK; s++) {
            run *= dsh[s];
            Pp[s] = run;
            cf[s] = bsh[s] / run;
        }
    }

    float lam;
    {
        float v = lp[h * DHEAD + r];
        lam = ((v > 20.f) ? v : log1pf(expf(v))) + 0.25f;
    }

    ulonglong2 B2[32];
    if (slot >= 0) {
        const float* base = g_hkk_ck + (((size_t)slot * NHEAD + h) << 14) + (size_t)r * DHEAD;
#pragma unroll
        for (int i = 0; i < 32; i++) B2[i] = *(const ulonglong2*)&base[i * 4];
    } else {
#pragma unroll
        for (int i = 0; i < 32; i++) { B2[i].x = 0ull; B2[i].y = 0ull; }
    }
    const float* kvb = (slot >= 0)
        ? g_hkv_ck + (((size_t)slot * NHEAD + h) << 14) + r : (const float*)0;
    __syncthreads();

    int par = 0;
    for (int jt = 0; jt < CHUNK; jt++) {
        const int t = cs + jt;
        {
            u64 w = splat2(cf[jt] * ks[jt][r]);
            const u64* kkp = (const u64*)&ks[jt][0];
#pragma unroll
            for (int i = 0; i < 32; i++) {
                ffma2(B2[i].x, w, kkp[2 * i]);
                ffma2(B2[i].y, w, kkp[2 * i + 1]);
            }
        }
        const float Pt = Pp[jt];
        const float b = g_qn[t * HID + h * DHEAD + r];

        float xx = 0.f, rr = b, p = b;
        ps[r] = b;
        float rs = blockReduce128(b * b, par); par ^= 1;
        const float rs_stop = 1e-10f * rs;

        for (int it = 0; it < 30; it++) {
            u64 aA = 0ull, aB = 0ull, aC = 0ull, aD = 0ull;
#pragma unroll
            for (int i = 0; i < 32; i += 2) {
                ulonglong2 p0 = *(const ulonglong2*)&ps[i * 4];
                ulonglong2 p1 = *(const ulonglong2*)&ps[i * 4 + 4];
                ffma2(aA, B2[i].x, p0.x);     ffma2(aB, B2[i].y, p0.y);
                ffma2(aC, B2[i + 1].x, p1.x); ffma2(aD, B2[i + 1].y, p1.y);
            }
            float2 fa = unpk(aA), fb = unpk(aB), fc = unpk(aC), fd = unpk(aD);
            float bp = ((fa.x + fa.y) + (fb.x + fb.y)) + ((fc.x + fc.y) + (fd.x + fd.y));
            float ap = Pt * bp + lam * p;
            float pap = blockReduce128(p * ap, par); par ^= 1;
            float alpha = rs / (pap + 1e-12f);
            xx += alpha * p;
            rr -= alpha * ap;
            float rsn = blockReduce128(rr * rr, par); par ^= 1;
            if (rsn < rs_stop) break;
            float bet = rsn / (rs + 1e-12f);
            p = rr + bet * p;
            rs = rsn;
            ps[r] = p;
            __syncthreads();
        }

        ps[r] = xx;
        __syncthreads();
        {
            const int sIdx = r >> 4;
            const int part = r & 15;
            float pg = 0.f;
            const int e0 = part * 8;
#pragma unroll
            for (int e = 0; e < 8; e++) pg += ks[sIdx][e0 + e] * ps[e0 + e];
#pragma unroll
            for (int off = 1; off <= 8; off <<= 1) pg += __shfl_xor_sync(0xffffffffu, pg, off);
            if (part == 0)
                gsh[sIdx] = (sIdx <= jt) ? pg * cf[sIdx] * Pt : 0.f;
        }
        __syncthreads();

        float o = 0.f;
        if (slot >= 0) {
            float o0 = 0, o1 = 0, o2 = 0, o3 = 0;
#pragma unroll
            for (int k2 = 0; k2 < DHEAD; k2 += 4) {
                o0 += ps[k2]     * kvb[(size_t)k2 * DHEAD];
                o1 += ps[k2 + 1] * kvb[(size_t)(k2 + 1) * DHEAD];
                o2 += ps[k2 + 2] * kvb[(size_t)(k2 + 2) * DHEAD];
                o3 += ps[k2 + 3] * kvb[(size_t)(k2 + 3) * DHEAD];
            }
            o = Pt * ((o0 + o1) + (o2 + o3));
        }
#pragma unroll
        for (int s = 0; s < CHUNK; s++) o += gsh[s] * vs[s][r];

        float ms = blockReduce128(o * o, par) * (1.0f / 128.0f); par ^= 1;
        float sc = rsqrtf(ms + 1e-5f);
        g_on[t * HID + h * DHEAD + r] = o * sc * onw[r];
        __syncthreads();
    }
}

// ---------------- launch ----------------
extern "C" void kernel_launch(void* const* d_in, const int* in_sizes, int n_in,
                              void* d_out, int out_size) {
    const float* x    = (const float*)d_in[0];
    const float* Wq   = (const float*)d_in[1];
    const float* Wk   = (const float*)d_in[2];
    const float* Wv   = (const float*)d_in[3];
    const float* Wa   = (const float*)d_in[4];
    const float* ba   = (const float*)d_in[5];
    const float* Wb   = (const float*)d_in[6];
    const float* bb   = (const float*)d_in[7];
    const float* cwq  = (const float*)d_in[8];
    const float* cwk  = (const float*)d_in[9];
    const float* lp   = (const float*)d_in[10];
    const float* onw  = (const float*)d_in[11];
    const float* Wo   = (const float*)d_in[12];
    float* out = (float*)d_out;

    __nv_bfloat16 *xhi, *xlo, *onhi, *onlo;
    float* onp;
    cudaGetSymbolAddress((void**)&xhi, g_xhi);
    cudaGetSymbolAddress((void**)&xlo, g_xlo);
    cudaGetSymbolAddress((void**)&onhi, g_onhi);
    cudaGetSymbolAddress((void**)&onlo, g_onlo);
    cudaGetSymbolAddress((void**)&onp, g_on);

    convert_x_kernel<<<256, 256>>>(x, xhi, xlo);
    convert_wt_kernel<<<dim3(4096, 4), 256>>>(Wq, Wk, Wv, Wo);
    qkv_tensor_kernel<<<dim3(16, 4, 3), 128>>>();
    prep_kernel<<<272, 256>>>(cwq, cwk, x, Wa, ba, Wb, bb);
    scan_kernel<<<dim3(16, NHEAD), 256>>>();
    solve_kernel<<<dim3(NHEAD, NSLOT), 128>>>(onw, lp);
    convert_x_kernel<<<256, 256>>>(onp, onhi, onlo);
    out_tensor_kernel<<<dim3(16, 4), 128>>>(out);
}

// round 9
// speedup vs baseline: 2.0094x; 1.1086x over previous
#include <cuda_runtime.h>
#include <cuda_bf16.h>
#include <math.h>

#define T_LEN 256
#define HID   2048
#define NHEAD 16
#define DHEAD 128
#define KD    2048
#define CHUNK 8
#define NSLOT (T_LEN / CHUNK)
#define WELEM (KD * HID)

// ---------------- scratch ----------------
__device__ float g_Q0[T_LEN * KD];
__device__ float g_K0[T_LEN * KD];
__device__ float g_V0[T_LEN * KD];
__device__ float g_qn[T_LEN * KD];
__device__ float g_kn[T_LEN * KD];
__device__ float g_beta[T_LEN * NHEAD];
__device__ float g_decay[T_LEN * NHEAD];
__device__ float g_on[T_LEN * KD];
__device__ float g_hkk_ck[(size_t)NSLOT * NHEAD * DHEAD * DHEAD];
__device__ float g_hkv_ck[(size_t)NSLOT * NHEAD * DHEAD * DHEAD];
__device__ __nv_bfloat16 g_xhi[T_LEN * HID];
__device__ __nv_bfloat16 g_xlo[T_LEN * HID];
__device__ __nv_bfloat16 g_onhi[T_LEN * KD];
__device__ __nv_bfloat16 g_onlo[T_LEN * KD];
__device__ __nv_bfloat16 g_wthi[(size_t)4 * WELEM];
__device__ __nv_bfloat16 g_wtlo[(size_t)4 * WELEM];

// ---------------- f32x2 helpers ----------------
typedef unsigned long long u64;
__device__ __forceinline__ u64 splat2(float a) {
    u64 d; unsigned u = __float_as_uint(a);
    asm("mov.b64 %0, {%1, %1};" : "=l"(d) : "r"(u));
    return d;
}
__device__ __forceinline__ void ffma2(u64& d, u64 a, u64 b) {
    asm("fma.rn.f32x2 %0, %1, %2, %0;" : "+l"(d) : "l"(a), "l"(b));
}
__device__ __forceinline__ float2 unpk(u64 v) {
    unsigned lo, hi;
    asm("mov.b64 {%0, %1}, %2;" : "=r"(lo), "=r"(hi) : "l"(v));
    return make_float2(__uint_as_float(lo), __uint_as_float(hi));
}

// ---------------- tensor-core helpers ----------------
__device__ __forceinline__ unsigned smem_u32(const void* p) {
    unsigned a;
    asm("{ .reg .u64 t; cvta.to.shared.u64 t, %1; cvt.u32.u64 %0, t; }" : "=r"(a) : "l"(p));
    return a;
}
__device__ __forceinline__ void ldm4(unsigned (&r)[4], unsigned addr) {
    asm volatile("ldmatrix.sync.aligned.m8n8.x4.shared.b16 {%0,%1,%2,%3}, [%4];"
        : "=r"(r[0]), "=r"(r[1]), "=r"(r[2]), "=r"(r[3]) : "r"(addr));
}
__device__ __forceinline__ void mma16816(float (&c)[4], const unsigned (&a)[4],
                                         unsigned b0, unsigned b1) {
    asm volatile("mma.sync.aligned.m16n8k16.row.col.f32.bf16.bf16.f32 "
        "{%0,%1,%2,%3}, {%4,%5,%6,%7}, {%8,%9}, {%0,%1,%2,%3};"
        : "+f"(c[0]), "+f"(c[1]), "+f"(c[2]), "+f"(c[3])
        : "r"(a[0]), "r"(a[1]), "r"(a[2]), "r"(a[3]), "r"(b0), "r"(b1));
}
__device__ __forceinline__ void splitbf(float x, __nv_bfloat16& h, __nv_bfloat16& l) {
    h = __float2bfloat16_rn(x);
    l = __float2bfloat16_rn(x - __bfloat162float(h));
}
__device__ __forceinline__ unsigned pk2(__nv_bfloat16 a, __nv_bfloat16 b) {
    __nv_bfloat162 t = __halves2bfloat162(a, b);
    return *reinterpret_cast<unsigned*>(&t);
}

// ---------------- convert kernels ----------------
__global__ void __launch_bounds__(256) convert_x_kernel(const float* __restrict__ src,
                                                        __nv_bfloat16* __restrict__ hi,
                                                        __nv_bfloat16* __restrict__ lo) {
    const int i = (blockIdx.x * 256 + threadIdx.x) * 8;
    float4 a = *(const float4*)(src + i);
    float4 b = *(const float4*)(src + i + 4);
    float v[8] = {a.x, a.y, a.z, a.w, b.x, b.y, b.z, b.w};
    __nv_bfloat16 h[8], l[8];
#pragma unroll
    for (int e = 0; e < 8; e++) splitbf(v[e], h[e], l[e]);
    uint4 ph = make_uint4(pk2(h[0], h[1]), pk2(h[2], h[3]), pk2(h[4], h[5]), pk2(h[6], h[7]));
    uint4 pl = make_uint4(pk2(l[0], l[1]), pk2(l[2], l[3]), pk2(l[4], l[5]), pk2(l[6], l[7]));
    *(uint4*)(hi + i) = ph;
    *(uint4*)(lo + i) = pl;
}

__global__ void __launch_bounds__(256) convert_wt_kernel(const float* __restrict__ W0,
                                                         const float* __restrict__ W1,
                                                         const float* __restrict__ W2,
                                                         const float* __restrict__ W3) {
    __shared__ float T[32][33];
    const int mat = blockIdx.y;
    const float* W = (mat == 0) ? W0 : (mat == 1) ? W1 : (mat == 2) ? W2 : W3;
    __nv_bfloat16* oh = g_wthi + (size_t)mat * WELEM;
    __nv_bfloat16* ol = g_wtlo + (size_t)mat * WELEM;
    const int k0 = (blockIdx.x & 63) * 32;
    const int n0 = (blockIdx.x >> 6) * 32;
    const int tid = threadIdx.x;
    const int r = tid >> 5, c = tid & 31;
#pragma unroll
    for (int p = 0; p < 4; p++) {
        int k = k0 + p * 8 + r;
        T[c][p * 8 + r] = W[(size_t)k * 2048 + n0 + c];
    }
    __syncthreads();
    const int nl = tid >> 3, kc = (tid & 7) * 4;
    float v0 = T[nl][kc], v1 = T[nl][kc + 1], v2 = T[nl][kc + 2], v3 = T[nl][kc + 3];
    __nv_bfloat16 h0, h1, h2, h3, l0, l1, l2, l3;
    splitbf(v0, h0, l0); splitbf(v1, h1, l1);
    splitbf(v2, h2, l2); splitbf(v3, h3, l3);
    uint2 ph = make_uint2(pk2(h0, h1), pk2(h2, h3));
    uint2 pl = make_uint2(pk2(l0, l1), pk2(l2, l3));
    size_t off = (size_t)(n0 + nl) * 2048 + k0 + kc;
    *(uint2*)(oh + off) = ph;
    *(uint2*)(ol + off) = pl;
}

// ---------------- tensor GEMM tile ----------------
__device__ __forceinline__ void tensor_gemm_tile(const __nv_bfloat16* __restrict__ Ahi,
                                                 const __nv_bfloat16* __restrict__ Alo,
                                                 const __nv_bfloat16* __restrict__ Bth,
                                                 const __nv_bfloat16* __restrict__ Btl,
                                                 float* __restrict__ C,
                                                 int m0, int n0) {
    __shared__ __align__(16) __nv_bfloat16 sAh[64 * 40];
    __shared__ __align__(16) __nv_bfloat16 sAl[64 * 40];
    __shared__ __align__(16) __nv_bfloat16 sBh[128 * 40];
    __shared__ __align__(16) __nv_bfloat16 sBl[128 * 40];

    const int tid = threadIdx.x;
    const int lane = tid & 31;
    const int warp = tid >> 5;
    const int wm0 = (warp & 1) * 32;
    const int wn0 = (warp >> 1) * 64;

    float acc[2][8][4];
#pragma unroll
    for (int i = 0; i < 2; i++)
#pragma unroll
        for (int j = 0; j < 8; j++)
#pragma unroll
            for (int q = 0; q < 4; q++) acc[i][j][q] = 0.f;

    const unsigned baseAh = smem_u32(sAh), baseAl = smem_u32(sAl);
    const unsigned baseBh = smem_u32(sBh), baseBl = smem_u32(sBl);

    const int a_k = (lane >> 4) * 8;
    const int b_k = ((lane >> 3) & 1) * 8;
    const int a_r = lane & 15;
    const int b_r = ((lane >> 4) & 1) * 8 + (lane & 7);

    const int am = tid >> 1, aseg = (tid & 1) * 16;
    const size_t a_src = (size_t)(m0 + am) * 2048 + aseg;
    const size_t b_src = (size_t)(n0 + tid) * 2048;

    for (int k0 = 0; k0 < 2048; k0 += 32) {
        uint4 rah0 = *(const uint4*)(Ahi + a_src + k0);
        uint4 rah1 = *(const uint4*)(Ahi + a_src + k0 + 8);
        uint4 ral0 = *(const uint4*)(Alo + a_src + k0);
        uint4 ral1 = *(const uint4*)(Alo + a_src + k0 + 8);
        uint4 rbh0 = *(const uint4*)(Bth + b_src + k0);
        uint4 rbh1 = *(const uint4*)(Bth + b_src + k0 + 8);
        uint4 rbh2 = *(const uint4*)(Bth + b_src + k0 + 16);
        uint4 rbh3 = *(const uint4*)(Bth + b_src + k0 + 24);
        uint4 rbl0 = *(const uint4*)(Btl + b_src + k0);
        uint4 rbl1 = *(const uint4*)(Btl + b_src + k0 + 8);
        uint4 rbl2 = *(const uint4*)(Btl + b_src + k0 + 16);
        uint4 rbl3 = *(const uint4*)(Btl + b_src + k0 + 24);
        __syncthreads();
        *(uint4*)&sAh[am * 40 + aseg]     = rah0;
        *(uint4*)&sAh[am * 40 + aseg + 8] = rah1;
        *(uint4*)&sAl[am * 40 + aseg]     = ral0;
        *(uint4*)&sAl[am * 40 + aseg + 8] = ral1;
        *(uint4*)&sBh[tid * 40]      = rbh0;
        *(uint4*)&sBh[tid * 40 + 8]  = rbh1;
        *(uint4*)&sBh[tid * 40 + 16] = rbh2;
        *(uint4*)&sBh[tid * 40 + 24] = rbh3;
        *(uint4*)&sBl[tid * 40]      = rbl0;
        *(uint4*)&sBl[tid * 40 + 8]  = rbl1;
        *(uint4*)&sBl[tid * 40 + 16] = rbl2;
        *(uint4*)&sBl[tid * 40 + 24] = rbl3;
        __syncthreads();

#pragma unroll
        for (int ks = 0; ks < 2; ks++) {
            unsigned bh[4][4], bl[4][4];
#pragma unroll
            for (int p = 0; p < 4; p++) {
                unsigned addr = ((unsigned)((wn0 + p * 16 + b_r) * 40 + ks * 16 + b_k)) * 2;
                ldm4(bh[p], baseBh + addr);
                ldm4(bl[p], baseBl + addr);
            }
#pragma unroll
            for (int mi = 0; mi < 2; mi++) {
                unsigned ah[4], al[4];
                unsigned addr = ((unsigned)((wm0 + mi * 16 + a_r) * 40 + ks * 16 + a_k)) * 2;
                ldm4(ah, baseAh + addr);
                ldm4(al, baseAl + addr);
#pragma unroll
                for (int nj = 0; nj < 8; nj++) {
                    unsigned b0h = bh[nj >> 1][(nj & 1) * 2];
                    unsigned b1h = bh[nj >> 1][(nj & 1) * 2 + 1];
                    unsigned b0l = bl[nj >> 1][(nj & 1) * 2];
                    unsigned b1l = bl[nj >> 1][(nj & 1) * 2 + 1];
                    mma16816(acc[mi][nj], ah, b0h, b1h);
                    mma16816(acc[mi][nj], ah, b0l, b1l);
                    mma16816(acc[mi][nj], al, b0h, b1h);
                }
            }
        }
    }

    const int g = lane >> 2, tc = (lane & 3) * 2;
#pragma unroll
    for (int mi = 0; mi < 2; mi++)
#pragma unroll
        for (int nj = 0; nj < 8; nj++) {
            int row = m0 + wm0 + 16 * mi + g;
            int col = n0 + wn0 + 8 * nj + tc;
            *(float2*)&C[(size_t)row * 2048 + col] =
                make_float2(acc[mi][nj][0], acc[mi][nj][1]);
            *(float2*)&C[(size_t)(row + 8) * 2048 + col] =
                make_float2(acc[mi][nj][2], acc[mi][nj][3]);
        }
}

__global__ void __launch_bounds__(128) qkv_tensor_kernel() {
    const int mat = blockIdx.z;
    const __nv_bfloat16* bh = g_wthi + (size_t)mat * WELEM;
    const __nv_bfloat16* bl = g_wtlo + (size_t)mat * WELEM;
    float* C = (mat == 0) ? g_Q0 : (mat == 1) ? g_K0 : g_V0;
    tensor_gemm_tile(g_xhi, g_xlo, bh, bl, C, blockIdx.y * 64, blockIdx.x * 128);
}

__global__ void __launch_bounds__(128) out_tensor_kernel(float* __restrict__ out) {
    tensor_gemm_tile(g_onhi, g_onlo, g_wthi + (size_t)3 * WELEM, g_wtlo + (size_t)3 * WELEM,
                     out, blockIdx.y * 64, blockIdx.x * 128);
}

// ---------------- beta/decay: one block per t, 256 threads ----------------
__global__ void __launch_bounds__(256) bg_kernel(const float* __restrict__ x,
                                                 const float* __restrict__ Wa,
                                                 const float* __restrict__ ba,
                                                 const float* __restrict__ Wb,
                                                 const float* __restrict__ bb) {
    const int t = blockIdx.x;
    const int tid = threadIdx.x;
    __shared__ __align__(16) float xs[HID];
    __shared__ float red[8][32];
    // load x row
    {
        const int i = tid * 8;
        *(float4*)&xs[i]     = *(const float4*)&x[t * HID + i];
        *(float4*)&xs[i + 4] = *(const float4*)&x[t * HID + i + 4];
    }
    __syncthreads();
    const int col = tid & 31;           // 0..15 decay (Wa), 16..31 beta (Wb)
    const int kg = tid >> 5;            // 0..7
    const float* Wsel = (col < 16) ? Wa : Wb;
    const int c = col & 15;
    const int kb = kg * 256;
    float a0 = 0.f, a1 = 0.f, a2 = 0.f, a3 = 0.f;
#pragma unroll 16
    for (int k = 0; k < 256; k += 4) {
        a0 += xs[kb + k]     * Wsel[(kb + k) * NHEAD + c];
        a1 += xs[kb + k + 1] * Wsel[(kb + k + 1) * NHEAD + c];
        a2 += xs[kb + k + 2] * Wsel[(kb + k + 2) * NHEAD + c];
        a3 += xs[kb + k + 3] * Wsel[(kb + k + 3) * NHEAD + c];
    }
    red[kg][col] = (a0 + a1) + (a2 + a3);
    __syncthreads();
    if (kg == 0) {
        float v = 0.f;
#pragma unroll
        for (int g = 0; g < 8; g++) v += red[g][col];
        if (col < 16) {
            float z = v + ba[c];
            g_decay[t * NHEAD + c] = 1.f / (1.f + expf(-z));
        } else {
            float z = v + bb[c];
            g_beta[t * NHEAD + c] = 1.f / (1.f + expf(-z));
        }
    }
}

// ---------------- prep: conv(4)+silu+l2norm only ----------------
__device__ __forceinline__ void conv_silu_l2(const float* __restrict__ src,
                                             const float* __restrict__ cw,
                                             float* __restrict__ dst,
                                             int t, int tid) {
    const int c0 = tid * 8;
    float wv[8][4];
#pragma unroll
    for (int e = 0; e < 8; e++) {
        float4 f = *(const float4*)&cw[(c0 + e) * 4];
        wv[e][0] = f.x; wv[e][1] = f.y; wv[e][2] = f.z; wv[e][3] = f.w;
    }
    float y[8];
#pragma unroll
    for (int e = 0; e < 8; e++) y[e] = 0.f;
#pragma unroll
    for (int i = 0; i < 4; i++) {
        int ts = t + i - 3;
        if (ts >= 0) {
            float4 xa = *(const float4*)&src[ts * HID + c0];
            float4 xb = *(const float4*)&src[ts * HID + c0 + 4];
            float xv[8] = {xa.x, xa.y, xa.z, xa.w, xb.x, xb.y, xb.z, xb.w};
#pragma unroll
            for (int e = 0; e < 8; e++) y[e] += xv[e] * wv[e][i];
        }
    }
#pragma unroll
    for (int e = 0; e < 8; e++) {
        float s = 1.f / (1.f + expf(-y[e]));
        y[e] *= s;
    }
    float ss = 0.f;
#pragma unroll
    for (int e = 0; e < 8; e++) ss += y[e] * y[e];
#pragma unroll
    for (int off = 1; off <= 8; off <<= 1) ss += __shfl_xor_sync(0xffffffffu, ss, off);
    float sc = rsqrtf(ss + 1e-6f);
    *(float4*)&dst[t * HID + c0] = make_float4(y[0] * sc, y[1] * sc, y[2] * sc, y[3] * sc);
    *(float4*)&dst[t * HID + c0 + 4] = make_float4(y[4] * sc, y[5] * sc, y[6] * sc, y[7] * sc);
}

__global__ void __launch_bounds__(256) prep_kernel(const float* __restrict__ cwq,
                                                   const float* __restrict__ cwk) {
    const int t = blockIdx.x;
    const int tid = threadIdx.x;
    conv_silu_l2(g_Q0, cwq, g_qn, t, tid);
    conv_silu_l2(g_K0, cwk, g_kn, t, tid);
}

// ---------------- state scan ----------------
__global__ void scan_kernel() {
    const int h = blockIdx.y;
    const int i0 = blockIdx.x * 8;
    const int tid = threadIdx.x;
    __shared__ float ds[T_LEN], bs[T_LEN];
    __shared__ __align__(16) float ks[2][DHEAD], vs[2][DHEAD];
    ds[tid] = g_decay[tid * NHEAD + h];
    bs[tid] = g_beta[tid * NHEAD + h];
    if (tid < 32)
        *(float4*)&ks[0][tid * 4] = *(const float4*)&g_kn[h * DHEAD + tid * 4];
    else if (tid < 64) {
        int l = tid - 32;
        *(float4*)&vs[0][l * 4] = *(const float4*)&g_V0[h * DHEAD + l * 4];
    }
    const int row = i0 + (tid >> 5);
    const int j0 = (tid & 31) * 4;
    float kk0 = 0, kk1 = 0, kk2 = 0, kk3 = 0;
    float kv0 = 0, kv1 = 0, kv2 = 0, kv3 = 0;
    for (int t = 0; t < T_LEN; t++) {
        __syncthreads();
        const int cb = t & 1, nb = (t + 1) & 1;
        if (t + 1 < T_LEN) {
            if (tid < 32)
                *(float4*)&ks[nb][tid * 4] =
                    *(const float4*)&g_kn[(t + 1) * HID + h * DHEAD + tid * 4];
            else if (tid < 64) {
                int l = tid - 32;
                *(float4*)&vs[nb][l * 4] =
                    *(const float4*)&g_V0[(t + 1) * HID + h * DHEAD + l * 4];
            }
        }
        const float d = ds[t], b = bs[t];
        const float kr = ks[cb][row];
        float4 kj = *(const float4*)&ks[cb][j0];
        float4 vj = *(const float4*)&vs[cb][j0];
        const float bk = b * kr;
        kk0 = kk0 * d + bk * kj.x; kk1 = kk1 * d + bk * kj.y;
        kk2 = kk2 * d + bk * kj.z; kk3 = kk3 * d + bk * kj.w;
        kv0 = kv0 * d + bk * vj.x; kv1 = kv1 * d + bk * vj.y;
        kv2 = kv2 * d + bk * vj.z; kv3 = kv3 * d + bk * vj.w;
        if (((t + 1) & (CHUNK - 1)) == 0) {
            const int slot = t / CHUNK;
            size_t base = (((size_t)slot * NHEAD + h) << 14) + (size_t)row * DHEAD + j0;
            *(float4*)&g_hkk_ck[base] = make_float4(kk0, kk1, kk2, kk3);
            *(float4*)&g_hkv_ck[base] = make_float4(kv0, kv1, kv2, kv3);
        }
    }
}

// ---------------- block reduce ----------------
__device__ __forceinline__ float blockReduce128(float v, int pb) {
    __shared__ float red[2][4];
#pragma unroll
    for (int off = 16; off > 0; off >>= 1) v += __shfl_xor_sync(0xffffffffu, v, off);
    const int w = threadIdx.x >> 5;
    if ((threadIdx.x & 31) == 0) red[pb][w] = v;
    __syncthreads();
    return red[pb][0] + red[pb][1] + red[pb][2] + red[pb][3];
}

// ---------------- merged CG solve ----------------
__global__ void __launch_bounds__(128, 4) solve_kernel(const float* __restrict__ onw,
                                                       const float* __restrict__ lp) {
    const int h = blockIdx.x;
    const int chunk = blockIdx.y;
    const int cs = chunk * CHUNK;
    const int slot = chunk - 1;
    const int r = threadIdx.x;

    __shared__ __align__(16) float ks[CHUNK][DHEAD];
    __shared__ __align__(16) float vs[CHUNK][DHEAD];
    __shared__ __align__(16) float ps[DHEAD];
    __shared__ float dsh[CHUNK], bsh[CHUNK], Pp[CHUNK], cf[CHUNK], gsh[CHUNK];

    {
        const int row = r >> 4;
        const int c0 = (r & 15) * 8;
        const float* kp = &g_kn[(cs + row) * HID + h * DHEAD + c0];
        const float* vp = &g_V0[(cs + row) * HID + h * DHEAD + c0];
        *(float4*)&ks[row][c0]     = *(const float4*)&kp[0];
        *(float4*)&ks[row][c0 + 4] = *(const float4*)&kp[4];
        *(float4*)&vs[row][c0]     = *(const float4*)&vp[0];
        *(float4*)&vs[row][c0 + 4] = *(const float4*)&vp[4];
        if (r < CHUNK) {
            dsh[r] = g_decay[(cs + r) * NHEAD + h];
            bsh[r] = g_beta[(cs + r) * NHEAD + h];
        }
    }
    __syncthreads();
    if (r == 0) {
        float run = 1.f;
#pragma unroll
        for (int s = 0; s < CHUNK; s++) {
            run *= dsh[s];
            Pp[s] = run;
            cf[s] = bsh[s] / run;
        }
    }

    float lam;
    {
        float v = lp[h * DHEAD + r];
        lam = ((v > 20.f) ? v : log1pf(expf(v))) + 0.25f;
    }

    ulonglong2 B2[32];
    if (slot >= 0) {
        const float* base = g_hkk_ck + (((size_t)slot * NHEAD + h) << 14) + (size_t)r * DHEAD;
#pragma unroll
        for (int i = 0; i < 32; i++) B2[i] = *(const ulonglong2*)&base[i * 4];
    } else {
#pragma unroll
        for (int i = 0; i < 32; i++) { B2[i].x = 0ull; B2[i].y = 0ull; }
    }
    const float* kvb = (slot >= 0)
        ? g_hkv_ck + (((size_t)slot * NHEAD + h) << 14) + r : (const float*)0;
    __syncthreads();

    int par = 0;
    for (int jt = 0; jt < CHUNK; jt++) {
        const int t = cs + jt;
        {
            u64 w = splat2(cf[jt] * ks[jt][r]);
            const u64* kkp = (const u64*)&ks[jt][0];
#pragma unroll
            for (int i = 0; i < 32; i++) {
                ffma2(B2[i].x, w, kkp[2 * i]);
                ffma2(B2[i].y, w, kkp[2 * i + 1]);
            }
        }
        const float Pt = Pp[jt];
        const float b = g_qn[t * HID + h * DHEAD + r];

        float xx = 0.f, rr = b, p = b;
        ps[r] = b;
        float rs = blockReduce128(b * b, par); par ^= 1;
        const float rs_stop = 1e-8f * rs;

        for (int it = 0; it < 30; it++) {
            u64 aA = 0ull, aB = 0ull, aC = 0ull, aD = 0ull;
#pragma unroll
            for (int i = 0; i < 32; i += 2) {
                ulonglong2 p0 = *(const ulonglong2*)&ps[i * 4];
                ulonglong2 p1 = *(const ulonglong2*)&ps[i * 4 + 4];
                ffma2(aA, B2[i].x, p0.x);     ffma2(aB, B2[i].y, p0.y);
                ffma2(aC, B2[i + 1].x, p1.x); ffma2(aD, B2[i + 1].y, p1.y);
            }
            float2 fa = unpk(aA), fb = unpk(aB), fc = unpk(aC), fd = unpk(aD);
            float bp = ((fa.x + fa.y) + (fb.x + fb.y)) + ((fc.x + fc.y) + (fd.x + fd.y));
            float ap = Pt * bp + lam * p;
            float pap = blockReduce128(p * ap, par); par ^= 1;
            float alpha = rs / (pap + 1e-12f);
            xx += alpha * p;
            rr -= alpha * ap;
            float rsn = blockReduce128(rr * rr, par); par ^= 1;
            if (rsn < rs_stop) break;
            float bet = rsn / (rs + 1e-12f);
            p = rr + bet * p;
            rs = rsn;
            ps[r] = p;
            __syncthreads();
        }

        ps[r] = xx;
        __syncthreads();
        {
            const int sIdx = r >> 4;
            const int part = r & 15;
            float pg = 0.f;
            const int e0 = part * 8;
#pragma unroll
            for (int e = 0; e < 8; e++) pg += ks[sIdx][e0 + e] * ps[e0 + e];
#pragma unroll
            for (int off = 1; off <= 8; off <<= 1) pg += __shfl_xor_sync(0xffffffffu, pg, off);
            if (part == 0)
                gsh[sIdx] = (sIdx <= jt) ? pg * cf[sIdx] * Pt : 0.f;
        }
        __syncthreads();

        float o = 0.f;
        if (slot >= 0) {
            float o0 = 0, o1 = 0, o2 = 0, o3 = 0;
#pragma unroll
            for (int k2 = 0; k2 < DHEAD; k2 += 4) {
                o0 += ps[k2]     * kvb[(size_t)k2 * DHEAD];
                o1 += ps[k2 + 1] * kvb[(size_t)(k2 + 1) * DHEAD];
                o2 += ps[k2 + 2] * kvb[(size_t)(k2 + 2) * DHEAD];
                o3 += ps[k2 + 3] * kvb[(size_t)(k2 + 3) * DHEAD];
            }
            o = Pt * ((o0 + o1) + (o2 + o3));
        }
#pragma unroll
        for (int s = 0; s < CHUNK; s++) o += gsh[s] * vs[s][r];

        float ms = blockReduce128(o * o, par) * (1.0f / 128.0f); par ^= 1;
        float sc = rsqrtf(ms + 1e-5f);
        g_on[t * HID + h * DHEAD + r] = o * sc * onw[r];
        __syncthreads();
    }
}

// ---------------- launch ----------------
extern "C" void kernel_launch(void* const* d_in, const int* in_sizes, int n_in,
                              void* d_out, int out_size) {
    const float* x    = (const float*)d_in[0];
    const float* Wq   = (const float*)d_in[1];
    const float* Wk   = (const float*)d_in[2];
    const float* Wv   = (const float*)d_in[3];
    const float* Wa   = (const float*)d_in[4];
    const float* ba   = (const float*)d_in[5];
    const float* Wb   = (const float*)d_in[6];
    const float* bb   = (const float*)d_in[7];
    const float* cwq  = (const float*)d_in[8];
    const float* cwk  = (const float*)d_in[9];
    const float* lp   = (const float*)d_in[10];
    const float* onw  = (const float*)d_in[11];
    const float* Wo   = (const float*)d_in[12];
    float* out = (float*)d_out;

    __nv_bfloat16 *xhi, *xlo, *onhi, *onlo;
    float* onp;
    cudaGetSymbolAddress((void**)&xhi, g_xhi);
    cudaGetSymbolAddress((void**)&xlo, g_xlo);
    cudaGetSymbolAddress((void**)&onhi, g_onhi);
    cudaGetSymbolAddress((void**)&onlo, g_onlo);
    cudaGetSymbolAddress((void**)&onp, g_on);

    convert_x_kernel<<<256, 256>>>(x, xhi, xlo);
    convert_wt_kernel<<<dim3(4096, 4), 256>>>(Wq, Wk, Wv, Wo);
    qkv_tensor_kernel<<<dim3(16, 4, 3), 128>>>();
    bg_kernel<<<256, 256>>>(x, Wa, ba, Wb, bb);
    prep_kernel<<<256, 256>>>(cwq, cwk);
    scan_kernel<<<dim3(16, NHEAD), 256>>>();
    solve_kernel<<<dim3(NHEAD, NSLOT), 128>>>(onw, lp);
    convert_x_kernel<<<256, 256>>>(onp, onhi, onlo);
    out_tensor_kernel<<<dim3(16, 4), 128>>>(out);
}

// round 11
// speedup vs baseline: 2.0555x; 1.0229x over previous
#include <cuda_runtime.h>
#include <cuda_bf16.h>
#include <math.h>

#define T_LEN 256
#define HID   2048
#define NHEAD 16
#define DHEAD 128
#define KD    2048
#define CHUNK 8
#define NSLOT (T_LEN / CHUNK)
#define WELEM (KD * HID)

// ---------------- scratch ----------------
__device__ float g_Q0[T_LEN * KD];
__device__ float g_K0[T_LEN * KD];
__device__ float g_V0[T_LEN * KD];
__device__ float g_qn[T_LEN * KD];
__device__ float g_kn[T_LEN * KD];
__device__ float g_beta[T_LEN * NHEAD];
__device__ float g_decay[T_LEN * NHEAD];
__device__ float g_hkk_ck[(size_t)NSLOT * NHEAD * DHEAD * DHEAD];
__device__ float g_hkv_ck[(size_t)NSLOT * NHEAD * DHEAD * DHEAD];
__device__ __nv_bfloat16 g_xhi[T_LEN * HID];
__device__ __nv_bfloat16 g_xlo[T_LEN * HID];
__device__ __nv_bfloat16 g_onhi[T_LEN * KD];
__device__ __nv_bfloat16 g_onlo[T_LEN * KD];
__device__ __nv_bfloat16 g_wthi[(size_t)4 * WELEM];
__device__ __nv_bfloat16 g_wtlo[(size_t)4 * WELEM];

// ---------------- f32x2 helpers ----------------
typedef unsigned long long u64;
__device__ __forceinline__ u64 splat2(float a) {
    u64 d; unsigned u = __float_as_uint(a);
    asm("mov.b64 %0, {%1, %1};" : "=l"(d) : "r"(u));
    return d;
}
__device__ __forceinline__ void ffma2(u64& d, u64 a, u64 b) {
    asm("fma.rn.f32x2 %0, %1, %2, %0;" : "+l"(d) : "l"(a), "l"(b));
}
__device__ __forceinline__ float2 unpk(u64 v) {
    unsigned lo, hi;
    asm("mov.b64 {%0, %1}, %2;" : "=r"(lo), "=r"(hi) : "l"(v));
    return make_float2(__uint_as_float(lo), __uint_as_float(hi));
}

// ---------------- tensor-core helpers ----------------
__device__ __forceinline__ unsigned smem_u32(const void* p) {
    unsigned a;
    asm("{ .reg .u64 t; cvta.to.shared.u64 t, %1; cvt.u32.u64 %0, t; }" : "=r"(a) : "l"(p));
    return a;
}
__device__ __forceinline__ void ldm4(unsigned (&r)[4], unsigned addr) {
    asm volatile("ldmatrix.sync.aligned.m8n8.x4.shared.b16 {%0,%1,%2,%3}, [%4];"
        : "=r"(r[0]), "=r"(r[1]), "=r"(r[2]), "=r"(r[3]) : "r"(addr));
}
__device__ __forceinline__ void mma16816(float (&c)[4], const unsigned (&a)[4],
                                         unsigned b0, unsigned b1) {
    asm volatile("mma.sync.aligned.m16n8k16.row.col.f32.bf16.bf16.f32 "
        "{%0,%1,%2,%3}, {%4,%5,%6,%7}, {%8,%9}, {%0,%1,%2,%3};"
        : "+f"(c[0]), "+f"(c[1]), "+f"(c[2]), "+f"(c[3])
        : "r"(a[0]), "r"(a[1]), "r"(a[2]), "r"(a[3]), "r"(b0), "r"(b1));
}
__device__ __forceinline__ void splitbf(float x, __nv_bfloat16& h, __nv_bfloat16& l) {
    h = __float2bfloat16_rn(x);
    l = __float2bfloat16_rn(x - __bfloat162float(h));
}
__device__ __forceinline__ unsigned pk2(__nv_bfloat16 a, __nv_bfloat16 b) {
    __nv_bfloat162 t = __halves2bfloat162(a, b);
    return *reinterpret_cast<unsigned*>(&t);
}

// ---------------- head kernel: bg + convert_x + convert_wt fused ----------------
__global__ void __launch_bounds__(256) head_kernel(const float* __restrict__ x,
                                                   const float* __restrict__ W0,
                                                   const float* __restrict__ W1,
                                                   const float* __restrict__ W2,
                                                   const float* __restrict__ W3,
                                                   const float* __restrict__ Wa,
                                                   const float* __restrict__ ba,
                                                   const float* __restrict__ Wb,
                                                   const float* __restrict__ bb) {
    const int b = blockIdx.x;
    const int tid = threadIdx.x;
    if (b < 256) {
        // ---- bg: beta/decay for t = b ----
        const int t = b;
        __shared__ __align__(16) float xs[HID];
        __shared__ float red[8][32];
        {
            const int i = tid * 8;
            *(float4*)&xs[i]     = *(const float4*)&x[t * HID + i];
            *(float4*)&xs[i + 4] = *(const float4*)&x[t * HID + i + 4];
        }
        __syncthreads();
        const int col = tid & 31;
        const int kg = tid >> 5;
        const float* Wsel = (col < 16) ? Wa : Wb;
        const int c = col & 15;
        const int kb = kg * 256;
        float a0 = 0.f, a1 = 0.f, a2 = 0.f, a3 = 0.f;
#pragma unroll 16
        for (int k = 0; k < 256; k += 4) {
            a0 += xs[kb + k]     * Wsel[(kb + k) * NHEAD + c];
            a1 += xs[kb + k + 1] * Wsel[(kb + k + 1) * NHEAD + c];
            a2 += xs[kb + k + 2] * Wsel[(kb + k + 2) * NHEAD + c];
            a3 += xs[kb + k + 3] * Wsel[(kb + k + 3) * NHEAD + c];
        }
        red[kg][col] = (a0 + a1) + (a2 + a3);
        __syncthreads();
        if (kg == 0) {
            float v = 0.f;
#pragma unroll
            for (int g = 0; g < 8; g++) v += red[g][col];
            if (col < 16) {
                g_decay[t * NHEAD + c] = 1.f / (1.f + expf(-(v + ba[c])));
            } else {
                g_beta[t * NHEAD + c] = 1.f / (1.f + expf(-(v + bb[c])));
            }
        }
        return;
    }
    if (b < 512) {
        // ---- convert_x: hi/lo split of x ----
        const int i = ((b - 256) * 256 + tid) * 8;
        float4 a = *(const float4*)(x + i);
        float4 bb4 = *(const float4*)(x + i + 4);
        float v[8] = {a.x, a.y, a.z, a.w, bb4.x, bb4.y, bb4.z, bb4.w};
        __nv_bfloat16 h[8], l[8];
#pragma unroll
        for (int e = 0; e < 8; e++) splitbf(v[e], h[e], l[e]);
        uint4 ph = make_uint4(pk2(h[0], h[1]), pk2(h[2], h[3]), pk2(h[4], h[5]), pk2(h[6], h[7]));
        uint4 pl = make_uint4(pk2(l[0], l[1]), pk2(l[2], l[3]), pk2(l[4], l[5]), pk2(l[6], l[7]));
        *(uint4*)(g_xhi + i) = ph;
        *(uint4*)(g_xlo + i) = pl;
        return;
    }
    // ---- convert_wt: W [k][n] fp32 -> Wt [n][k] bf16 hi/lo ----
    __shared__ float T[32][33];
    const int bp = b - 512;
    const int mat = bp >> 12;
    const int bx = bp & 4095;
    const float* W = (mat == 0) ? W0 : (mat == 1) ? W1 : (mat == 2) ? W2 : W3;
    __nv_bfloat16* oh = g_wthi + (size_t)mat * WELEM;
    __nv_bfloat16* ol = g_wtlo + (size_t)mat * WELEM;
    const int k0 = (bx & 63) * 32;
    const int n0 = (bx >> 6) * 32;
    const int r = tid >> 5, c = tid & 31;
#pragma unroll
    for (int p = 0; p < 4; p++) {
        int k = k0 + p * 8 + r;
        T[c][p * 8 + r] = W[(size_t)k * 2048 + n0 + c];
    }
    __syncthreads();
    const int nl = tid >> 3, kc = (tid & 7) * 4;
    float v0 = T[nl][kc], v1 = T[nl][kc + 1], v2 = T[nl][kc + 2], v3 = T[nl][kc + 3];
    __nv_bfloat16 h0, h1, h2, h3, l0, l1, l2, l3;
    splitbf(v0, h0, l0); splitbf(v1, h1, l1);
    splitbf(v2, h2, l2); splitbf(v3, h3, l3);
    uint2 ph = make_uint2(pk2(h0, h1), pk2(h2, h3));
    uint2 pl = make_uint2(pk2(l0, l1), pk2(l2, l3));
    size_t off = (size_t)(n0 + nl) * 2048 + k0 + kc;
    *(uint2*)(oh + off) = ph;
    *(uint2*)(ol + off) = pl;
}

// ---------------- tensor GEMM tile ----------------
__device__ __forceinline__ void tensor_gemm_tile(const __nv_bfloat16* __restrict__ Ahi,
                                                 const __nv_bfloat16* __restrict__ Alo,
                                                 const __nv_bfloat16* __restrict__ Bth,
                                                 const __nv_bfloat16* __restrict__ Btl,
                                                 float* __restrict__ C,
                                                 int m0, int n0) {
    __shared__ __align__(16) __nv_bfloat16 sAh[64 * 40];
    __shared__ __align__(16) __nv_bfloat16 sAl[64 * 40];
    __shared__ __align__(16) __nv_bfloat16 sBh[128 * 40];
    __shared__ __align__(16) __nv_bfloat16 sBl[128 * 40];

    const int tid = threadIdx.x;
    const int lane = tid & 31;
    const int warp = tid >> 5;
    const int wm0 = (warp & 1) * 32;
    const int wn0 = (warp >> 1) * 64;

    float acc[2][8][4];
#pragma unroll
    for (int i = 0; i < 2; i++)
#pragma unroll
        for (int j = 0; j < 8; j++)
#pragma unroll
            for (int q = 0; q < 4; q++) acc[i][j][q] = 0.f;

    const unsigned baseAh = smem_u32(sAh), baseAl = smem_u32(sAl);
    const unsigned baseBh = smem_u32(sBh), baseBl = smem_u32(sBl);

    const int a_k = (lane >> 4) * 8;
    const int b_k = ((lane >> 3) & 1) * 8;
    const int a_r = lane & 15;
    const int b_r = ((lane >> 4) & 1) * 8 + (lane & 7);

    const int am = tid >> 1, aseg = (tid & 1) * 16;
    const size_t a_src = (size_t)(m0 + am) * 2048 + aseg;
    const size_t b_src = (size_t)(n0 + tid) * 2048;

    for (int k0 = 0; k0 < 2048; k0 += 32) {
        uint4 rah0 = *(const uint4*)(Ahi + a_src + k0);
        uint4 rah1 = *(const uint4*)(Ahi + a_src + k0 + 8);
        uint4 ral0 = *(const uint4*)(Alo + a_src + k0);
        uint4 ral1 = *(const uint4*)(Alo + a_src + k0 + 8);
        uint4 rbh0 = *(const uint4*)(Bth + b_src + k0);
        uint4 rbh1 = *(const uint4*)(Bth + b_src + k0 + 8);
        uint4 rbh2 = *(const uint4*)(Bth + b_src + k0 + 16);
        uint4 rbh3 = *(const uint4*)(Bth + b_src + k0 + 24);
        uint4 rbl0 = *(const uint4*)(Btl + b_src + k0);
        uint4 rbl1 = *(const uint4*)(Btl + b_src + k0 + 8);
        uint4 rbl2 = *(const uint4*)(Btl + b_src + k0 + 16);
        uint4 rbl3 = *(const uint4*)(Btl + b_src + k0 + 24);
        __syncthreads();
        *(uint4*)&sAh[am * 40 + aseg]     = rah0;
        *(uint4*)&sAh[am * 40 + aseg + 8] = rah1;
        *(uint4*)&sAl[am * 40 + aseg]     = ral0;
        *(uint4*)&sAl[am * 40 + aseg + 8] = ral1;
        *(uint4*)&sBh[tid * 40]      = rbh0;
        *(uint4*)&sBh[tid * 40 + 8]  = rbh1;
        *(uint4*)&sBh[tid * 40 + 16] = rbh2;
        *(uint4*)&sBh[tid * 40 + 24] = rbh3;
        *(uint4*)&sBl[tid * 40]      = rbl0;
        *(uint4*)&sBl[tid * 40 + 8]  = rbl1;
        *(uint4*)&sBl[tid * 40 + 16] = rbl2;
        *(uint4*)&sBl[tid * 40 + 24] = rbl3;
        __syncthreads();

#pragma unroll
        for (int ks = 0; ks < 2; ks++) {
            unsigned bh[4][4], bl[4][4];
#pragma unroll
            for (int p = 0; p < 4; p++) {
                unsigned addr = ((unsigned)((wn0 + p * 16 + b_r) * 40 + ks * 16 + b_k)) * 2;
                ldm4(bh[p], baseBh + addr);
                ldm4(bl[p], baseBl + addr);
            }
#pragma unroll
            for (int mi = 0; mi < 2; mi++) {
                unsigned ah[4], al[4];
                unsigned addr = ((unsigned)((wm0 + mi * 16 + a_r) * 40 + ks * 16 + a_k)) * 2;
                ldm4(ah, baseAh + addr);
                ldm4(al, baseAl + addr);
#pragma unroll
                for (int nj = 0; nj < 8; nj++) {
                    unsigned b0h = bh[nj >> 1][(nj & 1) * 2];
                    unsigned b1h = bh[nj >> 1][(nj & 1) * 2 + 1];
                    unsigned b0l = bl[nj >> 1][(nj & 1) * 2];
                    unsigned b1l = bl[nj >> 1][(nj & 1) * 2 + 1];
                    mma16816(acc[mi][nj], ah, b0h, b1h);
                    mma16816(acc[mi][nj], ah, b0l, b1l);
                    mma16816(acc[mi][nj], al, b0h, b1h);
                }
            }
        }
    }

    const int g = lane >> 2, tc = (lane & 3) * 2;
#pragma unroll
    for (int mi = 0; mi < 2; mi++)
#pragma unroll
        for (int nj = 0; nj < 8; nj++) {
            int row = m0 + wm0 + 16 * mi + g;
            int col = n0 + wn0 + 8 * nj + tc;
            *(float2*)&C[(size_t)row * 2048 + col] =
                make_float2(acc[mi][nj][0], acc[mi][nj][1]);
            *(float2*)&C[(size_t)(row + 8) * 2048 + col] =
                make_float2(acc[mi][nj][2], acc[mi][nj][3]);
        }
}

__global__ void __launch_bounds__(128) qkv_tensor_kernel() {
    const int mat = blockIdx.z;
    const __nv_bfloat16* bh = g_wthi + (size_t)mat * WELEM;
    const __nv_bfloat16* bl = g_wtlo + (size_t)mat * WELEM;
    float* C = (mat == 0) ? g_Q0 : (mat == 1) ? g_K0 : g_V0;
    tensor_gemm_tile(g_xhi, g_xlo, bh, bl, C, blockIdx.y * 64, blockIdx.x * 128);
}

__global__ void __launch_bounds__(128) out_tensor_kernel(float* __restrict__ out) {
    tensor_gemm_tile(g_onhi, g_onlo, g_wthi + (size_t)3 * WELEM, g_wtlo + (size_t)3 * WELEM,
                     out, blockIdx.y * 64, blockIdx.x * 128);
}

// ---------------- prep: conv(4)+silu+l2norm ----------------
__device__ __forceinline__ void conv_silu_l2(const float* __restrict__ src,
                                             const float* __restrict__ cw,
                                             float* __restrict__ dst,
                                             int t, int tid) {
    const int c0 = tid * 8;
    float wv[8][4];
#pragma unroll
    for (int e = 0; e < 8; e++) {
        float4 f = *(const float4*)&cw[(c0 + e) * 4];
        wv[e][0] = f.x; wv[e][1] = f.y; wv[e][2] = f.z; wv[e][3] = f.w;
    }
    float y[8];
#pragma unroll
    for (int e = 0; e < 8; e++) y[e] = 0.f;
#pragma unroll
    for (int i = 0; i < 4; i++) {
        int ts = t + i - 3;
        if (ts >= 0) {
            float4 xa = *(const float4*)&src[ts * HID + c0];
            float4 xb = *(const float4*)&src[ts * HID + c0 + 4];
            float xv[8] = {xa.x, xa.y, xa.z, xa.w, xb.x, xb.y, xb.z, xb.w};
#pragma unroll
            for (int e = 0; e < 8; e++) y[e] += xv[e] * wv[e][i];
        }
    }
#pragma unroll
    for (int e = 0; e < 8; e++) {
        float s = 1.f / (1.f + expf(-y[e]));
        y[e] *= s;
    }
    float ss = 0.f;
#pragma unroll
    for (int e = 0; e < 8; e++) ss += y[e] * y[e];
#pragma unroll
    for (int off = 1; off <= 8; off <<= 1) ss += __shfl_xor_sync(0xffffffffu, ss, off);
    float sc = rsqrtf(ss + 1e-6f);
    *(float4*)&dst[t * HID + c0] = make_float4(y[0] * sc, y[1] * sc, y[2] * sc, y[3] * sc);
    *(float4*)&dst[t * HID + c0 + 4] = make_float4(y[4] * sc, y[5] * sc, y[6] * sc, y[7] * sc);
}

__global__ void __launch_bounds__(256) prep_kernel(const float* __restrict__ cwq,
                                                   const float* __restrict__ cwk) {
    const int t = blockIdx.x;
    const int tid = threadIdx.x;
    conv_silu_l2(g_Q0, cwq, g_qn, t, tid);
    conv_silu_l2(g_K0, cwk, g_kn, t, tid);
}

// ---------------- state scan ----------------
__global__ void scan_kernel() {
    const int h = blockIdx.y;
    const int i0 = blockIdx.x * 8;
    const int tid = threadIdx.x;
    __shared__ float ds[T_LEN], bs[T_LEN];
    __shared__ __align__(16) float ks[2][DHEAD], vs[2][DHEAD];
    ds[tid] = g_decay[tid * NHEAD + h];
    bs[tid] = g_beta[tid * NHEAD + h];
    if (tid < 32)
        *(float4*)&ks[0][tid * 4] = *(const float4*)&g_kn[h * DHEAD + tid * 4];
    else if (tid < 64) {
        int l = tid - 32;
        *(float4*)&vs[0][l * 4] = *(const float4*)&g_V0[h * DHEAD + l * 4];
    }
    const int row = i0 + (tid >> 5);
    const int j0 = (tid & 31) * 4;
    float kk0 = 0, kk1 = 0, kk2 = 0, kk3 = 0;
    float kv0 = 0, kv1 = 0, kv2 = 0, kv3 = 0;
    for (int t = 0; t < T_LEN; t++) {
        __syncthreads();
        const int cb = t & 1, nb = (t + 1) & 1;
        if (t + 1 < T_LEN) {
            if (tid < 32)
                *(float4*)&ks[nb][tid * 4] =
                    *(const float4*)&g_kn[(t + 1) * HID + h * DHEAD + tid * 4];
            else if (tid < 64) {
                int l = tid - 32;
                *(float4*)&vs[nb][l * 4] =
                    *(const float4*)&g_V0[(t + 1) * HID + h * DHEAD + l * 4];
            }
        }
        const float d = ds[t], b = bs[t];
        const float kr = ks[cb][row];
        float4 kj = *(const float4*)&ks[cb][j0];
        float4 vj = *(const float4*)&vs[cb][j0];
        const float bk = b * kr;
        kk0 = kk0 * d + bk * kj.x; kk1 = kk1 * d + bk * kj.y;
        kk2 = kk2 * d + bk * kj.z; kk3 = kk3 * d + bk * kj.w;
        kv0 = kv0 * d + bk * vj.x; kv1 = kv1 * d + bk * vj.y;
        kv2 = kv2 * d + bk * vj.z; kv3 = kv3 * d + bk * vj.w;
        if (((t + 1) & (CHUNK - 1)) == 0) {
            const int slot = t / CHUNK;
            size_t base = (((size_t)slot * NHEAD + h) << 14) + (size_t)row * DHEAD + j0;
            *(float4*)&g_hkk_ck[base] = make_float4(kk0, kk1, kk2, kk3);
            *(float4*)&g_hkv_ck[base] = make_float4(kv0, kv1, kv2, kv3);
        }
    }
}

// ---------------- block reduce (shfl tree + parity buffer) ----------------
__device__ __forceinline__ float blockReduce128(float v, int pb) {
    __shared__ float red[2][4];
#pragma unroll
    for (int off = 16; off > 0; off >>= 1) v += __shfl_xor_sync(0xffffffffu, v, off);
    const int wp = threadIdx.x >> 5;
    if ((threadIdx.x & 31) == 0) red[pb][wp] = v;
    __syncthreads();
    return red[pb][0] + red[pb][1] + red[pb][2] + red[pb][3];
}

// ---------------- merged CG solve (bf16 split fused into epilogue) ----------------
__global__ void __launch_bounds__(128, 4) solve_kernel(const float* __restrict__ onw,
                                                       const float* __restrict__ lp) {
    const int h = blockIdx.x;
    const int chunk = blockIdx.y;
    const int cs = chunk * CHUNK;
    const int slot = chunk - 1;
    const int r = threadIdx.x;

    __shared__ __align__(16) float ks[CHUNK][DHEAD];
    __shared__ __align__(16) float vs[CHUNK][DHEAD];
    __shared__ __align__(16) float ps[DHEAD];
    __shared__ float dsh[CHUNK], bsh[CHUNK], Pp[CHUNK], cf[CHUNK], gsh[CHUNK];

    {
        const int row = r >> 4;
        const int c0 = (r & 15) * 8;
        const float* kp = &g_kn[(cs + row) * HID + h * DHEAD + c0];
        const float* vp = &g_V0[(cs + row) * HID + h * DHEAD + c0];
        *(float4*)&ks[row][c0]     = *(const float4*)&kp[0];
        *(float4*)&ks[row][c0 + 4] = *(const float4*)&kp[4];
        *(float4*)&vs[row][c0]     = *(const float4*)&vp[0];
        *(float4*)&vs[row][c0 + 4] = *(const float4*)&vp[4];
        if (r < CHUNK) {
            dsh[r] = g_decay[(cs + r) * NHEAD + h];
            bsh[r] = g_beta[(cs + r) * NHEAD + h];
        }
    }
    __syncthreads();
    if (r == 0) {
        float run = 1.f;
#pragma unroll
        for (int s = 0; s < CHUNK; s++) {
            run *= dsh[s];
            Pp[s] = run;
            cf[s] = bsh[s] / run;
        }
    }

    float lam;
    {
        float v = lp[h * DHEAD + r];
        lam = ((v > 20.f) ? v : log1pf(expf(v))) + 0.25f;
    }

    ulonglong2 B2[32];
    if (slot >= 0) {
        const float* base = g_hkk_ck + (((size_t)slot * NHEAD + h) << 14) + (size_t)r * DHEAD;
#pragma unroll
        for (int i = 0; i < 32; i++) B2[i] = *(const ulonglong2*)&base[i * 4];
    } else {
#pragma unroll
        for (int i = 0; i < 32; i++) { B2[i].x = 0ull; B2[i].y = 0ull; }
    }
    const float* kvb = (slot >= 0)
        ? g_hkv_ck + (((size_t)slot * NHEAD + h) << 14) + r : (const float*)0;
    __syncthreads();

    int par = 0;
    for (int jt = 0; jt < CHUNK; jt++) {
        const int t = cs + jt;
        {
            u64 w = splat2(cf[jt] * ks[jt][r]);
            const u64* kkp = (const u64*)&ks[jt][0];
#pragma unroll
            for (int i = 0; i < 32; i++) {
                ffma2(B2[i].x, w, kkp[2 * i]);
                ffma2(B2[i].y, w, kkp[2 * i + 1]);
            }
        }
        const float Pt = Pp[jt];
        const float b = g_qn[t * HID + h * DHEAD + r];

        float xx = 0.f, rr = b, p = b;
        ps[r] = b;
        float rs = blockReduce128(b * b, par); par ^= 1;
        const float rs_stop = 1e-8f * rs;

        for (int it = 0; it < 30; it++) {
            u64 aA = 0ull, aB = 0ull, aC = 0ull, aD = 0ull;
#pragma unroll
            for (int i = 0; i < 32; i += 2) {
                ulonglong2 p0 = *(const ulonglong2*)&ps[i * 4];
                ulonglong2 p1 = *(const ulonglong2*)&ps[i * 4 + 4];
                ffma2(aA, B2[i].x, p0.x);     ffma2(aB, B2[i].y, p0.y);
                ffma2(aC, B2[i + 1].x, p1.x); ffma2(aD, B2[i + 1].y, p1.y);
            }
            float2 fa = unpk(aA), fb = unpk(aB), fc = unpk(aC), fd = unpk(aD);
            float bp = ((fa.x + fa.y) + (fb.x + fb.y)) + ((fc.x + fc.y) + (fd.x + fd.y));
            float ap = Pt * bp + lam * p;
            float pap = blockReduce128(p * ap, par); par ^= 1;
            float alpha = rs / (pap + 1e-12f);
            xx += alpha * p;
            rr -= alpha * ap;
            float rsn = blockReduce128(rr * rr, par); par ^= 1;
            if (rsn < rs_stop) break;
            float bet = rsn / (rs + 1e-12f);
            p = rr + bet * p;
            rs = rsn;
            ps[r] = p;
            __syncthreads();
        }

        ps[r] = xx;
        __syncthreads();
        {
            const int sIdx = r >> 4;
            const int part = r & 15;
            float pg = 0.f;
            const int e0 = part * 8;
#pragma unroll
            for (int e = 0; e < 8; e++) pg += ks[sIdx][e0 + e] * ps[e0 + e];
#pragma unroll
            for (int off = 1; off <= 8; off <<= 1) pg += __shfl_xor_sync(0xffffffffu, pg, off);
            if (part == 0)
                gsh[sIdx] = (sIdx <= jt) ? pg * cf[sIdx] * Pt : 0.f;
        }
        __syncthreads();

        float o = 0.f;
        if (slot >= 0) {
            float o0 = 0, o1 = 0, o2 = 0, o3 = 0;
#pragma unroll
            for (int k2 = 0; k2 < DHEAD; k2 += 4) {
                o0 += ps[k2]     * kvb[(size_t)k2 * DHEAD];
                o1 += ps[k2 + 1] * kvb[(size_t)(k2 + 1) * DHEAD];
                o2 += ps[k2 + 2] * kvb[(size_t)(k2 + 2) * DHEAD];
                o3 += ps[k2 + 3] * kvb[(size_t)(k2 + 3) * DHEAD];
            }
            o = Pt * ((o0 + o1) + (o2 + o3));
        }
#pragma unroll
        for (int s = 0; s < CHUNK; s++) o += gsh[s] * vs[s][r];

        float ms = blockReduce128(o * o, par) * (1.0f / 128.0f); par ^= 1;
        float sc = rsqrtf(ms + 1e-5f);
        float val = o * sc * onw[r];
        __nv_bfloat16 hb, lb;
        splitbf(val, hb, lb);
        g_onhi[t * HID + h * DHEAD + r] = hb;
        g_onlo[t * HID + h * DHEAD + r] = lb;
        __syncthreads();
    }
}

// ---------------- launch ----------------
extern "C" void kernel_launch(void* const* d_in, const int* in_sizes, int n_in,
                              void* d_out, int out_size) {
    const float* x    = (const float*)d_in[0];
    const float* Wq   = (const float*)d_in[1];
    const float* Wk   = (const float*)d_in[2];
    const float* Wv   = (const float*)d_in[3];
    const float* Wa   = (const float*)d_in[4];
    const float* ba   = (const float*)d_in[5];
    const float* Wb   = (const float*)d_in[6];
    const float* bb   = (const float*)d_in[7];
    const float* cwq  = (const float*)d_in[8];
    const float* cwk  = (const float*)d_in[9];
    const float* lp   = (const float*)d_in[10];
    const float* onw  = (const float*)d_in[11];
    const float* Wo   = (const float*)d_in[12];
    float* out = (float*)d_out;

    head_kernel<<<16896, 256>>>(x, Wq, Wk, Wv, Wo, Wa, ba, Wb, bb);
    qkv_tensor_kernel<<<dim3(16, 4, 3), 128>>>();
    prep_kernel<<<256, 256>>>(cwq, cwk);
    scan_kernel<<<dim3(16, NHEAD), 256>>>();
    solve_kernel<<<dim3(NHEAD, NSLOT), 128>>>(onw, lp);
    out_tensor_kernel<<<dim3(16, 4), 128>>>(out);
}

// round 12
// speedup vs baseline: 2.3468x; 1.1417x over previous
#include <cuda_runtime.h>
#include <cuda_bf16.h>
#include <math.h>

#define T_LEN 256
#define HID   2048
#define NHEAD 16
#define DHEAD 128
#define KD    2048
#define CHUNK 8
#define NSLOT (T_LEN / CHUNK)
#define SCHUNK 16
#define WELEM (KD * HID)

// ---------------- scratch ----------------
__device__ float g_Q0[T_LEN * KD];
__device__ float g_K0[T_LEN * KD];
__device__ float g_V0[T_LEN * KD];
__device__ float g_qn[T_LEN * KD];
__device__ float g_kn[T_LEN * KD];
__device__ float g_beta[T_LEN * NHEAD];
__device__ float g_decay[T_LEN * NHEAD];
__device__ float g_hkk_ck[(size_t)NSLOT * NHEAD * DHEAD * DHEAD];
__device__ float g_hkv_ck[(size_t)NSLOT * NHEAD * DHEAD * DHEAD];
__device__ __nv_bfloat16 g_xhi[T_LEN * HID];
__device__ __nv_bfloat16 g_xlo[T_LEN * HID];
__device__ __nv_bfloat16 g_onhi[T_LEN * KD];
__device__ __nv_bfloat16 g_onlo[T_LEN * KD];
__device__ __nv_bfloat16 g_wthi[(size_t)4 * WELEM];
__device__ __nv_bfloat16 g_wtlo[(size_t)4 * WELEM];

// ---------------- f32x2 helpers ----------------
typedef unsigned long long u64;
__device__ __forceinline__ u64 splat2(float a) {
    u64 d; unsigned u = __float_as_uint(a);
    asm("mov.b64 %0, {%1, %1};" : "=l"(d) : "r"(u));
    return d;
}
__device__ __forceinline__ void ffma2(u64& d, u64 a, u64 b) {
    asm("fma.rn.f32x2 %0, %1, %2, %0;" : "+l"(d) : "l"(a), "l"(b));
}
__device__ __forceinline__ float2 unpk(u64 v) {
    unsigned lo, hi;
    asm("mov.b64 {%0, %1}, %2;" : "=r"(lo), "=r"(hi) : "l"(v));
    return make_float2(__uint_as_float(lo), __uint_as_float(hi));
}

// ---------------- tensor-core helpers ----------------
__device__ __forceinline__ unsigned smem_u32(const void* p) {
    unsigned a;
    asm("{ .reg .u64 t; cvta.to.shared.u64 t, %1; cvt.u32.u64 %0, t; }" : "=r"(a) : "l"(p));
    return a;
}
__device__ __forceinline__ void ldm4(unsigned (&r)[4], unsigned addr) {
    asm volatile("ldmatrix.sync.aligned.m8n8.x4.shared.b16 {%0,%1,%2,%3}, [%4];"
        : "=r"(r[0]), "=r"(r[1]), "=r"(r[2]), "=r"(r[3]) : "r"(addr));
}
__device__ __forceinline__ void mma16816(float (&c)[4], const unsigned (&a)[4],
                                         unsigned b0, unsigned b1) {
    asm volatile("mma.sync.aligned.m16n8k16.row.col.f32.bf16.bf16.f32 "
        "{%0,%1,%2,%3}, {%4,%5,%6,%7}, {%8,%9}, {%0,%1,%2,%3};"
        : "+f"(c[0]), "+f"(c[1]), "+f"(c[2]), "+f"(c[3])
        : "r"(a[0]), "r"(a[1]), "r"(a[2]), "r"(a[3]), "r"(b0), "r"(b1));
}
__device__ __forceinline__ void splitbf(float x, __nv_bfloat16& h, __nv_bfloat16& l) {
    h = __float2bfloat16_rn(x);
    l = __float2bfloat16_rn(x - __bfloat162float(h));
}
__device__ __forceinline__ unsigned pk2(__nv_bfloat16 a, __nv_bfloat16 b) {
    __nv_bfloat162 t = __halves2bfloat162(a, b);
    return *reinterpret_cast<unsigned*>(&t);
}

// ---------------- head kernel: bg + convert_x + convert_wt fused ----------------
__global__ void __launch_bounds__(256) head_kernel(const float* __restrict__ x,
                                                   const float* __restrict__ W0,
                                                   const float* __restrict__ W1,
                                                   const float* __restrict__ W2,
                                                   const float* __restrict__ W3,
                                                   const float* __restrict__ Wa,
                                                   const float* __restrict__ ba,
                                                   const float* __restrict__ Wb,
                                                   const float* __restrict__ bb) {
    const int b = blockIdx.x;
    const int tid = threadIdx.x;
    if (b < 256) {
        const int t = b;
        __shared__ __align__(16) float xs[HID];
        __shared__ float red[8][32];
        {
            const int i = tid * 8;
            *(float4*)&xs[i]     = *(const float4*)&x[t * HID + i];
            *(float4*)&xs[i + 4] = *(const float4*)&x[t * HID + i + 4];
        }
        __syncthreads();
        const int col = tid & 31;
        const int kg = tid >> 5;
        const float* Wsel = (col < 16) ? Wa : Wb;
        const int c = col & 15;
        const int kb = kg * 256;
        float a0 = 0.f, a1 = 0.f, a2 = 0.f, a3 = 0.f;
#pragma unroll 16
        for (int k = 0; k < 256; k += 4) {
            a0 += xs[kb + k]     * Wsel[(kb + k) * NHEAD + c];
            a1 += xs[kb + k + 1] * Wsel[(kb + k + 1) * NHEAD + c];
            a2 += xs[kb + k + 2] * Wsel[(kb + k + 2) * NHEAD + c];
            a3 += xs[kb + k + 3] * Wsel[(kb + k + 3) * NHEAD + c];
        }
        red[kg][col] = (a0 + a1) + (a2 + a3);
        __syncthreads();
        if (kg == 0) {
            float v = 0.f;
#pragma unroll
            for (int g = 0; g < 8; g++) v += red[g][col];
            if (col < 16) {
                g_decay[t * NHEAD + c] = 1.f / (1.f + expf(-(v + ba[c])));
            } else {
                g_beta[t * NHEAD + c] = 1.f / (1.f + expf(-(v + bb[c])));
            }
        }
        return;
    }
    if (b < 512) {
        const int i = ((b - 256) * 256 + tid) * 8;
        float4 a = *(const float4*)(x + i);
        float4 bb4 = *(const float4*)(x + i + 4);
        float v[8] = {a.x, a.y, a.z, a.w, bb4.x, bb4.y, bb4.z, bb4.w};
        __nv_bfloat16 h[8], l[8];
#pragma unroll
        for (int e = 0; e < 8; e++) splitbf(v[e], h[e], l[e]);
        uint4 ph = make_uint4(pk2(h[0], h[1]), pk2(h[2], h[3]), pk2(h[4], h[5]), pk2(h[6], h[7]));
        uint4 pl = make_uint4(pk2(l[0], l[1]), pk2(l[2], l[3]), pk2(l[4], l[5]), pk2(l[6], l[7]));
        *(uint4*)(g_xhi + i) = ph;
        *(uint4*)(g_xlo + i) = pl;
        return;
    }
    __shared__ float T[32][33];
    const int bp = b - 512;
    const int mat = bp >> 12;
    const int bx = bp & 4095;
    const float* W = (mat == 0) ? W0 : (mat == 1) ? W1 : (mat == 2) ? W2 : W3;
    __nv_bfloat16* oh = g_wthi + (size_t)mat * WELEM;
    __nv_bfloat16* ol = g_wtlo + (size_t)mat * WELEM;
    const int k0 = (bx & 63) * 32;
    const int n0 = (bx >> 6) * 32;
    const int r = tid >> 5, c = tid & 31;
#pragma unroll
    for (int p = 0; p < 4; p++) {
        int k = k0 + p * 8 + r;
        T[c][p * 8 + r] = W[(size_t)k * 2048 + n0 + c];
    }
    __syncthreads();
    const int nl = tid >> 3, kc = (tid & 7) * 4;
    float v0 = T[nl][kc], v1 = T[nl][kc + 1], v2 = T[nl][kc + 2], v3 = T[nl][kc + 3];
    __nv_bfloat16 h0, h1, h2, h3, l0, l1, l2, l3;
    splitbf(v0, h0, l0); splitbf(v1, h1, l1);
    splitbf(v2, h2, l2); splitbf(v3, h3, l3);
    uint2 ph = make_uint2(pk2(h0, h1), pk2(h2, h3));
    uint2 pl = make_uint2(pk2(l0, l1), pk2(l2, l3));
    size_t off = (size_t)(n0 + nl) * 2048 + k0 + kc;
    *(uint2*)(oh + off) = ph;
    *(uint2*)(ol + off) = pl;
}

// ---------------- tensor GEMM tile ----------------
__device__ __forceinline__ void tensor_gemm_tile(const __nv_bfloat16* __restrict__ Ahi,
                                                 const __nv_bfloat16* __restrict__ Alo,
                                                 const __nv_bfloat16* __restrict__ Bth,
                                                 const __nv_bfloat16* __restrict__ Btl,
                                                 float* __restrict__ C,
                                                 int m0, int n0) {
    __shared__ __align__(16) __nv_bfloat16 sAh[64 * 40];
    __shared__ __align__(16) __nv_bfloat16 sAl[64 * 40];
    __shared__ __align__(16) __nv_bfloat16 sBh[128 * 40];
    __shared__ __align__(16) __nv_bfloat16 sBl[128 * 40];

    const int tid = threadIdx.x;
    const int lane = tid & 31;
    const int warp = tid >> 5;
    const int wm0 = (warp & 1) * 32;
    const int wn0 = (warp >> 1) * 64;

    float acc[2][8][4];
#pragma unroll
    for (int i = 0; i < 2; i++)
#pragma unroll
        for (int j = 0; j < 8; j++)
#pragma unroll
            for (int q = 0; q < 4; q++) acc[i][j][q] = 0.f;

    const unsigned baseAh = smem_u32(sAh), baseAl = smem_u32(sAl);
    const unsigned baseBh = smem_u32(sBh), baseBl = smem_u32(sBl);

    const int a_k = (lane >> 4) * 8;
    const int b_k = ((lane >> 3) & 1) * 8;
    const int a_r = lane & 15;
    const int b_r = ((lane >> 4) & 1) * 8 + (lane & 7);

    const int am = tid >> 1, aseg = (tid & 1) * 16;
    const size_t a_src = (size_t)(m0 + am) * 2048 + aseg;
    const size_t b_src = (size_t)(n0 + tid) * 2048;

    for (int k0 = 0; k0 < 2048; k0 += 32) {
        uint4 rah0 = *(const uint4*)(Ahi + a_src + k0);
        uint4 rah1 = *(const uint4*)(Ahi + a_src + k0 + 8);
        uint4 ral0 = *(const uint4*)(Alo + a_src + k0);
        uint4 ral1 = *(const uint4*)(Alo + a_src + k0 + 8);
        uint4 rbh0 = *(const uint4*)(Bth + b_src + k0);
        uint4 rbh1 = *(const uint4*)(Bth + b_src + k0 + 8);
        uint4 rbh2 = *(const uint4*)(Bth + b_src + k0 + 16);
        uint4 rbh3 = *(const uint4*)(Bth + b_src + k0 + 24);
        uint4 rbl0 = *(const uint4*)(Btl + b_src + k0);
        uint4 rbl1 = *(const uint4*)(Btl + b_src + k0 + 8);
        uint4 rbl2 = *(const uint4*)(Btl + b_src + k0 + 16);
        uint4 rbl3 = *(const uint4*)(Btl + b_src + k0 + 24);
        __syncthreads();
        *(uint4*)&sAh[am * 40 + aseg]     = rah0;
        *(uint4*)&sAh[am * 40 + aseg + 8] = rah1;
        *(uint4*)&sAl[am * 40 + aseg]     = ral0;
        *(uint4*)&sAl[am * 40 + aseg + 8] = ral1;
        *(uint4*)&sBh[tid * 40]      = rbh0;
        *(uint4*)&sBh[tid * 40 + 8]  = rbh1;
        *(uint4*)&sBh[tid * 40 + 16] = rbh2;
        *(uint4*)&sBh[tid * 40 + 24] = rbh3;
        *(uint4*)&sBl[tid * 40]      = rbl0;
        *(uint4*)&sBl[tid * 40 + 8]  = rbl1;
        *(uint4*)&sBl[tid * 40 + 16] = rbl2;
        *(uint4*)&sBl[tid * 40 + 24] = rbl3;
        __syncthreads();

#pragma unroll
        for (int ks = 0; ks < 2; ks++) {
            unsigned bh[4][4], bl[4][4];
#pragma unroll
            for (int p = 0; p < 4; p++) {
                unsigned addr = ((unsigned)((wn0 + p * 16 + b_r) * 40 + ks * 16 + b_k)) * 2;
                ldm4(bh[p], baseBh + addr);
                ldm4(bl[p], baseBl + addr);
            }
#pragma unroll
            for (int mi = 0; mi < 2; mi++) {
                unsigned ah[4], al[4];
                unsigned addr = ((unsigned)((wm0 + mi * 16 + a_r) * 40 + ks * 16 + a_k)) * 2;
                ldm4(ah, baseAh + addr);
                ldm4(al, baseAl + addr);
#pragma unroll
                for (int nj = 0; nj < 8; nj++) {
                    unsigned b0h = bh[nj >> 1][(nj & 1) * 2];
                    unsigned b1h = bh[nj >> 1][(nj & 1) * 2 + 1];
                    unsigned b0l = bl[nj >> 1][(nj & 1) * 2];
                    unsigned b1l = bl[nj >> 1][(nj & 1) * 2 + 1];
                    mma16816(acc[mi][nj], ah, b0h, b1h);
                    mma16816(acc[mi][nj], ah, b0l, b1l);
                    mma16816(acc[mi][nj], al, b0h, b1h);
                }
            }
        }
    }

    const int g = lane >> 2, tc = (lane & 3) * 2;
#pragma unroll
    for (int mi = 0; mi < 2; mi++)
#pragma unroll
        for (int nj = 0; nj < 8; nj++) {
            int row = m0 + wm0 + 16 * mi + g;
            int col = n0 + wn0 + 8 * nj + tc;
            *(float2*)&C[(size_t)row * 2048 + col] =
                make_float2(acc[mi][nj][0], acc[mi][nj][1]);
            *(float2*)&C[(size_t)(row + 8) * 2048 + col] =
                make_float2(acc[mi][nj][2], acc[mi][nj][3]);
        }
}

__global__ void __launch_bounds__(128) qkv_tensor_kernel() {
    const int mat = blockIdx.z;
    const __nv_bfloat16* bh = g_wthi + (size_t)mat * WELEM;
    const __nv_bfloat16* bl = g_wtlo + (size_t)mat * WELEM;
    float* C = (mat == 0) ? g_Q0 : (mat == 1) ? g_K0 : g_V0;
    tensor_gemm_tile(g_xhi, g_xlo, bh, bl, C, blockIdx.y * 64, blockIdx.x * 128);
}

__global__ void __launch_bounds__(128) out_tensor_kernel(float* __restrict__ out) {
    tensor_gemm_tile(g_onhi, g_onlo, g_wthi + (size_t)3 * WELEM, g_wtlo + (size_t)3 * WELEM,
                     out, blockIdx.y * 64, blockIdx.x * 128);
}

// ---------------- prep: conv(4)+silu+l2norm ----------------
__device__ __forceinline__ void conv_silu_l2(const float* __restrict__ src,
                                             const float* __restrict__ cw,
                                             float* __restrict__ dst,
                                             int t, int tid) {
    const int c0 = tid * 8;
    float wv[8][4];
#pragma unroll
    for (int e = 0; e < 8; e++) {
        float4 f = *(const float4*)&cw[(c0 + e) * 4];
        wv[e][0] = f.x; wv[e][1] = f.y; wv[e][2] = f.z; wv[e][3] = f.w;
    }
    float y[8];
#pragma unroll
    for (int e = 0; e < 8; e++) y[e] = 0.f;
#pragma unroll
    for (int i = 0; i < 4; i++) {
        int ts = t + i - 3;
        if (ts >= 0) {
            float4 xa = *(const float4*)&src[ts * HID + c0];
            float4 xb = *(const float4*)&src[ts * HID + c0 + 4];
            float xv[8] = {xa.x, xa.y, xa.z, xa.w, xb.x, xb.y, xb.z, xb.w};
#pragma unroll
            for (int e = 0; e < 8; e++) y[e] += xv[e] * wv[e][i];
        }
    }
#pragma unroll
    for (int e = 0; e < 8; e++) {
        float s = 1.f / (1.f + expf(-y[e]));
        y[e] *= s;
    }
    float ss = 0.f;
#pragma unroll
    for (int e = 0; e < 8; e++) ss += y[e] * y[e];
#pragma unroll
    for (int off = 1; off <= 8; off <<= 1) ss += __shfl_xor_sync(0xffffffffu, ss, off);
    float sc = rsqrtf(ss + 1e-6f);
    *(float4*)&dst[t * HID + c0] = make_float4(y[0] * sc, y[1] * sc, y[2] * sc, y[3] * sc);
    *(float4*)&dst[t * HID + c0 + 4] = make_float4(y[4] * sc, y[5] * sc, y[6] * sc, y[7] * sc);
}

__global__ void __launch_bounds__(256) prep_kernel(const float* __restrict__ cwq,
                                                   const float* __restrict__ cwk) {
    const int t = blockIdx.x;
    const int tid = threadIdx.x;
    conv_silu_l2(g_Q0, cwq, g_qn, t, tid);
    conv_silu_l2(g_K0, cwk, g_kn, t, tid);
}

// ---------------- state scan: time-blocked staging (16 steps / barrier pair) ----------------
__global__ void __launch_bounds__(256) scan_kernel() {
    const int h = blockIdx.y;
    const int i0 = blockIdx.x * 8;
    const int tid = threadIdx.x;
    __shared__ float ds[T_LEN], bs[T_LEN];
    __shared__ __align__(16) float ks[SCHUNK][DHEAD], vs[SCHUNK][DHEAD];
    ds[tid] = g_decay[tid * NHEAD + h];
    bs[tid] = g_beta[tid * NHEAD + h];
    const int row = i0 + (tid >> 5);
    const int j0 = (tid & 31) * 4;
    const int ls = tid >> 4;            // 0..15 timestep slot to load
    const int lc = (tid & 15) * 8;      // 0..120 column
    float kk0 = 0, kk1 = 0, kk2 = 0, kk3 = 0;
    float kv0 = 0, kv1 = 0, kv2 = 0, kv3 = 0;

    for (int tb = 0; tb < T_LEN; tb += SCHUNK) {
        __syncthreads();                // previous chunk's reads done
        {
            const float* kp = &g_kn[(tb + ls) * HID + h * DHEAD + lc];
            const float* vp = &g_V0[(tb + ls) * HID + h * DHEAD + lc];
            *(float4*)&ks[ls][lc]     = *(const float4*)&kp[0];
            *(float4*)&ks[ls][lc + 4] = *(const float4*)&kp[4];
            *(float4*)&vs[ls][lc]     = *(const float4*)&vp[0];
            *(float4*)&vs[ls][lc + 4] = *(const float4*)&vp[4];
        }
        __syncthreads();
#pragma unroll
        for (int s = 0; s < SCHUNK; s++) {
            const int t = tb + s;
            const float d = ds[t], b = bs[t];
            const float kr = ks[s][row];          // warp-uniform broadcast
            float4 kj = *(const float4*)&ks[s][j0];
            float4 vj = *(const float4*)&vs[s][j0];
            const float bk = b * kr;
            kk0 = kk0 * d + bk * kj.x; kk1 = kk1 * d + bk * kj.y;
            kk2 = kk2 * d + bk * kj.z; kk3 = kk3 * d + bk * kj.w;
            kv0 = kv0 * d + bk * vj.x; kv1 = kv1 * d + bk * vj.y;
            kv2 = kv2 * d + bk * vj.z; kv3 = kv3 * d + bk * vj.w;
            if ((s & (CHUNK - 1)) == CHUNK - 1) {
                const int slot = t / CHUNK;
                size_t base = (((size_t)slot * NHEAD + h) << 14) + (size_t)row * DHEAD + j0;
                *(float4*)&g_hkk_ck[base] = make_float4(kk0, kk1, kk2, kk3);
                *(float4*)&g_hkv_ck[base] = make_float4(kv0, kv1, kv2, kv3);
            }
        }
    }
}

// ---------------- block reduce (shfl tree + parity buffer) ----------------
__device__ __forceinline__ float blockReduce128(float v, int pb) {
    __shared__ float red[2][4];
#pragma unroll
    for (int off = 16; off > 0; off >>= 1) v += __shfl_xor_sync(0xffffffffu, v, off);
    const int wp = threadIdx.x >> 5;
    if ((threadIdx.x & 31) == 0) red[pb][wp] = v;
    __syncthreads();
    return red[pb][0] + red[pb][1] + red[pb][2] + red[pb][3];
}

// ---------------- merged CG solve (bf16 split fused into epilogue) ----------------
__global__ void __launch_bounds__(128, 4) solve_kernel(const float* __restrict__ onw,
                                                       const float* __restrict__ lp) {
    const int h = blockIdx.x;
    const int chunk = blockIdx.y;
    const int cs = chunk * CHUNK;
    const int slot = chunk - 1;
    const int r = threadIdx.x;

    __shared__ __align__(16) float ks[CHUNK][DHEAD];
    __shared__ __align__(16) float vs[CHUNK][DHEAD];
    __shared__ __align__(16) float ps[DHEAD];
    __shared__ float dsh[CHUNK], bsh[CHUNK], Pp[CHUNK], cf[CHUNK], gsh[CHUNK];

    {
        const int row = r >> 4;
        const int c0 = (r & 15) * 8;
        const float* kp = &g_kn[(cs + row) * HID + h * DHEAD + c0];
        const float* vp = &g_V0[(cs + row) * HID + h * DHEAD + c0];
        *(float4*)&ks[row][c0]     = *(const float4*)&kp[0];
        *(float4*)&ks[row][c0 + 4] = *(const float4*)&kp[4];
        *(float4*)&vs[row][c0]     = *(const float4*)&vp[0];
        *(float4*)&vs[row][c0 + 4] = *(const float4*)&vp[4];
        if (r < CHUNK) {
            dsh[r] = g_decay[(cs + r) * NHEAD + h];
            bsh[r] = g_beta[(cs + r) * NHEAD + h];
        }
    }
    __syncthreads();
    if (r == 0) {
        float run = 1.f;
#pragma unroll
        for (int s = 0; s < CHUNK; s++) {
            run *= dsh[s];
            Pp[s] = run;
            cf[s] = bsh[s] / run;
        }
    }

    float lam;
    {
        float v = lp[h * DHEAD + r];
        lam = ((v > 20.f) ? v : log1pf(expf(v))) + 0.25f;
    }

    ulonglong2 B2[32];
    if (slot >= 0) {
        const float* base = g_hkk_ck + (((size_t)slot * NHEAD + h) << 14) + (size_t)r * DHEAD;
#pragma unroll
        for (int i = 0; i < 32; i++) B2[i] = *(const ulonglong2*)&base[i * 4];
    } else {
#pragma unroll
        for (int i = 0; i < 32; i++) { B2[i].x = 0ull; B2[i].y = 0ull; }
    }
    const float* kvb = (slot >= 0)
        ? g_hkv_ck + (((size_t)slot * NHEAD + h) << 14) + r : (const float*)0;
    __syncthreads();

    int par = 0;
    for (int jt = 0; jt < CHUNK; jt++) {
        const int t = cs + jt;
        {
            u64 w = splat2(cf[jt] * ks[jt][r]);
            const u64* kkp = (const u64*)&ks[jt][0];
#pragma unroll
            for (int i = 0; i < 32; i++) {
                ffma2(B2[i].x, w, kkp[2 * i]);
                ffma2(B2[i].y, w, kkp[2 * i + 1]);
            }
        }
        const float Pt = Pp[jt];
        const float b = g_qn[t * HID + h * DHEAD + r];

        float xx = 0.f, rr = b, p = b;
        ps[r] = b;
        float rs = blockReduce128(b * b, par); par ^= 1;
        const float rs_stop = 1e-8f * rs;

        for (int it = 0; it < 30; it++) {
            u64 aA = 0ull, aB = 0ull, aC = 0ull, aD = 0ull;
#pragma unroll
            for (int i = 0; i < 32; i += 2) {
                ulonglong2 p0 = *(const ulonglong2*)&ps[i * 4];
                ulonglong2 p1 = *(const ulonglong2*)&ps[i * 4 + 4];
                ffma2(aA, B2[i].x, p0.x);     ffma2(aB, B2[i].y, p0.y);
                ffma2(aC, B2[i + 1].x, p1.x); ffma2(aD, B2[i + 1].y, p1.y);
            }
            float2 fa = unpk(aA), fb = unpk(aB), fc = unpk(aC), fd = unpk(aD);
            float bp = ((fa.x + fa.y) + (fb.x + fb.y)) + ((fc.x + fc.y) + (fd.x + fd.y));
            float ap = Pt * bp + lam * p;
            float pap = blockReduce128(p * ap, par); par ^= 1;
            float alpha = rs / (pap + 1e-12f);
            xx += alpha * p;
            rr -= alpha * ap;
            float rsn = blockReduce128(rr * rr, par); par ^= 1;
            if (rsn < rs_stop) break;
            float bet = rsn / (rs + 1e-12f);
            p = rr + bet * p;
            rs = rsn;
            ps[r] = p;
            __syncthreads();
        }

        ps[r] = xx;
        __syncthreads();
        {
            const int sIdx = r >> 4;
            const int part = r & 15;
            float pg = 0.f;
            const int e0 = part * 8;
#pragma unroll
            for (int e = 0; e < 8; e++) pg += ks[sIdx][e0 + e] * ps[e0 + e];
#pragma unroll
            for (int off = 1; off <= 8; off <<= 1) pg += __shfl_xor_sync(0xffffffffu, pg, off);
            if (part == 0)
                gsh[sIdx] = (sIdx <= jt) ? pg * cf[sIdx] * Pt : 0.f;
        }
        __syncthreads();

        float o = 0.f;
        if (slot >= 0) {
            float o0 = 0, o1 = 0, o2 = 0, o3 = 0;
#pragma unroll
            for (int k2 = 0; k2 < DHEAD; k2 += 4) {
                o0 += ps[k2]     * kvb[(size_t)k2 * DHEAD];
                o1 += ps[k2 + 1] * kvb[(size_t)(k2 + 1) * DHEAD];
                o2 += ps[k2 + 2] * kvb[(size_t)(k2 + 2) * DHEAD];
                o3 += ps[k2 + 3] * kvb[(size_t)(k2 + 3) * DHEAD];
            }
            o = Pt * ((o0 + o1) + (o2 + o3));
        }
#pragma unroll
        for (int s = 0; s < CHUNK; s++) o += gsh[s] * vs[s][r];

        float ms = blockReduce128(o * o, par) * (1.0f / 128.0f); par ^= 1;
        float sc = rsqrtf(ms + 1e-5f);
        float val = o * sc * onw[r];
        __nv_bfloat16 hb, lb;
        splitbf(val, hb, lb);
        g_onhi[t * HID + h * DHEAD + r] = hb;
        g_onlo[t * HID + h * DHEAD + r] = lb;
        __syncthreads();
    }
}

// ---------------- launch ----------------
extern "C" void kernel_launch(void* const* d_in, const int* in_sizes, int n_in,
                              void* d_out, int out_size) {
    const float* x    = (const float*)d_in[0];
    const float* Wq   = (const float*)d_in[1];
    const float* Wk   = (const float*)d_in[2];
    const float* Wv   = (const float*)d_in[3];
    const float* Wa   = (const float*)d_in[4];
    const float* ba   = (const float*)d_in[5];
    const float* Wb   = (const float*)d_in[6];
    const float* bb   = (const float*)d_in[7];
    const float* cwq  = (const float*)d_in[8];
    const float* cwk  = (const float*)d_in[9];
    const float* lp   = (const float*)d_in[10];
    const float* onw  = (const float*)d_in[11];
    const float* Wo   = (const float*)d_in[12];
    float* out = (float*)d_out;

    head_kernel<<<16896, 256>>>(x, Wq, Wk, Wv, Wo, Wa, ba, Wb, bb);
    qkv_tensor_kernel<<<dim3(16, 4, 3), 128>>>();
    prep_kernel<<<256, 256>>>(cwq, cwk);
    scan_kernel<<<dim3(16, NHEAD), 256>>>();
    solve_kernel<<<dim3(NHEAD, NSLOT), 128>>>(onw, lp);
    out_tensor_kernel<<<dim3(16, 4), 128>>>(out);
}

// round 15
// speedup vs baseline: 2.4300x; 1.0355x over previous
#include <cuda_runtime.h>
#include <cuda_bf16.h>
#include <math.h>

#define T_LEN 256
#define HID   2048
#define NHEAD 16
#define DHEAD 128
#define KD    2048
#define CHUNK 8
#define NSLOT (T_LEN / CHUNK)
#define SCHUNK 16
#define WELEM (KD * HID)

// ---------------- scratch ----------------
__device__ float g_Q0[T_LEN * KD];
__device__ float g_K0[T_LEN * KD];
__device__ float g_V0[T_LEN * KD];
__device__ float g_qn[T_LEN * KD];
__device__ float g_kn[T_LEN * KD];
__device__ float g_beta[T_LEN * NHEAD];
__device__ float g_decay[T_LEN * NHEAD];
__device__ float g_hkk_ck[(size_t)NSLOT * NHEAD * DHEAD * DHEAD];
__device__ float g_hkv_ck[(size_t)NSLOT * NHEAD * DHEAD * DHEAD];
__device__ __nv_bfloat16 g_xhi[T_LEN * HID];
__device__ __nv_bfloat16 g_xlo[T_LEN * HID];
__device__ __nv_bfloat16 g_onhi[T_LEN * KD];
__device__ __nv_bfloat16 g_onlo[T_LEN * KD];
__device__ __nv_bfloat16 g_wthi[(size_t)4 * WELEM];
__device__ __nv_bfloat16 g_wtlo[(size_t)4 * WELEM];

// ---------------- f32x2 helpers ----------------
typedef unsigned long long u64;
__device__ __forceinline__ u64 splat2(float a) {
    u64 d; unsigned u = __float_as_uint(a);
    asm("mov.b64 %0, {%1, %1};" : "=l"(d) : "r"(u));
    return d;
}
__device__ __forceinline__ void ffma2(u64& d, u64 a, u64 b) {
    asm("fma.rn.f32x2 %0, %1, %2, %0;" : "+l"(d) : "l"(a), "l"(b));
}
__device__ __forceinline__ float2 unpk(u64 v) {
    unsigned lo, hi;
    asm("mov.b64 {%0, %1}, %2;" : "=r"(lo), "=r"(hi) : "l"(v));
    return make_float2(__uint_as_float(lo), __uint_as_float(hi));
}

// ---------------- tensor-core helpers ----------------
__device__ __forceinline__ unsigned smem_u32(const void* p) {
    unsigned a;
    asm("{ .reg .u64 t; cvta.to.shared.u64 t, %1; cvt.u32.u64 %0, t; }" : "=r"(a) : "l"(p));
    return a;
}
__device__ __forceinline__ void ldm4(unsigned (&r)[4], unsigned addr) {
    asm volatile("ldmatrix.sync.aligned.m8n8.x4.shared.b16 {%0,%1,%2,%3}, [%4];"
        : "=r"(r[0]), "=r"(r[1]), "=r"(r[2]), "=r"(r[3]) : "r"(addr));
}
__device__ __forceinline__ void mma16816(float (&c)[4], const unsigned (&a)[4],
                                         unsigned b0, unsigned b1) {
    asm volatile("mma.sync.aligned.m16n8k16.row.col.f32.bf16.bf16.f32 "
        "{%0,%1,%2,%3}, {%4,%5,%6,%7}, {%8,%9}, {%0,%1,%2,%3};"
        : "+f"(c[0]), "+f"(c[1]), "+f"(c[2]), "+f"(c[3])
        : "r"(a[0]), "r"(a[1]), "r"(a[2]), "r"(a[3]), "r"(b0), "r"(b1));
}
__device__ __forceinline__ void splitbf(float x, __nv_bfloat16& h, __nv_bfloat16& l) {
    h = __float2bfloat16_rn(x);
    l = __float2bfloat16_rn(x - __bfloat162float(h));
}
__device__ __forceinline__ unsigned pk2(__nv_bfloat16 a, __nv_bfloat16 b) {
    __nv_bfloat162 t = __halves2bfloat162(a, b);
    return *reinterpret_cast<unsigned*>(&t);
}

// ---------------- head kernel: bg + convert_x + convert_wt fused ----------------
__global__ void __launch_bounds__(256) head_kernel(const float* __restrict__ x,
                                                   const float* __restrict__ W0,
                                                   const float* __restrict__ W1,
                                                   const float* __restrict__ W2,
                                                   const float* __restrict__ W3,
                                                   const float* __restrict__ Wa,
                                                   const float* __restrict__ ba,
                                                   const float* __restrict__ Wb,
                                                   const float* __restrict__ bb) {
    const int b = blockIdx.x;
    const int tid = threadIdx.x;
    if (b < 256) {
        const int t = b;
        __shared__ __align__(16) float xs[HID];
        __shared__ float red[8][32];
        {
            const int i = tid * 8;
            *(float4*)&xs[i]     = *(const float4*)&x[t * HID + i];
            *(float4*)&xs[i + 4] = *(const float4*)&x[t * HID + i + 4];
        }
        __syncthreads();
        const int col = tid & 31;
        const int kg = tid >> 5;
        const float* Wsel = (col < 16) ? Wa : Wb;
        const int c = col & 15;
        const int kb = kg * 256;
        float a0 = 0.f, a1 = 0.f, a2 = 0.f, a3 = 0.f;
#pragma unroll 16
        for (int k = 0; k < 256; k += 4) {
            a0 += xs[kb + k]     * Wsel[(kb + k) * NHEAD + c];
            a1 += xs[kb + k + 1] * Wsel[(kb + k + 1) * NHEAD + c];
            a2 += xs[kb + k + 2] * Wsel[(kb + k + 2) * NHEAD + c];
            a3 += xs[kb + k + 3] * Wsel[(kb + k + 3) * NHEAD + c];
        }
        red[kg][col] = (a0 + a1) + (a2 + a3);
        __syncthreads();
        if (kg == 0) {
            float v = 0.f;
#pragma unroll
            for (int g = 0; g < 8; g++) v += red[g][col];
            if (col < 16) {
                g_decay[t * NHEAD + c] = 1.f / (1.f + expf(-(v + ba[c])));
            } else {
                g_beta[t * NHEAD + c] = 1.f / (1.f + expf(-(v + bb[c])));
            }
        }
        return;
    }
    if (b < 512) {
        const int i = ((b - 256) * 256 + tid) * 8;
        float4 a = *(const float4*)(x + i);
        float4 bb4 = *(const float4*)(x + i + 4);
        float v[8] = {a.x, a.y, a.z, a.w, bb4.x, bb4.y, bb4.z, bb4.w};
        __nv_bfloat16 h[8], l[8];
#pragma unroll
        for (int e = 0; e < 8; e++) splitbf(v[e], h[e], l[e]);
        uint4 ph = make_uint4(pk2(h[0], h[1]), pk2(h[2], h[3]), pk2(h[4], h[5]), pk2(h[6], h[7]));
        uint4 pl = make_uint4(pk2(l[0], l[1]), pk2(l[2], l[3]), pk2(l[4], l[5]), pk2(l[6], l[7]));
        *(uint4*)(g_xhi + i) = ph;
        *(uint4*)(g_xlo + i) = pl;
        return;
    }
    __shared__ float T[32][33];
    const int bp = b - 512;
    const int mat = bp >> 12;
    const int bx = bp & 4095;
    const float* W = (mat == 0) ? W0 : (mat == 1) ? W1 : (mat == 2) ? W2 : W3;
    __nv_bfloat16* oh = g_wthi + (size_t)mat * WELEM;
    __nv_bfloat16* ol = g_wtlo + (size_t)mat * WELEM;
    const int k0 = (bx & 63) * 32;
    const int n0 = (bx >> 6) * 32;
    const int r = tid >> 5, c = tid & 31;
#pragma unroll
    for (int p = 0; p < 4; p++) {
        int k = k0 + p * 8 + r;
        T[c][p * 8 + r] = W[(size_t)k * 2048 + n0 + c];
    }
    __syncthreads();
    const int nl = tid >> 3, kc = (tid & 7) * 4;
    float v0 = T[nl][kc], v1 = T[nl][kc + 1], v2 = T[nl][kc + 2], v3 = T[nl][kc + 3];
    __nv_bfloat16 h0, h1, h2, h3, l0, l1, l2, l3;
    splitbf(v0, h0, l0); splitbf(v1, h1, l1);
    splitbf(v2, h2, l2); splitbf(v3, h3, l3);
    uint2 ph = make_uint2(pk2(h0, h1), pk2(h2, h3));
    uint2 pl = make_uint2(pk2(l0, l1), pk2(l2, l3));
    size_t off = (size_t)(n0 + nl) * 2048 + k0 + kc;
    *(uint2*)(oh + off) = ph;
    *(uint2*)(ol + off) = pl;
}

// ---------------- tensor GEMM tile (software-pipelined: LDG(i+1) before compute(i)) ----------------
__device__ __forceinline__ void tensor_gemm_tile(const __nv_bfloat16* __restrict__ Ahi,
                                                 const __nv_bfloat16* __restrict__ Alo,
                                                 const __nv_bfloat16* __restrict__ Bth,
                                                 const __nv_bfloat16* __restrict__ Btl,
                                                 float* __restrict__ C,
                                                 int m0, int n0) {
    __shared__ __align__(16) __nv_bfloat16 sAh[64 * 40];
    __shared__ __align__(16) __nv_bfloat16 sAl[64 * 40];
    __shared__ __align__(16) __nv_bfloat16 sBh[128 * 40];
    __shared__ __align__(16) __nv_bfloat16 sBl[128 * 40];

    const int tid = threadIdx.x;
    const int lane = tid & 31;
    const int warp = tid >> 5;
    const int wm0 = (warp & 1) * 32;
    const int wn0 = (warp >> 1) * 64;

    float acc[2][8][4];
#pragma unroll
    for (int i = 0; i < 2; i++)
#pragma unroll
        for (int j = 0; j < 8; j++)
#pragma unroll
            for (int q = 0; q < 4; q++) acc[i][j][q] = 0.f;

    const unsigned baseAh = smem_u32(sAh), baseAl = smem_u32(sAl);
    const unsigned baseBh = smem_u32(sBh), baseBl = smem_u32(sBl);

    const int a_k = (lane >> 4) * 8;
    const int b_k = ((lane >> 3) & 1) * 8;
    const int a_r = lane & 15;
    const int b_r = ((lane >> 4) & 1) * 8 + (lane & 7);

    const int am = tid >> 1, aseg = (tid & 1) * 16;
    const size_t a_src = (size_t)(m0 + am) * 2048 + aseg;
    const size_t b_src = (size_t)(n0 + tid) * 2048;

    // prefetch tile 0 into registers
    uint4 rah0 = *(const uint4*)(Ahi + a_src);
    uint4 rah1 = *(const uint4*)(Ahi + a_src + 8);
    uint4 ral0 = *(const uint4*)(Alo + a_src);
    uint4 ral1 = *(const uint4*)(Alo + a_src + 8);
    uint4 rbh0 = *(const uint4*)(Bth + b_src);
    uint4 rbh1 = *(const uint4*)(Bth + b_src + 8);
    uint4 rbh2 = *(const uint4*)(Bth + b_src + 16);
    uint4 rbh3 = *(const uint4*)(Bth + b_src + 24);
    uint4 rbl0 = *(const uint4*)(Btl + b_src);
    uint4 rbl1 = *(const uint4*)(Btl + b_src + 8);
    uint4 rbl2 = *(const uint4*)(Btl + b_src + 16);
    uint4 rbl3 = *(const uint4*)(Btl + b_src + 24);

    for (int k0 = 0; k0 < 2048; k0 += 32) {
        __syncthreads();   // all reads of smem from previous iteration done
        *(uint4*)&sAh[am * 40 + aseg]     = rah0;
        *(uint4*)&sAh[am * 40 + aseg + 8] = rah1;
        *(uint4*)&sAl[am * 40 + aseg]     = ral0;
        *(uint4*)&sAl[am * 40 + aseg + 8] = ral1;
        *(uint4*)&sBh[tid * 40]      = rbh0;
        *(uint4*)&sBh[tid * 40 + 8]  = rbh1;
        *(uint4*)&sBh[tid * 40 + 16] = rbh2;
        *(uint4*)&sBh[tid * 40 + 24] = rbh3;
        *(uint4*)&sBl[tid * 40]      = rbl0;
        *(uint4*)&sBl[tid * 40 + 8]  = rbl1;
        *(uint4*)&sBl[tid * 40 + 16] = rbl2;
        *(uint4*)&sBl[tid * 40 + 24] = rbl3;
        __syncthreads();   // smem tile valid

        // issue next tile's global loads now; consumed after the full compute below
        if (k0 + 32 < 2048) {
            const int kn = k0 + 32;
            rah0 = *(const uint4*)(Ahi + a_src + kn);
            rah1 = *(const uint4*)(Ahi + a_src + kn + 8);
            ral0 = *(const uint4*)(Alo + a_src + kn);
            ral1 = *(const uint4*)(Alo + a_src + kn + 8);
            rbh0 = *(const uint4*)(Bth + b_src + kn);
            rbh1 = *(const uint4*)(Bth + b_src + kn + 8);
            rbh2 = *(const uint4*)(Bth + b_src + kn + 16);
            rbh3 = *(const uint4*)(Bth + b_src + kn + 24);
            rbl0 = *(const uint4*)(Btl + b_src + kn);
            rbl1 = *(const uint4*)(Btl + b_src + kn + 8);
            rbl2 = *(const uint4*)(Btl + b_src + kn + 16);
            rbl3 = *(const uint4*)(Btl + b_src + kn + 24);
        }

#pragma unroll
        for (int ks = 0; ks < 2; ks++) {
            unsigned bh[4][4], bl[4][4];
#pragma unroll
            for (int p = 0; p < 4; p++) {
                unsigned addr = ((unsigned)((wn0 + p * 16 + b_r) * 40 + ks * 16 + b_k)) * 2;
                ldm4(bh[p], baseBh + addr);
                ldm4(bl[p], baseBl + addr);
            }
#pragma unroll
            for (int mi = 0; mi < 2; mi++) {
                unsigned ah[4], al[4];
                unsigned addr = ((unsigned)((wm0 + mi * 16 + a_r) * 40 + ks * 16 + a_k)) * 2;
                ldm4(ah, baseAh + addr);
                ldm4(al, baseAl + addr);
#pragma unroll
                for (int nj = 0; nj < 8; nj++) {
                    unsigned b0h = bh[nj >> 1][(nj & 1) * 2];
                    unsigned b1h = bh[nj >> 1][(nj & 1) * 2 + 1];
                    unsigned b0l = bl[nj >> 1][(nj & 1) * 2];
                    unsigned b1l = bl[nj >> 1][(nj & 1) * 2 + 1];
                    mma16816(acc[mi][nj], ah, b0h, b1h);
                    mma16816(acc[mi][nj], ah, b0l, b1l);
                    mma16816(acc[mi][nj], al, b0h, b1h);
                }
            }
        }
    }

    const int g = lane >> 2, tc = (lane & 3) * 2;
#pragma unroll
    for (int mi = 0; mi < 2; mi++)
#pragma unroll
        for (int nj = 0; nj < 8; nj++) {
            int row = m0 + wm0 + 16 * mi + g;
            int col = n0 + wn0 + 8 * nj + tc;
            *(float2*)&C[(size_t)row * 2048 + col] =
                make_float2(acc[mi][nj][0], acc[mi][nj][1]);
            *(float2*)&C[(size_t)(row + 8) * 2048 + col] =
                make_float2(acc[mi][nj][2], acc[mi][nj][3]);
        }
}

__global__ void __launch_bounds__(128) qkv_tensor_kernel() {
    const int mat = blockIdx.z;
    const __nv_bfloat16* bh = g_wthi + (size_t)mat * WELEM;
    const __nv_bfloat16* bl = g_wtlo + (size_t)mat * WELEM;
    float* C = (mat == 0) ? g_Q0 : (mat == 1) ? g_K0 : g_V0;
    tensor_gemm_tile(g_xhi, g_xlo, bh, bl, C, blockIdx.y * 64, blockIdx.x * 128);
}

__global__ void __launch_bounds__(128) out_tensor_kernel(float* __restrict__ out) {
    tensor_gemm_tile(g_onhi, g_onlo, g_wthi + (size_t)3 * WELEM, g_wtlo + (size_t)3 * WELEM,
                     out, blockIdx.y * 64, blockIdx.x * 128);
}

// ---------------- prep: conv(4)+silu+l2norm ----------------
__device__ __forceinline__ void conv_silu_l2(const float* __restrict__ src,
                                             const float* __restrict__ cw,
                                             float* __restrict__ dst,
                                             int t, int tid) {
    const int c0 = tid * 8;
    float wv[8][4];
#pragma unroll
    for (int e = 0; e < 8; e++) {
        float4 f = *(const float4*)&cw[(c0 + e) * 4];
        wv[e][0] = f.x; wv[e][1] = f.y; wv[e][2] = f.z; wv[e][3] = f.w;
    }
    float y[8];
#pragma unroll
    for (int e = 0; e < 8; e++) y[e] = 0.f;
#pragma unroll
    for (int i = 0; i < 4; i++) {
        int ts = t + i - 3;
        if (ts >= 0) {
            float4 xa = *(const float4*)&src[ts * HID + c0];
            float4 xb = *(const float4*)&src[ts * HID + c0 + 4];
            float xv[8] = {xa.x, xa.y, xa.z, xa.w, xb.x, xb.y, xb.z, xb.w};
#pragma unroll
            for (int e = 0; e < 8; e++) y[e] += xv[e] * wv[e][i];
        }
    }
#pragma unroll
    for (int e = 0; e < 8; e++) {
        float s = 1.f / (1.f + expf(-y[e]));
        y[e] *= s;
    }
    float ss = 0.f;
#pragma unroll
    for (int e = 0; e < 8; e++) ss += y[e] * y[e];
#pragma unroll
    for (int off = 1; off <= 8; off <<= 1) ss += __shfl_xor_sync(0xffffffffu, ss, off);
    float sc = rsqrtf(ss + 1e-6f);
    *(float4*)&dst[t * HID + c0] = make_float4(y[0] * sc, y[1] * sc, y[2] * sc, y[3] * sc);
    *(float4*)&dst[t * HID + c0 + 4] = make_float4(y[4] * sc, y[5] * sc, y[6] * sc, y[7] * sc);
}

__global__ void __launch_bounds__(256) prep_kernel(const float* __restrict__ cwq,
                                                   const float* __restrict__ cwk) {
    const int t = blockIdx.x;
    const int tid = threadIdx.x;
    conv_silu_l2(g_Q0, cwq, g_qn, t, tid);
    conv_silu_l2(g_K0, cwk, g_kn, t, tid);
}

// ---------------- state scan: time-blocked staging ----------------
__global__ void __launch_bounds__(256) scan_kernel() {
    const int h = blockIdx.y;
    const int i0 = blockIdx.x * 8;
    const int tid = threadIdx.x;
    __shared__ float ds[T_LEN], bs[T_LEN];
    __shared__ __align__(16) float ks[SCHUNK][DHEAD], vs[SCHUNK][DHEAD];
    ds[tid] = g_decay[tid * NHEAD + h];
    bs[tid] = g_beta[tid * NHEAD + h];
    const int row = i0 + (tid >> 5);
    const int j0 = (tid & 31) * 4;
    const int ls = tid >> 4;
    const int lc = (tid & 15) * 8;
    float kk0 = 0, kk1 = 0, kk2 = 0, kk3 = 0;
    float kv0 = 0, kv1 = 0, kv2 = 0, kv3 = 0;

    for (int tb = 0; tb < T_LEN; tb += SCHUNK) {
        __syncthreads();
        {
            const float* kp = &g_kn[(tb + ls) * HID + h * DHEAD + lc];
            const float* vp = &g_V0[(tb + ls) * HID + h * DHEAD + lc];
            *(float4*)&ks[ls][lc]     = *(const float4*)&kp[0];
            *(float4*)&ks[ls][lc + 4] = *(const float4*)&kp[4];
            *(float4*)&vs[ls][lc]     = *(const float4*)&vp[0];
            *(float4*)&vs[ls][lc + 4] = *(const float4*)&vp[4];
        }
        __syncthreads();
#pragma unroll
        for (int s = 0; s < SCHUNK; s++) {
            const int t = tb + s;
            const float d = ds[t], b = bs[t];
            const float kr = ks[s][row];
            float4 kj = *(const float4*)&ks[s][j0];
            float4 vj = *(const float4*)&vs[s][j0];
            const float bk = b * kr;
            kk0 = kk0 * d + bk * kj.x; kk1 = kk1 * d + bk * kj.y;
            kk2 = kk2 * d + bk * kj.z; kk3 = kk3 * d + bk * kj.w;
            kv0 = kv0 * d + bk * vj.x; kv1 = kv1 * d + bk * vj.y;
            kv2 = kv2 * d + bk * vj.z; kv3 = kv3 * d + bk * vj.w;
            if ((s & (CHUNK - 1)) == CHUNK - 1) {
                const int slot = t / CHUNK;
                size_t base = (((size_t)slot * NHEAD + h) << 14) + (size_t)row * DHEAD + j0;
                *(float4*)&g_hkk_ck[base] = make_float4(kk0, kk1, kk2, kk3);
                *(float4*)&g_hkv_ck[base] = make_float4(kv0, kv1, kv2, kv3);
            }
        }
    }
}

// ---------------- block reduce (shfl tree + parity buffer) ----------------
__device__ __forceinline__ float blockReduce128(float v, int pb) {
    __shared__ float red[2][4];
#pragma unroll
    for (int off = 16; off > 0; off >>= 1) v += __shfl_xor_sync(0xffffffffu, v, off);
    const int wp = threadIdx.x >> 5;
    if ((threadIdx.x & 31) == 0) red[pb][wp] = v;
    __syncthreads();
    return red[pb][0] + red[pb][1] + red[pb][2] + red[pb][3];
}

// ---------------- merged CG solve (proven R12 version) ----------------
__global__ void __launch_bounds__(128, 4) solve_kernel(const float* __restrict__ onw,
                                                       const float* __restrict__ lp) {
    const int h = blockIdx.x;
    const int chunk = blockIdx.y;
    const int cs = chunk * CHUNK;
    const int slot = chunk - 1;
    const int r = threadIdx.x;

    __shared__ __align__(16) float ks[CHUNK][DHEAD];
    __shared__ __align__(16) float vs[CHUNK][DHEAD];
    __shared__ __align__(16) float ps[DHEAD];
    __shared__ float dsh[CHUNK], bsh[CHUNK], Pp[CHUNK], cf[CHUNK], gsh[CHUNK];

    {
        const int row = r >> 4;
        const int c0 = (r & 15) * 8;
        const float* kp = &g_kn[(cs + row) * HID + h * DHEAD + c0];
        const float* vp = &g_V0[(cs + row) * HID + h * DHEAD + c0];
        *(float4*)&ks[row][c0]     = *(const float4*)&kp[0];
        *(float4*)&ks[row][c0 + 4] = *(const float4*)&kp[4];
        *(float4*)&vs[row][c0]     = *(const float4*)&vp[0];
        *(float4*)&vs[row][c0 + 4] = *(const float4*)&vp[4];
        if (r < CHUNK) {
            dsh[r] = g_decay[(cs + r) * NHEAD + h];
            bsh[r] = g_beta[(cs + r) * NHEAD + h];
        }
    }
    __syncthreads();
    if (r == 0) {
        float run = 1.f;
#pragma unroll
        for (int s = 0; s < CHUNK; s++) {
            run *= dsh[s];
            Pp[s] = run;
            cf[s] = bsh[s] / run;
        }
    }

    float lam;
    {
        float v = lp[h * DHEAD + r];
        lam = ((v > 20.f) ? v : log1pf(expf(v))) + 0.25f;
    }

    ulonglong2 B2[32];
    if (slot >= 0) {
        const float* base = g_hkk_ck + (((size_t)slot * NHEAD + h) << 14) + (size_t)r * DHEAD;
#pragma unroll
        for (int i = 0; i < 32; i++) B2[i] = *(const ulonglong2*)&base[i * 4];
    } else {
#pragma unroll
        for (int i = 0; i < 32; i++) { B2[i].x = 0ull; B2[i].y = 0ull; }
    }
    const float* kvb = (slot >= 0)
        ? g_hkv_ck + (((size_t)slot * NHEAD + h) << 14) + r : (const float*)0;
    __syncthreads();

    int par = 0;
    for (int jt = 0; jt < CHUNK; jt++) {
        const int t = cs + jt;
        {
            u64 w = splat2(cf[jt] * ks[jt][r]);
            const u64* kkp = (const u64*)&ks[jt][0];
#pragma unroll
            for (int i = 0; i < 32; i++) {
                ffma2(B2[i].x, w, kkp[2 * i]);
                ffma2(B2[i].y, w, kkp[2 * i + 1]);
            }
        }
        const float Pt = Pp[jt];
        const float b = g_qn[t * HID + h * DHEAD + r];

        float xx = 0.f, rr = b, p = b;
        ps[r] = b;
        float rs = blockReduce128(b * b, par); par ^= 1;
        const float rs_stop = 1e-8f * rs;

        for (int it = 0; it < 30; it++) {
            u64 aA = 0ull, aB = 0ull, aC = 0ull, aD = 0ull;
#pragma unroll
            for (int i = 0; i < 32; i += 2) {
                ulonglong2 p0 = *(const ulonglong2*)&ps[i * 4];
                ulonglong2 p1 = *(const ulonglong2*)&ps[i * 4 + 4];
                ffma2(aA, B2[i].x, p0.x);     ffma2(aB, B2[i].y, p0.y);
                ffma2(aC, B2[i + 1].x, p1.x); ffma2(aD, B2[i + 1].y, p1.y);
            }
            float2 fa = unpk(aA), fb = unpk(aB), fc = unpk(aC), fd = unpk(aD);
            float bp = ((fa.x + fa.y) + (fb.x + fb.y)) + ((fc.x + fc.y) + (fd.x + fd.y));
            float ap = Pt * bp + lam * p;
            float pap = blockReduce128(p * ap, par); par ^= 1;
            float alpha = rs / (pap + 1e-12f);
            xx += alpha * p;
            rr -= alpha * ap;
            float rsn = blockReduce128(rr * rr, par); par ^= 1;
            if (rsn < rs_stop) break;
            float bet = rsn / (rs + 1e-12f);
            p = rr + bet * p;
            rs = rsn;
            ps[r] = p;
            __syncthreads();
        }

        ps[r] = xx;
        __syncthreads();
        {
            const int sIdx = r >> 4;
            const int part = r & 15;
            float pg = 0.f;
            const int e0 = part * 8;
#pragma unroll
            for (int e = 0; e < 8; e++) pg += ks[sIdx][e0 + e] * ps[e0 + e];
#pragma unroll
            for (int off = 1; off <= 8; off <<= 1) pg += __shfl_xor_sync(0xffffffffu, pg, off);
            if (part == 0)
                gsh[sIdx] = (sIdx <= jt) ? pg * cf[sIdx] * Pt : 0.f;
        }
        __syncthreads();

        float o = 0.f;
        if (slot >= 0) {
            float o0 = 0, o1 = 0, o2 = 0, o3 = 0;
#pragma unroll
            for (int k2 = 0; k2 < DHEAD; k2 += 4) {
                o0 += ps[k2]     * kvb[(size_t)k2 * DHEAD];
                o1 += ps[k2 + 1] * kvb[(size_t)(k2 + 1) * DHEAD];
                o2 += ps[k2 + 2] * kvb[(size_t)(k2 + 2) * DHEAD];
                o3 += ps[k2 + 3] * kvb[(size_t)(k2 + 3) * DHEAD];
            }
            o = Pt * ((o0 + o1) + (o2 + o3));
        }
#pragma unroll
        for (int s = 0; s < CHUNK; s++) o += gsh[s] * vs[s][r];

        float ms = blockReduce128(o * o, par) * (1.0f / 128.0f); par ^= 1;
        float sc = rsqrtf(ms + 1e-5f);
        float val = o * sc * onw[r];
        __nv_bfloat16 hb, lb;
        splitbf(val, hb, lb);
        g_onhi[t * HID + h * DHEAD + r] = hb;
        g_onlo[t * HID + h * DHEAD + r] = lb;
        __syncthreads();
    }
}

// ---------------- launch ----------------
extern "C" void kernel_launch(void* const* d_in, const int* in_sizes, int n_in,
                              void* d_out, int out_size) {
    const float* x    = (const float*)d_in[0];
    const float* Wq   = (const float*)d_in[1];
    const float* Wk   = (const float*)d_in[2];
    const float* Wv   = (const float*)d_in[3];
    const float* Wa   = (const float*)d_in[4];
    const float* ba   = (const float*)d_in[5];
    const float* Wb   = (const float*)d_in[6];
    const float* bb   = (const float*)d_in[7];
    const float* cwq  = (const float*)d_in[8];
    const float* cwk  = (const float*)d_in[9];
    const float* lp   = (const float*)d_in[10];
    const float* onw  = (const float*)d_in[11];
    const float* Wo   = (const float*)d_in[12];
    float* out = (float*)d_out;

    head_kernel<<<16896, 256>>>(x, Wq, Wk, Wv, Wo, Wa, ba, Wb, bb);
    qkv_tensor_kernel<<<dim3(16, 4, 3), 128>>>();
    prep_kernel<<<256, 256>>>(cwq, cwk);
    scan_kernel<<<dim3(16, NHEAD), 256>>>();
    solve_kernel<<<dim3(NHEAD, NSLOT), 128>>>(onw, lp);
    out_tensor_kernel<<<dim3(16, 4), 128>>>(out);
}

// round 16
// speedup vs baseline: 2.4500x; 1.0082x over previous
#include <cuda_runtime.h>
#include <cuda_bf16.h>
#include <math.h>

#define T_LEN 256
#define HID   2048
#define NHEAD 16
#define DHEAD 128
#define KD    2048
#define CHUNK 8
#define NSLOT (T_LEN / CHUNK)
#define SCHUNK 16
#define WELEM (KD * HID)

// ---------------- scratch ----------------
__device__ float g_Q0[T_LEN * KD];
__device__ float g_K0[T_LEN * KD];
__device__ float g_V0[T_LEN * KD];
__device__ float g_qn[T_LEN * KD];
__device__ float g_kn[T_LEN * KD];
__device__ float g_beta[T_LEN * NHEAD];
__device__ float g_decay[T_LEN * NHEAD];
__device__ float g_hkk_ck[(size_t)NSLOT * NHEAD * DHEAD * DHEAD];
__device__ float g_hkv_ck[(size_t)NSLOT * NHEAD * DHEAD * DHEAD];
__device__ __nv_bfloat16 g_xhi[T_LEN * HID];
__device__ __nv_bfloat16 g_xlo[T_LEN * HID];
__device__ __nv_bfloat16 g_onhi[T_LEN * KD];
__device__ __nv_bfloat16 g_onlo[T_LEN * KD];
__device__ __nv_bfloat16 g_wthi[(size_t)4 * WELEM];
__device__ __nv_bfloat16 g_wtlo[(size_t)4 * WELEM];

// ---------------- f32x2 helpers ----------------
typedef unsigned long long u64;
__device__ __forceinline__ u64 splat2(float a) {
    u64 d; unsigned u = __float_as_uint(a);
    asm("mov.b64 %0, {%1, %1};" : "=l"(d) : "r"(u));
    return d;
}
__device__ __forceinline__ void ffma2(u64& d, u64 a, u64 b) {
    asm("fma.rn.f32x2 %0, %1, %2, %0;" : "+l"(d) : "l"(a), "l"(b));
}
__device__ __forceinline__ float2 unpk(u64 v) {
    unsigned lo, hi;
    asm("mov.b64 {%0, %1}, %2;" : "=r"(lo), "=r"(hi) : "l"(v));
    return make_float2(__uint_as_float(lo), __uint_as_float(hi));
}

// ---------------- tensor-core helpers ----------------
__device__ __forceinline__ unsigned smem_u32(const void* p) {
    unsigned a;
    asm("{ .reg .u64 t; cvta.to.shared.u64 t, %1; cvt.u32.u64 %0, t; }" : "=r"(a) : "l"(p));
    return a;
}
__device__ __forceinline__ void ldm4(unsigned (&r)[4], unsigned addr) {
    asm volatile("ldmatrix.sync.aligned.m8n8.x4.shared.b16 {%0,%1,%2,%3}, [%4];"
        : "=r"(r[0]), "=r"(r[1]), "=r"(r[2]), "=r"(r[3]) : "r"(addr));
}
__device__ __forceinline__ void mma16816(float (&c)[4], const unsigned (&a)[4],
                                         unsigned b0, unsigned b1) {
    asm volatile("mma.sync.aligned.m16n8k16.row.col.f32.bf16.bf16.f32 "
        "{%0,%1,%2,%3}, {%4,%5,%6,%7}, {%8,%9}, {%0,%1,%2,%3};"
        : "+f"(c[0]), "+f"(c[1]), "+f"(c[2]), "+f"(c[3])
        : "r"(a[0]), "r"(a[1]), "r"(a[2]), "r"(a[3]), "r"(b0), "r"(b1));
}
__device__ __forceinline__ void splitbf(float x, __nv_bfloat16& h, __nv_bfloat16& l) {
    h = __float2bfloat16_rn(x);
    l = __float2bfloat16_rn(x - __bfloat162float(h));
}
__device__ __forceinline__ unsigned pk2(__nv_bfloat16 a, __nv_bfloat16 b) {
    __nv_bfloat162 t = __halves2bfloat162(a, b);
    return *reinterpret_cast<unsigned*>(&t);
}

// ---------------- head kernel: bg + convert_x + convert_wt fused ----------------
__global__ void __launch_bounds__(256) head_kernel(const float* __restrict__ x,
                                                   const float* __restrict__ W0,
                                                   const float* __restrict__ W1,
                                                   const float* __restrict__ W2,
                                                   const float* __restrict__ W3,
                                                   const float* __restrict__ Wa,
                                                   const float* __restrict__ ba,
                                                   const float* __restrict__ Wb,
                                                   const float* __restrict__ bb) {
    const int b = blockIdx.x;
    const int tid = threadIdx.x;
    if (b < 256) {
        const int t = b;
        __shared__ __align__(16) float xs[HID];
        __shared__ float red[8][32];
        {
            const int i = tid * 8;
            *(float4*)&xs[i]     = *(const float4*)&x[t * HID + i];
            *(float4*)&xs[i + 4] = *(const float4*)&x[t * HID + i + 4];
        }
        __syncthreads();
        const int col = tid & 31;
        const int kg = tid >> 5;
        const float* Wsel = (col < 16) ? Wa : Wb;
        const int c = col & 15;
        const int kb = kg * 256;
        float a0 = 0.f, a1 = 0.f, a2 = 0.f, a3 = 0.f;
#pragma unroll 16
        for (int k = 0; k < 256; k += 4) {
            a0 += xs[kb + k]     * Wsel[(kb + k) * NHEAD + c];
            a1 += xs[kb + k + 1] * Wsel[(kb + k + 1) * NHEAD + c];
            a2 += xs[kb + k + 2] * Wsel[(kb + k + 2) * NHEAD + c];
            a3 += xs[kb + k + 3] * Wsel[(kb + k + 3) * NHEAD + c];
        }
        red[kg][col] = (a0 + a1) + (a2 + a3);
        __syncthreads();
        if (kg == 0) {
            float v = 0.f;
#pragma unroll
            for (int g = 0; g < 8; g++) v += red[g][col];
            if (col < 16) {
                g_decay[t * NHEAD + c] = 1.f / (1.f + expf(-(v + ba[c])));
            } else {
                g_beta[t * NHEAD + c] = 1.f / (1.f + expf(-(v + bb[c])));
            }
        }
        return;
    }
    if (b < 512) {
        const int i = ((b - 256) * 256 + tid) * 8;
        float4 a = *(const float4*)(x + i);
        float4 bb4 = *(const float4*)(x + i + 4);
        float v[8] = {a.x, a.y, a.z, a.w, bb4.x, bb4.y, bb4.z, bb4.w};
        __nv_bfloat16 h[8], l[8];
#pragma unroll
        for (int e = 0; e < 8; e++) splitbf(v[e], h[e], l[e]);
        uint4 ph = make_uint4(pk2(h[0], h[1]), pk2(h[2], h[3]), pk2(h[4], h[5]), pk2(h[6], h[7]));
        uint4 pl = make_uint4(pk2(l[0], l[1]), pk2(l[2], l[3]), pk2(l[4], l[5]), pk2(l[6], l[7]));
        *(uint4*)(g_xhi + i) = ph;
        *(uint4*)(g_xlo + i) = pl;
        return;
    }
    __shared__ float T[32][33];
    const int bp = b - 512;
    const int mat = bp >> 12;
    const int bx = bp & 4095;
    const float* W = (mat == 0) ? W0 : (mat == 1) ? W1 : (mat == 2) ? W2 : W3;
    __nv_bfloat16* oh = g_wthi + (size_t)mat * WELEM;
    __nv_bfloat16* ol = g_wtlo + (size_t)mat * WELEM;
    const int k0 = (bx & 63) * 32;
    const int n0 = (bx >> 6) * 32;
    const int r = tid >> 5, c = tid & 31;
#pragma unroll
    for (int p = 0; p < 4; p++) {
        int k = k0 + p * 8 + r;
        T[c][p * 8 + r] = W[(size_t)k * 2048 + n0 + c];
    }
    __syncthreads();
    const int nl = tid >> 3, kc = (tid & 7) * 4;
    float v0 = T[nl][kc], v1 = T[nl][kc + 1], v2 = T[nl][kc + 2], v3 = T[nl][kc + 3];
    __nv_bfloat16 h0, h1, h2, h3, l0, l1, l2, l3;
    splitbf(v0, h0, l0); splitbf(v1, h1, l1);
    splitbf(v2, h2, l2); splitbf(v3, h3, l3);
    uint2 ph = make_uint2(pk2(h0, h1), pk2(h2, h3));
    uint2 pl = make_uint2(pk2(l0, l1), pk2(l2, l3));
    size_t off = (size_t)(n0 + nl) * 2048 + k0 + kc;
    *(uint2*)(oh + off) = ph;
    *(uint2*)(ol + off) = pl;
}

// ---------------- tensor GEMM tile (software-pipelined) ----------------
__device__ __forceinline__ void tensor_gemm_tile(const __nv_bfloat16* __restrict__ Ahi,
                                                 const __nv_bfloat16* __restrict__ Alo,
                                                 const __nv_bfloat16* __restrict__ Bth,
                                                 const __nv_bfloat16* __restrict__ Btl,
                                                 float* __restrict__ C,
                                                 int m0, int n0) {
    __shared__ __align__(16) __nv_bfloat16 sAh[64 * 40];
    __shared__ __align__(16) __nv_bfloat16 sAl[64 * 40];
    __shared__ __align__(16) __nv_bfloat16 sBh[128 * 40];
    __shared__ __align__(16) __nv_bfloat16 sBl[128 * 40];

    const int tid = threadIdx.x;
    const int lane = tid & 31;
    const int warp = tid >> 5;
    const int wm0 = (warp & 1) * 32;
    const int wn0 = (warp >> 1) * 64;

    float acc[2][8][4];
#pragma unroll
    for (int i = 0; i < 2; i++)
#pragma unroll
        for (int j = 0; j < 8; j++)
#pragma unroll
            for (int q = 0; q < 4; q++) acc[i][j][q] = 0.f;

    const unsigned baseAh = smem_u32(sAh), baseAl = smem_u32(sAl);
    const unsigned baseBh = smem_u32(sBh), baseBl = smem_u32(sBl);

    const int a_k = (lane >> 4) * 8;
    const int b_k = ((lane >> 3) & 1) * 8;
    const int a_r = lane & 15;
    const int b_r = ((lane >> 4) & 1) * 8 + (lane & 7);

    const int am = tid >> 1, aseg = (tid & 1) * 16;
    const size_t a_src = (size_t)(m0 + am) * 2048 + aseg;
    const size_t b_src = (size_t)(n0 + tid) * 2048;

    uint4 rah0 = *(const uint4*)(Ahi + a_src);
    uint4 rah1 = *(const uint4*)(Ahi + a_src + 8);
    uint4 ral0 = *(const uint4*)(Alo + a_src);
    uint4 ral1 = *(const uint4*)(Alo + a_src + 8);
    uint4 rbh0 = *(const uint4*)(Bth + b_src);
    uint4 rbh1 = *(const uint4*)(Bth + b_src + 8);
    uint4 rbh2 = *(const uint4*)(Bth + b_src + 16);
    uint4 rbh3 = *(const uint4*)(Bth + b_src + 24);
    uint4 rbl0 = *(const uint4*)(Btl + b_src);
    uint4 rbl1 = *(const uint4*)(Btl + b_src + 8);
    uint4 rbl2 = *(const uint4*)(Btl + b_src + 16);
    uint4 rbl3 = *(const uint4*)(Btl + b_src + 24);

    for (int k0 = 0; k0 < 2048; k0 += 32) {
        __syncthreads();
        *(uint4*)&sAh[am * 40 + aseg]     = rah0;
        *(uint4*)&sAh[am * 40 + aseg + 8] = rah1;
        *(uint4*)&sAl[am * 40 + aseg]     = ral0;
        *(uint4*)&sAl[am * 40 + aseg + 8] = ral1;
        *(uint4*)&sBh[tid * 40]      = rbh0;
        *(uint4*)&sBh[tid * 40 + 8]  = rbh1;
        *(uint4*)&sBh[tid * 40 + 16] = rbh2;
        *(uint4*)&sBh[tid * 40 + 24] = rbh3;
        *(uint4*)&sBl[tid * 40]      = rbl0;
        *(uint4*)&sBl[tid * 40 + 8]  = rbl1;
        *(uint4*)&sBl[tid * 40 + 16] = rbl2;
        *(uint4*)&sBl[tid * 40 + 24] = rbl3;
        __syncthreads();

        if (k0 + 32 < 2048) {
            const int kn = k0 + 32;
            rah0 = *(const uint4*)(Ahi + a_src + kn);
            rah1 = *(const uint4*)(Ahi + a_src + kn + 8);
            ral0 = *(const uint4*)(Alo + a_src + kn);
            ral1 = *(const uint4*)(Alo + a_src + kn + 8);
            rbh0 = *(const uint4*)(Bth + b_src + kn);
            rbh1 = *(const uint4*)(Bth + b_src + kn + 8);
            rbh2 = *(const uint4*)(Bth + b_src + kn + 16);
            rbh3 = *(const uint4*)(Bth + b_src + kn + 24);
            rbl0 = *(const uint4*)(Btl + b_src + kn);
            rbl1 = *(const uint4*)(Btl + b_src + kn + 8);
            rbl2 = *(const uint4*)(Btl + b_src + kn + 16);
            rbl3 = *(const uint4*)(Btl + b_src + kn + 24);
        }

#pragma unroll
        for (int ks = 0; ks < 2; ks++) {
            unsigned bh[4][4], bl[4][4];
#pragma unroll
            for (int p = 0; p < 4; p++) {
                unsigned addr = ((unsigned)((wn0 + p * 16 + b_r) * 40 + ks * 16 + b_k)) * 2;
                ldm4(bh[p], baseBh + addr);
                ldm4(bl[p], baseBl + addr);
            }
#pragma unroll
            for (int mi = 0; mi < 2; mi++) {
                unsigned ah[4], al[4];
                unsigned addr = ((unsigned)((wm0 + mi * 16 + a_r) * 40 + ks * 16 + a_k)) * 2;
                ldm4(ah, baseAh + addr);
                ldm4(al, baseAl + addr);
#pragma unroll
                for (int nj = 0; nj < 8; nj++) {
                    unsigned b0h = bh[nj >> 1][(nj & 1) * 2];
                    unsigned b1h = bh[nj >> 1][(nj & 1) * 2 + 1];
                    unsigned b0l = bl[nj >> 1][(nj & 1) * 2];
                    unsigned b1l = bl[nj >> 1][(nj & 1) * 2 + 1];
                    mma16816(acc[mi][nj], ah, b0h, b1h);
                    mma16816(acc[mi][nj], ah, b0l, b1l);
                    mma16816(acc[mi][nj], al, b0h, b1h);
                }
            }
        }
    }

    const int g = lane >> 2, tc = (lane & 3) * 2;
#pragma unroll
    for (int mi = 0; mi < 2; mi++)
#pragma unroll
        for (int nj = 0; nj < 8; nj++) {
            int row = m0 + wm0 + 16 * mi + g;
            int col = n0 + wn0 + 8 * nj + tc;
            *(float2*)&C[(size_t)row * 2048 + col] =
                make_float2(acc[mi][nj][0], acc[mi][nj][1]);
            *(float2*)&C[(size_t)(row + 8) * 2048 + col] =
                make_float2(acc[mi][nj][2], acc[mi][nj][3]);
        }
}

__global__ void __launch_bounds__(128) qkv_tensor_kernel() {
    const int mat = blockIdx.z;
    const __nv_bfloat16* bh = g_wthi + (size_t)mat * WELEM;
    const __nv_bfloat16* bl = g_wtlo + (size_t)mat * WELEM;
    float* C = (mat == 0) ? g_Q0 : (mat == 1) ? g_K0 : g_V0;
    tensor_gemm_tile(g_xhi, g_xlo, bh, bl, C, blockIdx.y * 64, blockIdx.x * 128);
}

__global__ void __launch_bounds__(128) out_tensor_kernel(float* __restrict__ out) {
    tensor_gemm_tile(g_onhi, g_onlo, g_wthi + (size_t)3 * WELEM, g_wtlo + (size_t)3 * WELEM,
                     out, blockIdx.y * 64, blockIdx.x * 128);
}

// ---------------- prep: conv(4)+silu+l2norm ----------------
__device__ __forceinline__ void conv_silu_l2(const float* __restrict__ src,
                                             const float* __restrict__ cw,
                                             float* __restrict__ dst,
                                             int t, int tid) {
    const int c0 = tid * 8;
    float wv[8][4];
#pragma unroll
    for (int e = 0; e < 8; e++) {
        float4 f = *(const float4*)&cw[(c0 + e) * 4];
        wv[e][0] = f.x; wv[e][1] = f.y; wv[e][2] = f.z; wv[e][3] = f.w;
    }
    float y[8];
#pragma unroll
    for (int e = 0; e < 8; e++) y[e] = 0.f;
#pragma unroll
    for (int i = 0; i < 4; i++) {
        int ts = t + i - 3;
        if (ts >= 0) {
            float4 xa = *(const float4*)&src[ts * HID + c0];
            float4 xb = *(const float4*)&src[ts * HID + c0 + 4];
            float xv[8] = {xa.x, xa.y, xa.z, xa.w, xb.x, xb.y, xb.z, xb.w};
#pragma unroll
            for (int e = 0; e < 8; e++) y[e] += xv[e] * wv[e][i];
        }
    }
#pragma unroll
    for (int e = 0; e < 8; e++) {
        float s = 1.f / (1.f + expf(-y[e]));
        y[e] *= s;
    }
    float ss = 0.f;
#pragma unroll
    for (int e = 0; e < 8; e++) ss += y[e] * y[e];
#pragma unroll
    for (int off = 1; off <= 8; off <<= 1) ss += __shfl_xor_sync(0xffffffffu, ss, off);
    float sc = rsqrtf(ss + 1e-6f);
    *(float4*)&dst[t * HID + c0] = make_float4(y[0] * sc, y[1] * sc, y[2] * sc, y[3] * sc);
    *(float4*)&dst[t * HID + c0 + 4] = make_float4(y[4] * sc, y[5] * sc, y[6] * sc, y[7] * sc);
}

__global__ void __launch_bounds__(256) prep_kernel(const float* __restrict__ cwq,
                                                   const float* __restrict__ cwk) {
    const int t = blockIdx.x;
    const int tid = threadIdx.x;
    conv_silu_l2(g_Q0, cwq, g_qn, t, tid);
    conv_silu_l2(g_K0, cwk, g_kn, t, tid);
}

// ---------------- state scan: time-blocked staging ----------------
__global__ void __launch_bounds__(256) scan_kernel() {
    const int h = blockIdx.y;
    const int i0 = blockIdx.x * 8;
    const int tid = threadIdx.x;
    __shared__ float ds[T_LEN], bs[T_LEN];
    __shared__ __align__(16) float ks[SCHUNK][DHEAD], vs[SCHUNK][DHEAD];
    ds[tid] = g_decay[tid * NHEAD + h];
    bs[tid] = g_beta[tid * NHEAD + h];
    const int row = i0 + (tid >> 5);
    const int j0 = (tid & 31) * 4;
    const int ls = tid >> 4;
    const int lc = (tid & 15) * 8;
    float kk0 = 0, kk1 = 0, kk2 = 0, kk3 = 0;
    float kv0 = 0, kv1 = 0, kv2 = 0, kv3 = 0;

    for (int tb = 0; tb < T_LEN; tb += SCHUNK) {
        __syncthreads();
        {
            const float* kp = &g_kn[(tb + ls) * HID + h * DHEAD + lc];
            const float* vp = &g_V0[(tb + ls) * HID + h * DHEAD + lc];
            *(float4*)&ks[ls][lc]     = *(const float4*)&kp[0];
            *(float4*)&ks[ls][lc + 4] = *(const float4*)&kp[4];
            *(float4*)&vs[ls][lc]     = *(const float4*)&vp[0];
            *(float4*)&vs[ls][lc + 4] = *(const float4*)&vp[4];
        }
        __syncthreads();
#pragma unroll
        for (int s = 0; s < SCHUNK; s++) {
            const int t = tb + s;
            const float d = ds[t], b = bs[t];
            const float kr = ks[s][row];
            float4 kj = *(const float4*)&ks[s][j0];
            float4 vj = *(const float4*)&vs[s][j0];
            const float bk = b * kr;
            kk0 = kk0 * d + bk * kj.x; kk1 = kk1 * d + bk * kj.y;
            kk2 = kk2 * d + bk * kj.z; kk3 = kk3 * d + bk * kj.w;
            kv0 = kv0 * d + bk * vj.x; kv1 = kv1 * d + bk * vj.y;
            kv2 = kv2 * d + bk * vj.z; kv3 = kv3 * d + bk * vj.w;
            if ((s & (CHUNK - 1)) == CHUNK - 1) {
                const int slot = t / CHUNK;
                size_t base = (((size_t)slot * NHEAD + h) << 14) + (size_t)row * DHEAD + j0;
                *(float4*)&g_hkk_ck[base] = make_float4(kk0, kk1, kk2, kk3);
                *(float4*)&g_hkv_ck[base] = make_float4(kv0, kv1, kv2, kv3);
            }
        }
    }
}

// ---------------- block reduce (shfl tree + parity buffer) ----------------
__device__ __forceinline__ float blockReduce128(float v, int pb) {
    __shared__ float red[2][4];
#pragma unroll
    for (int off = 16; off > 0; off >>= 1) v += __shfl_xor_sync(0xffffffffu, v, off);
    const int wp = threadIdx.x >> 5;
    if ((threadIdx.x & 31) == 0) red[pb][wp] = v;
    __syncthreads();
    return red[pb][0] + red[pb][1] + red[pb][2] + red[pb][3];
}

// ---------------- merged CG solve: 2-sync iteration via Ap recursion ----------------
// matvec on the shared vector ps; loc = this thread's element of that vector
#define MATVEC(OUTV, LOC)                                                          \
    {                                                                              \
        u64 aA = 0ull, aB = 0ull, aC = 0ull, aD = 0ull;                            \
        _Pragma("unroll")                                                          \
        for (int i = 0; i < 32; i += 2) {                                          \
            ulonglong2 p0 = *(const ulonglong2*)&ps[i * 4];                        \
            ulonglong2 p1 = *(const ulonglong2*)&ps[i * 4 + 4];                    \
            ffma2(aA, B2[i].x, p0.x);     ffma2(aB, B2[i].y, p0.y);                \
            ffma2(aC, B2[i + 1].x, p1.x); ffma2(aD, B2[i + 1].y, p1.y);            \
        }                                                                          \
        float2 fa = unpk(aA), fb = unpk(aB), fc = unpk(aC), fd = unpk(aD);         \
        float bp_ = ((fa.x + fa.y) + (fb.x + fb.y)) + ((fc.x + fc.y) + (fd.x + fd.y)); \
        OUTV = Pt * bp_ + lam * (LOC);                                             \
    }

__global__ void __launch_bounds__(128, 4) solve_kernel(const float* __restrict__ onw,
                                                       const float* __restrict__ lp) {
    const int h = blockIdx.x;
    const int chunk = blockIdx.y;
    const int cs = chunk * CHUNK;
    const int slot = chunk - 1;
    const int r = threadIdx.x;

    __shared__ __align__(16) float ks[CHUNK][DHEAD];
    __shared__ __align__(16) float vs[CHUNK][DHEAD];
    __shared__ __align__(16) float ps[DHEAD];
    __shared__ float dsh[CHUNK], bsh[CHUNK], Pp[CHUNK], cf[CHUNK], gsh[CHUNK];

    {
        const int row = r >> 4;
        const int c0 = (r & 15) * 8;
        const float* kp = &g_kn[(cs + row) * HID + h * DHEAD + c0];
        const float* vp = &g_V0[(cs + row) * HID + h * DHEAD + c0];
        *(float4*)&ks[row][c0]     = *(const float4*)&kp[0];
        *(float4*)&ks[row][c0 + 4] = *(const float4*)&kp[4];
        *(float4*)&vs[row][c0]     = *(const float4*)&vp[0];
        *(float4*)&vs[row][c0 + 4] = *(const float4*)&vp[4];
        if (r < CHUNK) {
            dsh[r] = g_decay[(cs + r) * NHEAD + h];
            bsh[r] = g_beta[(cs + r) * NHEAD + h];
        }
    }
    __syncthreads();
    if (r == 0) {
        float run = 1.f;
#pragma unroll
        for (int s = 0; s < CHUNK; s++) {
            run *= dsh[s];
            Pp[s] = run;
            cf[s] = bsh[s] / run;
        }
    }

    float lam;
    {
        float v = lp[h * DHEAD + r];
        lam = ((v > 20.f) ? v : log1pf(expf(v))) + 0.25f;
    }

    ulonglong2 B2[32];
    if (slot >= 0) {
        const float* base = g_hkk_ck + (((size_t)slot * NHEAD + h) << 14) + (size_t)r * DHEAD;
#pragma unroll
        for (int i = 0; i < 32; i++) B2[i] = *(const ulonglong2*)&base[i * 4];
    } else {
#pragma unroll
        for (int i = 0; i < 32; i++) { B2[i].x = 0ull; B2[i].y = 0ull; }
    }
    const float* kvb = (slot >= 0)
        ? g_hkv_ck + (((size_t)slot * NHEAD + h) << 14) + r : (const float*)0;
    __syncthreads();

    int par = 0;
    for (int jt = 0; jt < CHUNK; jt++) {
        const int t = cs + jt;
        {
            u64 w = splat2(cf[jt] * ks[jt][r]);
            const u64* kkp = (const u64*)&ks[jt][0];
#pragma unroll
            for (int i = 0; i < 32; i++) {
                ffma2(B2[i].x, w, kkp[2 * i]);
                ffma2(B2[i].y, w, kkp[2 * i + 1]);
            }
        }
        const float Pt = Pp[jt];
        const float b = g_qn[t * HID + h * DHEAD + r];

        float xx = 0.f, rr = b, p = b;
        ps[r] = b;
        float rs = blockReduce128(b * b, par); par ^= 1;   // sync also publishes ps=b
        const float rs_stop = 1e-8f * rs;

        float Ap;
        MATVEC(Ap, p);   // initial Ap = A*b (reads ps=b)

        for (int it = 0; it < 30; it++) {
            float pap = blockReduce128(p * Ap, par); par ^= 1;  // sync #1 (fences ps reads)
            float alpha = rs / (pap + 1e-12f);
            xx += alpha * p;
            rr -= alpha * Ap;
            ps[r] = rr;                                         // publish residual
            float rsn = blockReduce128(rr * rr, par); par ^= 1; // sync #2 (publishes ps)
            if (rsn < rs_stop) break;
            float bet = rsn / (rs + 1e-12f);
            p = rr + bet * p;
            float Ar;
            MATVEC(Ar, rr);                                     // reads ps=rr
            Ap = Ar + bet * Ap;                                 // exact: A(r+bet*p)=Ar+bet*Ap
            rs = rsn;
        }

        ps[r] = xx;
        __syncthreads();
        {
            const int sIdx = r >> 4;
            const int part = r & 15;
            float pg = 0.f;
            const int e0 = part * 8;
#pragma unroll
            for (int e = 0; e < 8; e++) pg += ks[sIdx][e0 + e] * ps[e0 + e];
#pragma unroll
            for (int off = 1; off <= 8; off <<= 1) pg += __shfl_xor_sync(0xffffffffu, pg, off);
            if (part == 0)
                gsh[sIdx] = (sIdx <= jt) ? pg * cf[sIdx] * Pt : 0.f;
        }
        __syncthreads();

        float o = 0.f;
        if (slot >= 0) {
            float o0 = 0, o1 = 0, o2 = 0, o3 = 0;
#pragma unroll
            for (int k2 = 0; k2 < DHEAD; k2 += 4) {
                o0 += ps[k2]     * kvb[(size_t)k2 * DHEAD];
                o1 += ps[k2 + 1] * kvb[(size_t)(k2 + 1) * DHEAD];
                o2 += ps[k2 + 2] * kvb[(size_t)(k2 + 2) * DHEAD];
                o3 += ps[k2 + 3] * kvb[(size_t)(k2 + 3) * DHEAD];
            }
            o = Pt * ((o0 + o1) + (o2 + o3));
        }
#pragma unroll
        for (int s = 0; s < CHUNK; s++) o += gsh[s] * vs[s][r];

        float ms = blockReduce128(o * o, par) * (1.0f / 128.0f); par ^= 1;
        float sc = rsqrtf(ms + 1e-5f);
        float val = o * sc * onw[r];
        __nv_bfloat16 hb, lb;
        splitbf(val, hb, lb);
        g_onhi[t * HID + h * DHEAD + r] = hb;
        g_onlo[t * HID + h * DHEAD + r] = lb;
        __syncthreads();
    }
}

// ---------------- launch ----------------
extern "C" void kernel_launch(void* const* d_in, const int* in_sizes, int n_in,
                              void* d_out, int out_size) {
    const float* x    = (const float*)d_in[0];
    const float* Wq   = (const float*)d_in[1];
    const float* Wk   = (const float*)d_in[2];
    const float* Wv   = (const float*)d_in[3];
    const float* Wa   = (const float*)d_in[4];
    const float* ba   = (const float*)d_in[5];
    const float* Wb   = (const float*)d_in[6];
    const float* bb   = (const float*)d_in[7];
    const float* cwq  = (const float*)d_in[8];
    const float* cwk  = (const float*)d_in[9];
    const float* lp   = (const float*)d_in[10];
    const float* onw  = (const float*)d_in[11];
    const float* Wo   = (const float*)d_in[12];
    float* out = (float*)d_out;

    head_kernel<<<16896, 256>>>(x, Wq, Wk, Wv, Wo, Wa, ba, Wb, bb);
    qkv_tensor_kernel<<<dim3(16, 4, 3), 128>>>();
    prep_kernel<<<256, 256>>>(cwq, cwk);
    scan_kernel<<<dim3(16, NHEAD), 256>>>();
    solve_kernel<<<dim3(NHEAD, NSLOT), 128>>>(onw, lp);
    out_tensor_kernel<<<dim3(16, 4), 128>>>(out);
}

// round 17
// speedup vs baseline: 2.4519x; 1.0008x over previous
#include <cuda_runtime.h>
#include <cuda_bf16.h>
#include <math.h>

#define T_LEN 256
#define HID   2048
#define NHEAD 16
#define DHEAD 128
#define KD    2048
#define CHUNK 8
#define NSLOT (T_LEN / CHUNK)
#define SCHUNK 16
#define WELEM (KD * HID)

// ---------------- scratch ----------------
__device__ float g_Q0[T_LEN * KD];
__device__ float g_K0[T_LEN * KD];
__device__ float g_V0[T_LEN * KD];
__device__ float g_qn[T_LEN * KD];
__device__ float g_kn[T_LEN * KD];
__device__ float g_beta[T_LEN * NHEAD];
__device__ float g_decay[T_LEN * NHEAD];
__device__ float g_hkk_ck[(size_t)NSLOT * NHEAD * DHEAD * DHEAD];
__device__ float g_hkv_ck[(size_t)NSLOT * NHEAD * DHEAD * DHEAD];
__device__ __nv_bfloat16 g_xhi[T_LEN * HID];
__device__ __nv_bfloat16 g_xlo[T_LEN * HID];
__device__ __nv_bfloat16 g_onhi[T_LEN * KD];
__device__ __nv_bfloat16 g_onlo[T_LEN * KD];
__device__ __nv_bfloat16 g_wthi[(size_t)4 * WELEM];
__device__ __nv_bfloat16 g_wtlo[(size_t)4 * WELEM];

// ---------------- f32x2 helpers ----------------
typedef unsigned long long u64;
__device__ __forceinline__ u64 splat2(float a) {
    u64 d; unsigned u = __float_as_uint(a);
    asm("mov.b64 %0, {%1, %1};" : "=l"(d) : "r"(u));
    return d;
}
__device__ __forceinline__ void ffma2(u64& d, u64 a, u64 b) {
    asm("fma.rn.f32x2 %0, %1, %2, %0;" : "+l"(d) : "l"(a), "l"(b));
}
__device__ __forceinline__ float2 unpk(u64 v) {
    unsigned lo, hi;
    asm("mov.b64 {%0, %1}, %2;" : "=r"(lo), "=r"(hi) : "l"(v));
    return make_float2(__uint_as_float(lo), __uint_as_float(hi));
}

// ---------------- tensor-core helpers ----------------
__device__ __forceinline__ unsigned smem_u32(const void* p) {
    unsigned a;
    asm("{ .reg .u64 t; cvta.to.shared.u64 t, %1; cvt.u32.u64 %0, t; }" : "=r"(a) : "l"(p));
    return a;
}
__device__ __forceinline__ void ldm4(unsigned (&r)[4], unsigned addr) {
    asm volatile("ldmatrix.sync.aligned.m8n8.x4.shared.b16 {%0,%1,%2,%3}, [%4];"
        : "=r"(r[0]), "=r"(r[1]), "=r"(r[2]), "=r"(r[3]) : "r"(addr));
}
__device__ __forceinline__ void mma16816(float (&c)[4], const unsigned (&a)[4],
                                         unsigned b0, unsigned b1) {
    asm volatile("mma.sync.aligned.m16n8k16.row.col.f32.bf16.bf16.f32 "
        "{%0,%1,%2,%3}, {%4,%5,%6,%7}, {%8,%9}, {%0,%1,%2,%3};"
        : "+f"(c[0]), "+f"(c[1]), "+f"(c[2]), "+f"(c[3])
        : "r"(a[0]), "r"(a[1]), "r"(a[2]), "r"(a[3]), "r"(b0), "r"(b1));
}
__device__ __forceinline__ void splitbf(float x, __nv_bfloat16& h, __nv_bfloat16& l) {
    h = __float2bfloat16_rn(x);
    l = __float2bfloat16_rn(x - __bfloat162float(h));
}
__device__ __forceinline__ unsigned pk2(__nv_bfloat16 a, __nv_bfloat16 b) {
    __nv_bfloat162 t = __halves2bfloat162(a, b);
    return *reinterpret_cast<unsigned*>(&t);
}

// ---------------- head kernel: bg + convert_x + convert_wt fused ----------------
__global__ void __launch_bounds__(256) head_kernel(const float* __restrict__ x,
                                                   const float* __restrict__ W0,
                                                   const float* __restrict__ W1,
                                                   const float* __restrict__ W2,
                                                   const float* __restrict__ W3,
                                                   const float* __restrict__ Wa,
                                                   const float* __restrict__ ba,
                                                   const float* __restrict__ Wb,
                                                   const float* __restrict__ bb) {
    const int b = blockIdx.x;
    const int tid = threadIdx.x;
    if (b < 256) {
        const int t = b;
        __shared__ __align__(16) float xs[HID];
        __shared__ float red[8][32];
        {
            const int i = tid * 8;
            *(float4*)&xs[i]     = *(const float4*)&x[t * HID + i];
            *(float4*)&xs[i + 4] = *(const float4*)&x[t * HID + i + 4];
        }
        __syncthreads();
        const int col = tid & 31;
        const int kg = tid >> 5;
        const float* Wsel = (col < 16) ? Wa : Wb;
        const int c = col & 15;
        const int kb = kg * 256;
        float a0 = 0.f, a1 = 0.f, a2 = 0.f, a3 = 0.f;
#pragma unroll 16
        for (int k = 0; k < 256; k += 4) {
            a0 += xs[kb + k]     * Wsel[(kb + k) * NHEAD + c];
            a1 += xs[kb + k + 1] * Wsel[(kb + k + 1) * NHEAD + c];
            a2 += xs[kb + k + 2] * Wsel[(kb + k + 2) * NHEAD + c];
            a3 += xs[kb + k + 3] * Wsel[(kb + k + 3) * NHEAD + c];
        }
        red[kg][col] = (a0 + a1) + (a2 + a3);
        __syncthreads();
        if (kg == 0) {
            float v = 0.f;
#pragma unroll
            for (int g = 0; g < 8; g++) v += red[g][col];
            if (col < 16) {
                g_decay[t * NHEAD + c] = 1.f / (1.f + expf(-(v + ba[c])));
            } else {
                g_beta[t * NHEAD + c] = 1.f / (1.f + expf(-(v + bb[c])));
            }
        }
        return;
    }
    if (b < 512) {
        const int i = ((b - 256) * 256 + tid) * 8;
        float4 a = *(const float4*)(x + i);
        float4 bb4 = *(const float4*)(x + i + 4);
        float v[8] = {a.x, a.y, a.z, a.w, bb4.x, bb4.y, bb4.z, bb4.w};
        __nv_bfloat16 h[8], l[8];
#pragma unroll
        for (int e = 0; e < 8; e++) splitbf(v[e], h[e], l[e]);
        uint4 ph = make_uint4(pk2(h[0], h[1]), pk2(h[2], h[3]), pk2(h[4], h[5]), pk2(h[6], h[7]));
        uint4 pl = make_uint4(pk2(l[0], l[1]), pk2(l[2], l[3]), pk2(l[4], l[5]), pk2(l[6], l[7]));
        *(uint4*)(g_xhi + i) = ph;
        *(uint4*)(g_xlo + i) = pl;
        return;
    }
    __shared__ float T[32][33];
    const int bp = b - 512;
    const int mat = bp >> 12;
    const int bx = bp & 4095;
    const float* W = (mat == 0) ? W0 : (mat == 1) ? W1 : (mat == 2) ? W2 : W3;
    __nv_bfloat16* oh = g_wthi + (size_t)mat * WELEM;
    __nv_bfloat16* ol = g_wtlo + (size_t)mat * WELEM;
    const int k0 = (bx & 63) * 32;
    const int n0 = (bx >> 6) * 32;
    const int r = tid >> 5, c = tid & 31;
#pragma unroll
    for (int p = 0; p < 4; p++) {
        int k = k0 + p * 8 + r;
        T[c][p * 8 + r] = W[(size_t)k * 2048 + n0 + c];
    }
    __syncthreads();
    const int nl = tid >> 3, kc = (tid & 7) * 4;
    float v0 = T[nl][kc], v1 = T[nl][kc + 1], v2 = T[nl][kc + 2], v3 = T[nl][kc + 3];
    __nv_bfloat16 h0, h1, h2, h3, l0, l1, l2, l3;
    splitbf(v0, h0, l0); splitbf(v1, h1, l1);
    splitbf(v2, h2, l2); splitbf(v3, h3, l3);
    uint2 ph = make_uint2(pk2(h0, h1), pk2(h2, h3));
    uint2 pl = make_uint2(pk2(l0, l1), pk2(l2, l3));
    size_t off = (size_t)(n0 + nl) * 2048 + k0 + kc;
    *(uint2*)(oh + off) = ph;
    *(uint2*)(ol + off) = pl;
}

// ---------------- tensor GEMM tile (software-pipelined) ----------------
__device__ __forceinline__ void tensor_gemm_tile(const __nv_bfloat16* __restrict__ Ahi,
                                                 const __nv_bfloat16* __restrict__ Alo,
                                                 const __nv_bfloat16* __restrict__ Bth,
                                                 const __nv_bfloat16* __restrict__ Btl,
                                                 float* __restrict__ C,
                                                 int m0, int n0) {
    __shared__ __align__(16) __nv_bfloat16 sAh[64 * 40];
    __shared__ __align__(16) __nv_bfloat16 sAl[64 * 40];
    __shared__ __align__(16) __nv_bfloat16 sBh[128 * 40];
    __shared__ __align__(16) __nv_bfloat16 sBl[128 * 40];

    const int tid = threadIdx.x;
    const int lane = tid & 31;
    const int warp = tid >> 5;
    const int wm0 = (warp & 1) * 32;
    const int wn0 = (warp >> 1) * 64;

    float acc[2][8][4];
#pragma unroll
    for (int i = 0; i < 2; i++)
#pragma unroll
        for (int j = 0; j < 8; j++)
#pragma unroll
            for (int q = 0; q < 4; q++) acc[i][j][q] = 0.f;

    const unsigned baseAh = smem_u32(sAh), baseAl = smem_u32(sAl);
    const unsigned baseBh = smem_u32(sBh), baseBl = smem_u32(sBl);

    const int a_k = (lane >> 4) * 8;
    const int b_k = ((lane >> 3) & 1) * 8;
    const int a_r = lane & 15;
    const int b_r = ((lane >> 4) & 1) * 8 + (lane & 7);

    const int am = tid >> 1, aseg = (tid & 1) * 16;
    const size_t a_src = (size_t)(m0 + am) * 2048 + aseg;
    const size_t b_src = (size_t)(n0 + tid) * 2048;

    uint4 rah0 = *(const uint4*)(Ahi + a_src);
    uint4 rah1 = *(const uint4*)(Ahi + a_src + 8);
    uint4 ral0 = *(const uint4*)(Alo + a_src);
    uint4 ral1 = *(const uint4*)(Alo + a_src + 8);
    uint4 rbh0 = *(const uint4*)(Bth + b_src);
    uint4 rbh1 = *(const uint4*)(Bth + b_src + 8);
    uint4 rbh2 = *(const uint4*)(Bth + b_src + 16);
    uint4 rbh3 = *(const uint4*)(Bth + b_src + 24);
    uint4 rbl0 = *(const uint4*)(Btl + b_src);
    uint4 rbl1 = *(const uint4*)(Btl + b_src + 8);
    uint4 rbl2 = *(const uint4*)(Btl + b_src + 16);
    uint4 rbl3 = *(const uint4*)(Btl + b_src + 24);

    for (int k0 = 0; k0 < 2048; k0 += 32) {
        __syncthreads();
        *(uint4*)&sAh[am * 40 + aseg]     = rah0;
        *(uint4*)&sAh[am * 40 + aseg + 8] = rah1;
        *(uint4*)&sAl[am * 40 + aseg]     = ral0;
        *(uint4*)&sAl[am * 40 + aseg + 8] = ral1;
        *(uint4*)&sBh[tid * 40]      = rbh0;
        *(uint4*)&sBh[tid * 40 + 8]  = rbh1;
        *(uint4*)&sBh[tid * 40 + 16] = rbh2;
        *(uint4*)&sBh[tid * 40 + 24] = rbh3;
        *(uint4*)&sBl[tid * 40]      = rbl0;
        *(uint4*)&sBl[tid * 40 + 8]  = rbl1;
        *(uint4*)&sBl[tid * 40 + 16] = rbl2;
        *(uint4*)&sBl[tid * 40 + 24] = rbl3;
        __syncthreads();

        if (k0 + 32 < 2048) {
            const int kn = k0 + 32;
            rah0 = *(const uint4*)(Ahi + a_src + kn);
            rah1 = *(const uint4*)(Ahi + a_src + kn + 8);
            ral0 = *(const uint4*)(Alo + a_src + kn);
            ral1 = *(const uint4*)(Alo + a_src + kn + 8);
            rbh0 = *(const uint4*)(Bth + b_src + kn);
            rbh1 = *(const uint4*)(Bth + b_src + kn + 8);
            rbh2 = *(const uint4*)(Bth + b_src + kn + 16);
            rbh3 = *(const uint4*)(Bth + b_src + kn + 24);
            rbl0 = *(const uint4*)(Btl + b_src + kn);
            rbl1 = *(const uint4*)(Btl + b_src + kn + 8);
            rbl2 = *(const uint4*)(Btl + b_src + kn + 16);
            rbl3 = *(const uint4*)(Btl + b_src + kn + 24);
        }

#pragma unroll
        for (int ks = 0; ks < 2; ks++) {
            unsigned bh[4][4], bl[4][4];
#pragma unroll
            for (int p = 0; p < 4; p++) {
                unsigned addr = ((unsigned)((wn0 + p * 16 + b_r) * 40 + ks * 16 + b_k)) * 2;
                ldm4(bh[p], baseBh + addr);
                ldm4(bl[p], baseBl + addr);
            }
#pragma unroll
            for (int mi = 0; mi < 2; mi++) {
                unsigned ah[4], al[4];
                unsigned addr = ((unsigned)((wm0 + mi * 16 + a_r) * 40 + ks * 16 + a_k)) * 2;
                ldm4(ah, baseAh + addr);
                ldm4(al, baseAl + addr);
#pragma unroll
                for (int nj = 0; nj < 8; nj++) {
                    unsigned b0h = bh[nj >> 1][(nj & 1) * 2];
                    unsigned b1h = bh[nj >> 1][(nj & 1) * 2 + 1];
                    unsigned b0l = bl[nj >> 1][(nj & 1) * 2];
                    unsigned b1l = bl[nj >> 1][(nj & 1) * 2 + 1];
                    mma16816(acc[mi][nj], ah, b0h, b1h);
                    mma16816(acc[mi][nj], ah, b0l, b1l);
                    mma16816(acc[mi][nj], al, b0h, b1h);
                }
            }
        }
    }

    const int g = lane >> 2, tc = (lane & 3) * 2;
#pragma unroll
    for (int mi = 0; mi < 2; mi++)
#pragma unroll
        for (int nj = 0; nj < 8; nj++) {
            int row = m0 + wm0 + 16 * mi + g;
            int col = n0 + wn0 + 8 * nj + tc;
            *(float2*)&C[(size_t)row * 2048 + col] =
                make_float2(acc[mi][nj][0], acc[mi][nj][1]);
            *(float2*)&C[(size_t)(row + 8) * 2048 + col] =
                make_float2(acc[mi][nj][2], acc[mi][nj][3]);
        }
}

__global__ void __launch_bounds__(128) qkv_tensor_kernel() {
    const int mat = blockIdx.z;
    const __nv_bfloat16* bh = g_wthi + (size_t)mat * WELEM;
    const __nv_bfloat16* bl = g_wtlo + (size_t)mat * WELEM;
    float* C = (mat == 0) ? g_Q0 : (mat == 1) ? g_K0 : g_V0;
    tensor_gemm_tile(g_xhi, g_xlo, bh, bl, C, blockIdx.y * 64, blockIdx.x * 128);
}

__global__ void __launch_bounds__(128) out_tensor_kernel(float* __restrict__ out) {
    tensor_gemm_tile(g_onhi, g_onlo, g_wthi + (size_t)3 * WELEM, g_wtlo + (size_t)3 * WELEM,
                     out, blockIdx.y * 64, blockIdx.x * 128);
}

// ---------------- prep: conv(4)+silu+l2norm ----------------
__device__ __forceinline__ void conv_silu_l2(const float* __restrict__ src,
                                             const float* __restrict__ cw,
                                             float* __restrict__ dst,
                                             int t, int tid) {
    const int c0 = tid * 8;
    float wv[8][4];
#pragma unroll
    for (int e = 0; e < 8; e++) {
        float4 f = *(const float4*)&cw[(c0 + e) * 4];
        wv[e][0] = f.x; wv[e][1] = f.y; wv[e][2] = f.z; wv[e][3] = f.w;
    }
    float y[8];
#pragma unroll
    for (int e = 0; e < 8; e++) y[e] = 0.f;
#pragma unroll
    for (int i = 0; i < 4; i++) {
        int ts = t + i - 3;
        if (ts >= 0) {
            float4 xa = *(const float4*)&src[ts * HID + c0];
            float4 xb = *(const float4*)&src[ts * HID + c0 + 4];
            float xv[8] = {xa.x, xa.y, xa.z, xa.w, xb.x, xb.y, xb.z, xb.w};
#pragma unroll
            for (int e = 0; e < 8; e++) y[e] += xv[e] * wv[e][i];
        }
    }
#pragma unroll
    for (int e = 0; e < 8; e++) {
        float s = 1.f / (1.f + expf(-y[e]));
        y[e] *= s;
    }
    float ss = 0.f;
#pragma unroll
    for (int e = 0; e < 8; e++) ss += y[e] * y[e];
#pragma unroll
    for (int off = 1; off <= 8; off <<= 1) ss += __shfl_xor_sync(0xffffffffu, ss, off);
    float sc = rsqrtf(ss + 1e-6f);
    *(float4*)&dst[t * HID + c0] = make_float4(y[0] * sc, y[1] * sc, y[2] * sc, y[3] * sc);
    *(float4*)&dst[t * HID + c0 + 4] = make_float4(y[4] * sc, y[5] * sc, y[6] * sc, y[7] * sc);
}

__global__ void __launch_bounds__(256) prep_kernel(const float* __restrict__ cwq,
                                                   const float* __restrict__ cwk) {
    const int t = blockIdx.x;
    const int tid = threadIdx.x;
    conv_silu_l2(g_Q0, cwq, g_qn, t, tid);
    conv_silu_l2(g_K0, cwk, g_kn, t, tid);
}

// ---------------- state scan: time-blocked + software-pipelined staging ----------------
__global__ void __launch_bounds__(256) scan_kernel() {
    const int h = blockIdx.y;
    const int i0 = blockIdx.x * 8;
    const int tid = threadIdx.x;
    __shared__ float ds[T_LEN], bs[T_LEN];
    __shared__ __align__(16) float ks[SCHUNK][DHEAD], vs[SCHUNK][DHEAD];
    ds[tid] = g_decay[tid * NHEAD + h];
    bs[tid] = g_beta[tid * NHEAD + h];
    const int row = i0 + (tid >> 5);
    const int j0 = (tid & 31) * 4;
    const int ls = tid >> 4;
    const int lc = (tid & 15) * 8;
    float kk0 = 0, kk1 = 0, kk2 = 0, kk3 = 0;
    float kv0 = 0, kv1 = 0, kv2 = 0, kv3 = 0;

    // prefetch phase 0
    float4 rk0 = *(const float4*)&g_kn[ls * HID + h * DHEAD + lc];
    float4 rk1 = *(const float4*)&g_kn[ls * HID + h * DHEAD + lc + 4];
    float4 rv0 = *(const float4*)&g_V0[ls * HID + h * DHEAD + lc];
    float4 rv1 = *(const float4*)&g_V0[ls * HID + h * DHEAD + lc + 4];

    for (int tb = 0; tb < T_LEN; tb += SCHUNK) {
        __syncthreads();                 // previous phase's smem reads done (also fences ds/bs on iter 0)
        *(float4*)&ks[ls][lc]     = rk0;
        *(float4*)&ks[ls][lc + 4] = rk1;
        *(float4*)&vs[ls][lc]     = rv0;
        *(float4*)&vs[ls][lc + 4] = rv1;
        __syncthreads();                 // tile valid
        if (tb + SCHUNK < T_LEN) {       // issue next phase's loads; consumed after compute
            const float* kp = &g_kn[(tb + SCHUNK + ls) * HID + h * DHEAD + lc];
            const float* vp = &g_V0[(tb + SCHUNK + ls) * HID + h * DHEAD + lc];
            rk0 = *(const float4*)&kp[0];
            rk1 = *(const float4*)&kp[4];
            rv0 = *(const float4*)&vp[0];
            rv1 = *(const float4*)&vp[4];
        }
#pragma unroll
        for (int s = 0; s < SCHUNK; s++) {
            const int t = tb + s;
            const float d = ds[t], b = bs[t];
            const float kr = ks[s][row];
            float4 kj = *(const float4*)&ks[s][j0];
            float4 vj = *(const float4*)&vs[s][j0];
            const float bk = b * kr;
            kk0 = kk0 * d + bk * kj.x; kk1 = kk1 * d + bk * kj.y;
            kk2 = kk2 * d + bk * kj.z; kk3 = kk3 * d + bk * kj.w;
            kv0 = kv0 * d + bk * vj.x; kv1 = kv1 * d + bk * vj.y;
            kv2 = kv2 * d + bk * vj.z; kv3 = kv3 * d + bk * vj.w;
            if ((s & (CHUNK - 1)) == CHUNK - 1) {
                const int slot = t / CHUNK;
                size_t base = (((size_t)slot * NHEAD + h) << 14) + (size_t)row * DHEAD + j0;
                *(float4*)&g_hkk_ck[base] = make_float4(kk0, kk1, kk2, kk3);
                *(float4*)&g_hkv_ck[base] = make_float4(kv0, kv1, kv2, kv3);
            }
        }
    }
}

// ---------------- block reduce (shfl tree + parity buffer) ----------------
__device__ __forceinline__ float blockReduce128(float v, int pb) {
    __shared__ float red[2][4];
#pragma unroll
    for (int off = 16; off > 0; off >>= 1) v += __shfl_xor_sync(0xffffffffu, v, off);
    const int wp = threadIdx.x >> 5;
    if ((threadIdx.x & 31) == 0) red[pb][wp] = v;
    __syncthreads();
    return red[pb][0] + red[pb][1] + red[pb][2] + red[pb][3];
}

// ---------------- merged CG solve: 2-sync iteration via Ap recursion ----------------
#define MATVEC(OUTV, LOC)                                                          \
    {                                                                              \
        u64 aA = 0ull, aB = 0ull, aC = 0ull, aD = 0ull;                            \
        _Pragma("unroll")                                                          \
        for (int i = 0; i < 32; i += 2) {                                          \
            ulonglong2 p0 = *(const ulonglong2*)&ps[i * 4];                        \
            ulonglong2 p1 = *(const ulonglong2*)&ps[i * 4 + 4];                    \
            ffma2(aA, B2[i].x, p0.x);     ffma2(aB, B2[i].y, p0.y);                \
            ffma2(aC, B2[i + 1].x, p1.x); ffma2(aD, B2[i + 1].y, p1.y);            \
        }                                                                          \
        float2 fa = unpk(aA), fb = unpk(aB), fc = unpk(aC), fd = unpk(aD);         \
        float bp_ = ((fa.x + fa.y) + (fb.x + fb.y)) + ((fc.x + fc.y) + (fd.x + fd.y)); \
        OUTV = Pt * bp_ + lam * (LOC);                                             \
    }

__global__ void __launch_bounds__(128, 4) solve_kernel(const float* __restrict__ onw,
                                                       const float* __restrict__ lp) {
    const int h = blockIdx.x;
    const int chunk = blockIdx.y;
    const int cs = chunk * CHUNK;
    const int slot = chunk - 1;
    const int r = threadIdx.x;

    __shared__ __align__(16) float ks[CHUNK][DHEAD];
    __shared__ __align__(16) float vs[CHUNK][DHEAD];
    __shared__ __align__(16) float ps[DHEAD];
    __shared__ float dsh[CHUNK], bsh[CHUNK], Pp[CHUNK], cf[CHUNK], gsh[CHUNK];

    // issue checkpoint load FIRST: latency overlaps staging + setup below
    ulonglong2 B2[32];
    if (slot >= 0) {
        const float* base = g_hkk_ck + (((size_t)slot * NHEAD + h) << 14) + (size_t)r * DHEAD;
#pragma unroll
        for (int i = 0; i < 32; i++) B2[i] = *(const ulonglong2*)&base[i * 4];
    } else {
#pragma unroll
        for (int i = 0; i < 32; i++) { B2[i].x = 0ull; B2[i].y = 0ull; }
    }

    {
        const int row = r >> 4;
        const int c0 = (r & 15) * 8;
        const float* kp = &g_kn[(cs + row) * HID + h * DHEAD + c0];
        const float* vp = &g_V0[(cs + row) * HID + h * DHEAD + c0];
        *(float4*)&ks[row][c0]     = *(const float4*)&kp[0];
        *(float4*)&ks[row][c0 + 4] = *(const float4*)&kp[4];
        *(float4*)&vs[row][c0]     = *(const float4*)&vp[0];
        *(float4*)&vs[row][c0 + 4] = *(const float4*)&vp[4];
        if (r < CHUNK) {
            dsh[r] = g_decay[(cs + r) * NHEAD + h];
            bsh[r] = g_beta[(cs + r) * NHEAD + h];
        }
    }
    __syncthreads();
    if (r == 0) {
        float run = 1.f;
#pragma unroll
        for (int s = 0; s < CHUNK; s++) {
            run *= dsh[s];
            Pp[s] = run;
            cf[s] = bsh[s] / run;
        }
    }

    float lam;
    {
        float v = lp[h * DHEAD + r];
        lam = ((v > 20.f) ? v : log1pf(expf(v))) + 0.25f;
    }
    const float* kvb = (slot >= 0)
        ? g_hkv_ck + (((size_t)slot * NHEAD + h) << 14) + r : (const float*)0;
    __syncthreads();

    int par = 0;
    for (int jt = 0; jt < CHUNK; jt++) {
        const int t = cs + jt;
        {
            u64 w = splat2(cf[jt] * ks[jt][r]);
            const u64* kkp = (const u64*)&ks[jt][0];
#pragma unroll
            for (int i = 0; i < 32; i++) {
                ffma2(B2[i].x, w, kkp[2 * i]);
                ffma2(B2[i].y, w, kkp[2 * i + 1]);
            }
        }
        const float Pt = Pp[jt];
        const float b = g_qn[t * HID + h * DHEAD + r];

        float xx = 0.f, rr = b, p = b;
        ps[r] = b;
        float rs = blockReduce128(b * b, par); par ^= 1;   // sync also publishes ps=b
        const float rs_stop = 1e-8f * rs;

        float Ap;
        MATVEC(Ap, p);   // initial Ap = A*b

        for (int it = 0; it < 30; it++) {
            float pap = blockReduce128(p * Ap, par); par ^= 1;  // sync #1 (fences ps reads)
            float alpha = rs / (pap + 1e-12f);
            xx += alpha * p;
            rr -= alpha * Ap;
            ps[r] = rr;
            float rsn = blockReduce128(rr * rr, par); par ^= 1; // sync #2 (publishes ps)
            if (rsn < rs_stop) break;
            float bet = rsn / (rs + 1e-12f);
            p = rr + bet * p;
            float Ar;
            MATVEC(Ar, rr);
            Ap = Ar + bet * Ap;
            rs = rsn;
        }

        ps[r] = xx;
        __syncthreads();
        {
            const int sIdx = r >> 4;
            const int part = r & 15;
            float pg = 0.f;
            const int e0 = part * 8;
#pragma unroll
            for (int e = 0; e < 8; e++) pg += ks[sIdx][e0 + e] * ps[e0 + e];
#pragma unroll
            for (int off = 1; off <= 8; off <<= 1) pg += __shfl_xor_sync(0xffffffffu, pg, off);
            if (part == 0)
                gsh[sIdx] = (sIdx <= jt) ? pg * cf[sIdx] * Pt : 0.f;
        }
        __syncthreads();

        float o = 0.f;
        if (slot >= 0) {
            float o0 = 0, o1 = 0, o2 = 0, o3 = 0;
#pragma unroll
            for (int k2 = 0; k2 < DHEAD; k2 += 4) {
                o0 += ps[k2]     * kvb[(size_t)k2 * DHEAD];
                o1 += ps[k2 + 1] * kvb[(size_t)(k2 + 1) * DHEAD];
                o2 += ps[k2 + 2] * kvb[(size_t)(k2 + 2) * DHEAD];
                o3 += ps[k2 + 3] * kvb[(size_t)(k2 + 3) * DHEAD];
            }
            o = Pt * ((o0 + o1) + (o2 + o3));
        }
#pragma unroll
        for (int s = 0; s < CHUNK; s++) o += gsh[s] * vs[s][r];

        float ms = blockReduce128(o * o, par) * (1.0f / 128.0f); par ^= 1;
        float sc = rsqrtf(ms + 1e-5f);
        float val = o * sc * onw[r];
        __nv_bfloat16 hb, lb;
        splitbf(val, hb, lb);
        g_onhi[t * HID + h * DHEAD + r] = hb;
        g_onlo[t * HID + h * DHEAD + r] = lb;
        __syncthreads();
    }
}

// ---------------- launch ----------------
extern "C" void kernel_launch(void* const* d_in, const int* in_sizes, int n_in,
                              void* d_out, int out_size) {
    const float* x    = (const float*)d_in[0];
    const float* Wq   = (const float*)d_in[1];
    const float* Wk   = (const float*)d_in[2];
    const float* Wv   = (const float*)d_in[3];
    const float* Wa   = (const float*)d_in[4];
    const float* ba   = (const float*)d_in[5];
    const float* Wb   = (const float*)d_in[6];
    const float* bb   = (const float*)d_in[7];
    const float* cwq  = (const float*)d_in[8];
    const float* cwk  = (const float*)d_in[9];
    const float* lp   = (const float*)d_in[10];
    const float* onw  = (const float*)d_in[11];
    const float* Wo   = (const float*)d_in[12];
    float* out = (float*)d_out;

    head_kernel<<<16896, 256>>>(x, Wq, Wk, Wv, Wo, Wa, ba, Wb, bb);
    qkv_tensor_kernel<<<dim3(16, 4, 3), 128>>>();
    prep_kernel<<<256, 256>>>(cwq, cwk);
    scan_kernel<<<dim3(16, NHEAD), 256>>>();
    solve_kernel<<<dim3(NHEAD, NSLOT), 128>>>(onw, lp);
    out_tensor_kernel<<<dim3(16, 4), 128>>>(out);
}